// round 5
// baseline (speedup 1.0000x reference)
#include <cuda_runtime.h>
#include <math.h>
#include <float.h>
#include <stdint.h>

// ---------------- problem dims (fixed by setup_inputs) ----------------
#define D_MODEL 1024
#define N_HEADS 16
#define DH      64
#define D_FF    4096
#define NFAM    64
#define DICT    16384
#define BB      2
#define TT      2048
#define BT      (BB*TT)          // 4096 tokens
#define TOPK    8
#define EPS_F   1e-6f

// output layout (tuple flattened: x, attn, family_scores, sparsity, e1, e2)
#define X_N     ((size_t)BT * D_MODEL)                    // 4,194,304
#define ATT_N   ((size_t)BB * N_HEADS * TT * TT)          // 134,217,728
#define FS_N    ((size_t)BT * NFAM)                       // 262,144
#define X_OFF   ((size_t)0)
#define ATT_OFF (X_N)
#define FS_OFF  (X_N + ATT_N)
#define SC_OFF  (X_N + ATT_N + FS_N)                      // sparsity, e1, e2

// ---------------- device scratch (no allocation allowed) ----------------
__device__ float g_resid  [BT * D_MODEL];
__device__ float g_basis  [BT * D_MODEL];
__device__ float g_xrec   [BT * D_MODEL];
__device__ float g_normed [BT * D_MODEL];
__device__ float g_q      [BT * D_MODEL];
__device__ float g_k      [BT * D_MODEL];
__device__ float g_v      [BT * D_MODEL];
__device__ float g_kmod   [BT * D_MODEL];   // [b,h,t,dh] contiguous
__device__ float g_ctx    [BT * D_MODEL];
__device__ float g_x2     [BT * D_MODEL];
__device__ float g_normed2[BT * D_MODEL];
__device__ float g_coeffs [(size_t)BT * DICT];   // 256 MB
__device__ float g_gate   [(size_t)BT * D_FF];   // 64 MB (reused for h)
__device__ float g_up     [(size_t)BT * D_FF];   // 64 MB
__device__ float g_rms1   [BT];
__device__ float g_rms2   [BT];
__device__ float g_spars  [BT];

// =====================================================================
// Generic SGEMM: C[M,N] = A[M,K] @ B[N,K]^T (+ res), row-major.
// 128x128 block tile, BK=16, 256 threads, 8x8 per-thread microtile.
// M,N multiples of 128; K multiple of 16 (true for all call sites).
// res (optional) has row stride ldc.
// =====================================================================
__global__ void __launch_bounds__(256)
gemm_tn_kernel(const float* __restrict__ A, int lda,
               const float* __restrict__ B, int ldb,
               float* __restrict__ C, int ldc,
               const float* __restrict__ res,
               int K)
{
    __shared__ float As[16][128];
    __shared__ float Bs[16][128];
    const int bm  = blockIdx.y * 128;
    const int bn  = blockIdx.x * 128;
    const int tid = threadIdx.x;
    const int tx  = tid & 15;
    const int ty  = tid >> 4;
    const int lrow = tid >> 1;
    const int lk   = (tid & 1) << 3;

    float acc[8][8];
#pragma unroll
    for (int i = 0; i < 8; i++)
#pragma unroll
        for (int j = 0; j < 8; j++) acc[i][j] = 0.f;

    const float* aptr = A + (size_t)(bm + lrow) * lda + lk;
    const float* bptr = B + (size_t)(bn + lrow) * ldb + lk;

    for (int k0 = 0; k0 < K; k0 += 16) {
        float4 a0 = *(const float4*)(aptr + k0);
        float4 a1 = *(const float4*)(aptr + k0 + 4);
        float4 b0 = *(const float4*)(bptr + k0);
        float4 b1 = *(const float4*)(bptr + k0 + 4);
        As[lk+0][lrow]=a0.x; As[lk+1][lrow]=a0.y; As[lk+2][lrow]=a0.z; As[lk+3][lrow]=a0.w;
        As[lk+4][lrow]=a1.x; As[lk+5][lrow]=a1.y; As[lk+6][lrow]=a1.z; As[lk+7][lrow]=a1.w;
        Bs[lk+0][lrow]=b0.x; Bs[lk+1][lrow]=b0.y; Bs[lk+2][lrow]=b0.z; Bs[lk+3][lrow]=b0.w;
        Bs[lk+4][lrow]=b1.x; Bs[lk+5][lrow]=b1.y; Bs[lk+6][lrow]=b1.z; Bs[lk+7][lrow]=b1.w;
        __syncthreads();
#pragma unroll
        for (int k = 0; k < 16; k++) {
            float ra[8], rb[8];
            *(float4*)(ra)   = *(const float4*)&As[k][ty*8];
            *(float4*)(ra+4) = *(const float4*)&As[k][ty*8+4];
            *(float4*)(rb)   = *(const float4*)&Bs[k][tx*8];
            *(float4*)(rb+4) = *(const float4*)&Bs[k][tx*8+4];
#pragma unroll
            for (int i = 0; i < 8; i++)
#pragma unroll
                for (int j = 0; j < 8; j++) acc[i][j] += ra[i] * rb[j];
        }
        __syncthreads();
    }

#pragma unroll
    for (int i = 0; i < 8; i++) {
        const int row = bm + ty*8 + i;
        float* crow = C + (size_t)row * ldc + bn + tx*8;
        if (res) {
            const float* rrow = res + (size_t)row * ldc + bn + tx*8;
#pragma unroll
            for (int j = 0; j < 8; j++) acc[i][j] += rrow[j];
        }
        *(float4*)(crow)     = make_float4(acc[i][0], acc[i][1], acc[i][2], acc[i][3]);
        *(float4*)(crow + 4) = make_float4(acc[i][4], acc[i][5], acc[i][6], acc[i][7]);
    }
}

// =====================================================================
// Family basis pool
// =====================================================================
__global__ void __launch_bounds__(256)
family_kernel(const float* __restrict__ x, const float* __restrict__ fgw,
              const float* __restrict__ proto, float* __restrict__ fs_out)
{
    __shared__ float xs[D_MODEL];
    __shared__ float sc[NFAM];
    const int row = blockIdx.x;
    const int tid = threadIdx.x;
    const float* xr = x + (size_t)row * D_MODEL;
    for (int d = tid; d < D_MODEL; d += 256) xs[d] = xr[d];
    __syncthreads();

    const int warp = tid >> 5, lane = tid & 31;
    for (int f = warp; f < NFAM; f += 8) {
        const float* w = fgw + (size_t)f * D_MODEL;
        float s = 0.f;
        for (int d = lane; d < D_MODEL; d += 32) s += xs[d] * w[d];
#pragma unroll
        for (int o = 16; o; o >>= 1) s += __shfl_xor_sync(0xffffffffu, s, o);
        if (lane == 0) sc[f] = s;
    }
    __syncthreads();

    if (tid < 32) {
        float m = fmaxf(sc[tid], sc[tid + 32]);
#pragma unroll
        for (int o = 16; o; o >>= 1) m = fmaxf(m, __shfl_xor_sync(0xffffffffu, m, o));
        const float e0 = __expf(sc[tid] - m);
        const float e1 = __expf(sc[tid + 32] - m);
        float s = e0 + e1;
#pragma unroll
        for (int o = 16; o; o >>= 1) s += __shfl_xor_sync(0xffffffffu, s, o);
        const float inv = 1.f / s;
        sc[tid]      = e0 * inv;
        sc[tid + 32] = e1 * inv;
    }
    __syncthreads();

    if (tid < NFAM) fs_out[(size_t)row * NFAM + tid] = sc[tid];

    for (int d = tid; d < D_MODEL; d += 256) {
        float b = 0.f;
#pragma unroll 8
        for (int f = 0; f < NFAM; f++) b += sc[f] * proto[f * D_MODEL + d];
        g_basis[(size_t)row * D_MODEL + d] = b;
        g_resid[(size_t)row * D_MODEL + d] = xs[d] - b;
    }
}

// =====================================================================
// Top-8 + offset gather + x_rec + sparsity
// =====================================================================
__global__ void __launch_bounds__(256)
topk_kernel(const float* __restrict__ dict_w, const float* __restrict__ bias)
{
    __shared__ float sval[2048];
    __shared__ int   sidx[2048];
    __shared__ float rv[256];
    __shared__ int   ri[256];
    __shared__ int   rp[256];
    __shared__ float selv[TOPK];
    __shared__ int   seli[TOPK];

    const int row = blockIdx.x;
    const int tid = threadIdx.x;
    const float* cr = g_coeffs + (size_t)row * DICT;

    float lv[TOPK]; int li[TOPK];
#pragma unroll
    for (int r = 0; r < TOPK; r++) { lv[r] = -FLT_MAX; li[r] = 0x7fffffff; }
    for (int j = tid; j < DICT; j += 256) {
        const float v = cr[j];
        if (v > lv[TOPK-1]) {
            int p = TOPK - 1;
            while (p > 0 && lv[p-1] < v) { lv[p] = lv[p-1]; li[p] = li[p-1]; p--; }
            lv[p] = v; li[p] = j;
        }
    }
#pragma unroll
    for (int r = 0; r < TOPK; r++) { sval[tid*TOPK + r] = lv[r]; sidx[tid*TOPK + r] = li[r]; }
    __syncthreads();

    for (int sel = 0; sel < TOPK; sel++) {
        float bv = -FLT_MAX; int bi = 0x7fffffff; int bp = 0;
#pragma unroll
        for (int r = 0; r < TOPK; r++) {
            const int p = tid*TOPK + r;
            const float v = sval[p]; const int ix = sidx[p];
            if (v > bv || (v == bv && ix < bi)) { bv = v; bi = ix; bp = p; }
        }
        rv[tid] = bv; ri[tid] = bi; rp[tid] = bp;
        __syncthreads();
        for (int s = 128; s > 0; s >>= 1) {
            if (tid < s) {
                if (rv[tid+s] > rv[tid] || (rv[tid+s] == rv[tid] && ri[tid+s] < ri[tid])) {
                    rv[tid] = rv[tid+s]; ri[tid] = ri[tid+s]; rp[tid] = rp[tid+s];
                }
            }
            __syncthreads();
        }
        if (tid == 0) {
            selv[sel] = rv[0]; seli[sel] = ri[0];
            sval[rp[0]] = -FLT_MAX; sidx[rp[0]] = 0x7fffffff;
        }
        __syncthreads();
    }

    for (int d = tid; d < D_MODEL; d += 256) {
        float o = g_basis[(size_t)row * D_MODEL + d] + bias[d];
#pragma unroll
        for (int j = 0; j < TOPK; j++) o += selv[j] * dict_w[(size_t)seli[j] * D_MODEL + d];
        g_xrec[(size_t)row * D_MODEL + d] = o;
    }
    if (tid == 0) {
        float s = 0.f;
#pragma unroll
        for (int j = 0; j < TOPK; j++) s += fabsf(selv[j]);
        g_spars[row] = s;
    }
}

// =====================================================================
// RMSNorm
// =====================================================================
__global__ void __launch_bounds__(256)
rmsnorm_kernel(const float* __restrict__ in, const float* __restrict__ w,
               float* __restrict__ out, float* __restrict__ rmsbuf)
{
    __shared__ float red[256];
    const int row = blockIdx.x, tid = threadIdx.x;
    const float* xr = in + (size_t)row * D_MODEL;
    float s = 0.f;
    for (int d = tid; d < D_MODEL; d += 256) { const float v = xr[d]; s += v * v; }
    red[tid] = s;
    __syncthreads();
    for (int st = 128; st > 0; st >>= 1) { if (tid < st) red[tid] += red[tid + st]; __syncthreads(); }
    const float rms = sqrtf(red[0] / (float)D_MODEL + EPS_F);
    const float inv = 1.f / rms;
    for (int d = tid; d < D_MODEL; d += 256)
        out[(size_t)row * D_MODEL + d] = w[d] * xr[d] * inv;
    if (tid == 0) rmsbuf[row] = rms;
}

// =====================================================================
// k_mod[b,h,t,e] = sum_d k[b,t,h*64+d] * templ[h,d,e]
// =====================================================================
__global__ void __launch_bounds__(256)
kmod_kernel(const float* __restrict__ kbuf, const float* __restrict__ rel)
{
    __shared__ float ks[64][65];
    __shared__ float ts[64][65];
    const int bh = blockIdx.y, b = bh >> 4, h = bh & 15;
    const int t0 = blockIdx.x * 64;
    const int tid = threadIdx.x;
    for (int i = tid; i < 4096; i += 256) {
        const int r = i >> 6, c = i & 63;
        ks[r][c] = kbuf[(size_t)(b*TT + t0 + r) * D_MODEL + h*DH + c];
        ts[r][c] = rel[(size_t)h*DH*DH + r*DH + c];
    }
    __syncthreads();
    const int tx = tid & 15, ty = tid >> 4;
    float acc[4][4] = {};
#pragma unroll
    for (int d = 0; d < 64; d++) {
        float ra[4], rb[4];
#pragma unroll
        for (int i = 0; i < 4; i++) ra[i] = ks[ty*4 + i][d];
#pragma unroll
        for (int j = 0; j < 4; j++) rb[j] = ts[d][tx*4 + j];
#pragma unroll
        for (int i = 0; i < 4; i++)
#pragma unroll
            for (int j = 0; j < 4; j++) acc[i][j] += ra[i] * rb[j];
    }
#pragma unroll
    for (int i = 0; i < 4; i++)
#pragma unroll
        for (int j = 0; j < 4; j++)
            g_kmod[((size_t)bh*TT + t0 + ty*4 + i) * DH + tx*4 + j] = acc[i][j];
}

// =====================================================================
// Attention logits
// =====================================================================
__global__ void __launch_bounds__(256)
logits_kernel(const float* __restrict__ qbuf, float* __restrict__ P)
{
    __shared__ float qs[64][65];
    __shared__ float ks[64][65];
    const int bh = blockIdx.z, b = bh >> 4, h = bh & 15;
    const int tq0 = blockIdx.y * 64, tk0 = blockIdx.x * 64;
    const int tid = threadIdx.x;
    for (int i = tid; i < 4096; i += 256) {
        const int r = i >> 6, c = i & 63;
        qs[r][c] = qbuf[(size_t)(b*TT + tq0 + r) * D_MODEL + h*DH + c];
        ks[r][c] = g_kmod[((size_t)bh*TT + tk0 + r) * DH + c];
    }
    __syncthreads();
    const int tx = tid & 15, ty = tid >> 4;
    float acc[4][4] = {};
#pragma unroll
    for (int d = 0; d < 64; d++) {
        float ra[4], rb[4];
#pragma unroll
        for (int i = 0; i < 4; i++) ra[i] = qs[ty*4 + i][d];
#pragma unroll
        for (int j = 0; j < 4; j++) rb[j] = ks[tx*4 + j][d];
#pragma unroll
        for (int i = 0; i < 4; i++)
#pragma unroll
            for (int j = 0; j < 4; j++) acc[i][j] += ra[i] * rb[j];
    }
#pragma unroll
    for (int i = 0; i < 4; i++)
#pragma unroll
        for (int j = 0; j < 4; j++)
            P[((size_t)bh*TT + tq0 + ty*4 + i) * TT + tk0 + tx*4 + j] = acc[i][j] * 0.125f;
}

// =====================================================================
// Row softmax over 2048, in place
// =====================================================================
__global__ void __launch_bounds__(256)
softmax_kernel(float* __restrict__ P)
{
    __shared__ float red[256];
    const size_t row = blockIdx.x;
    float* p = P + row * (size_t)TT;
    const int tid = threadIdx.x;
    float v[8];
#pragma unroll
    for (int i = 0; i < 8; i++) v[i] = p[tid + i*256];
    float m = v[0];
#pragma unroll
    for (int i = 1; i < 8; i++) m = fmaxf(m, v[i]);
    red[tid] = m;
    __syncthreads();
    for (int st = 128; st > 0; st >>= 1) { if (tid < st) red[tid] = fmaxf(red[tid], red[tid+st]); __syncthreads(); }
    m = red[0];
    __syncthreads();
    float s = 0.f;
#pragma unroll
    for (int i = 0; i < 8; i++) { v[i] = __expf(v[i] - m); s += v[i]; }
    red[tid] = s;
    __syncthreads();
    for (int st = 128; st > 0; st >>= 1) { if (tid < st) red[tid] += red[tid+st]; __syncthreads(); }
    const float inv = 1.f / red[0];
#pragma unroll
    for (int i = 0; i < 8; i++) p[tid + i*256] = v[i] * inv;
}

// =====================================================================
// ctx = attn @ v
// =====================================================================
__global__ void __launch_bounds__(256)
av_kernel(const float* __restrict__ P, const float* __restrict__ vbuf)
{
    __shared__ float ps[64][65];
    __shared__ float vs[64][65];
    const int bh = blockIdx.y, b = bh >> 4, h = bh & 15;
    const int tq0 = blockIdx.x * 64;
    const int tid = threadIdx.x;
    const int tx = tid & 15, ty = tid >> 4;
    float acc[4][4] = {};
    for (int kt = 0; kt < TT; kt += 64) {
        for (int i = tid; i < 4096; i += 256) {
            const int r = i >> 6, c = i & 63;
            ps[r][c] = P[((size_t)bh*TT + tq0 + r) * TT + kt + c];
            vs[r][c] = vbuf[(size_t)(b*TT + kt + r) * D_MODEL + h*DH + c];
        }
        __syncthreads();
#pragma unroll
        for (int kk = 0; kk < 64; kk++) {
            float ra[4], rb[4];
#pragma unroll
            for (int i = 0; i < 4; i++) ra[i] = ps[ty*4 + i][kk];
#pragma unroll
            for (int j = 0; j < 4; j++) rb[j] = vs[kk][tx*4 + j];
#pragma unroll
            for (int i = 0; i < 4; i++)
#pragma unroll
                for (int j = 0; j < 4; j++) acc[i][j] += ra[i] * rb[j];
        }
        __syncthreads();
    }
#pragma unroll
    for (int i = 0; i < 4; i++)
#pragma unroll
        for (int j = 0; j < 4; j++)
            g_ctx[(size_t)(b*TT + tq0 + ty*4 + i) * D_MODEL + h*DH + tx*4 + j] = acc[i][j];
}

// =====================================================================
// h = sigmoid(gate) * silu(up)  (over g_gate)
// =====================================================================
__global__ void __launch_bounds__(256)
gateup_kernel()
{
    const size_t n = (size_t)BT * D_FF;
    for (size_t i = (size_t)blockIdx.x * blockDim.x + threadIdx.x; i < n;
         i += (size_t)gridDim.x * blockDim.x) {
        const float g = g_gate[i], u = g_up[i];
        const float sg = 1.f / (1.f + __expf(-g));
        const float su = u / (1.f + __expf(-u));
        g_gate[i] = sg * su;
    }
}

// =====================================================================
// Final scalars
// =====================================================================
__global__ void __launch_bounds__(256)
finalize_kernel(float* __restrict__ out)
{
    __shared__ float s1[256], s2[256], s3[256];
    const int tid = threadIdx.x;
    float a = 0.f, b = 0.f, c = 0.f;
    for (int i = tid; i < BT; i += 256) { a += g_spars[i]; b += g_rms1[i]; c += g_rms2[i]; }
    s1[tid] = a; s2[tid] = b; s3[tid] = c;
    __syncthreads();
    for (int st = 128; st > 0; st >>= 1) {
        if (tid < st) { s1[tid] += s1[tid+st]; s2[tid] += s2[tid+st]; s3[tid] += s3[tid+st]; }
        __syncthreads();
    }
    if (tid == 0) {
        out[SC_OFF + 0] = s1[0] / ((float)BB * (float)TT * (float)DICT);
        out[SC_OFF + 1] = s2[0] / (float)BT;
        out[SC_OFF + 2] = s3[0] / (float)BT;
    }
}

// =====================================================================
// host launcher
// =====================================================================
extern "C" void kernel_launch(void* const* d_in, const int* in_sizes, int n_in,
                              void* d_out, int out_size)
{
    (void)in_sizes; (void)n_in; (void)out_size;
    const float* x     = (const float*)d_in[0];
    // d_in[1] = top_k (int32 scalar, fixed at 8; compiled in)
    const float* proto = (const float*)d_in[2];
    const float* fgw   = (const float*)d_in[3];
    const float* dictw = (const float*)d_in[4];
    const float* encw  = (const float*)d_in[5];
    const float* wq    = (const float*)d_in[6];
    const float* wk    = (const float*)d_in[7];
    const float* wv    = (const float*)d_in[8];
    const float* wo    = (const float*)d_in[9];
    const float* rel   = (const float*)d_in[10];
    const float* gatew = (const float*)d_in[11];
    const float* upw   = (const float*)d_in[12];
    const float* downw = (const float*)d_in[13];
    const float* n1w   = (const float*)d_in[14];
    const float* n2w   = (const float*)d_in[15];
    const float* bias  = (const float*)d_in[16];
    float* out = (float*)d_out;

    float *p_resid, *p_coeffs, *p_xrec, *p_normed, *p_q, *p_k, *p_v, *p_ctx,
          *p_x2, *p_normed2, *p_gate, *p_up, *p_rms1, *p_rms2;
    cudaGetSymbolAddress((void**)&p_resid,   g_resid);
    cudaGetSymbolAddress((void**)&p_coeffs,  g_coeffs);
    cudaGetSymbolAddress((void**)&p_xrec,    g_xrec);
    cudaGetSymbolAddress((void**)&p_normed,  g_normed);
    cudaGetSymbolAddress((void**)&p_q,       g_q);
    cudaGetSymbolAddress((void**)&p_k,       g_k);
    cudaGetSymbolAddress((void**)&p_v,       g_v);
    cudaGetSymbolAddress((void**)&p_ctx,     g_ctx);
    cudaGetSymbolAddress((void**)&p_x2,      g_x2);
    cudaGetSymbolAddress((void**)&p_normed2, g_normed2);
    cudaGetSymbolAddress((void**)&p_gate,    g_gate);
    cudaGetSymbolAddress((void**)&p_up,      g_up);
    cudaGetSymbolAddress((void**)&p_rms1,    g_rms1);
    cudaGetSymbolAddress((void**)&p_rms2,    g_rms2);

    // 1) family pool: scores -> d_out, basis, resid
    family_kernel<<<BT, 256>>>(x, fgw, proto, out + FS_OFF);

    // 2) coeffs = resid @ enc_w^T   [4096 x 16384], K=1024
    gemm_tn_kernel<<<dim3(DICT/128, BT/128), 256>>>(p_resid, D_MODEL, encw, D_MODEL,
                                                    p_coeffs, DICT, nullptr, D_MODEL);

    // 3) top-8 + offset gather -> x_rec, sparsity
    topk_kernel<<<BT, 256>>>(dictw, bias);

    // 4) norm1
    rmsnorm_kernel<<<BT, 256>>>(p_xrec, n1w, p_normed, p_rms1);

    // 5) q,k,v projections (K=1024)
    gemm_tn_kernel<<<dim3(D_MODEL/128, BT/128), 256>>>(p_normed, D_MODEL, wq, D_MODEL,
                                                       p_q, D_MODEL, nullptr, D_MODEL);
    gemm_tn_kernel<<<dim3(D_MODEL/128, BT/128), 256>>>(p_normed, D_MODEL, wk, D_MODEL,
                                                       p_k, D_MODEL, nullptr, D_MODEL);
    gemm_tn_kernel<<<dim3(D_MODEL/128, BT/128), 256>>>(p_normed, D_MODEL, wv, D_MODEL,
                                                       p_v, D_MODEL, nullptr, D_MODEL);

    // 6) k_mod
    kmod_kernel<<<dim3(TT/64, BB*N_HEADS), 256>>>(p_k, rel);

    // 7) attn logits -> d_out, softmax in place
    logits_kernel<<<dim3(TT/64, TT/64, BB*N_HEADS), 256>>>(p_q, out + ATT_OFF);
    softmax_kernel<<<BB*N_HEADS*TT, 256>>>(out + ATT_OFF);

    // 8) ctx = attn @ v
    av_kernel<<<dim3(TT/64, BB*N_HEADS), 256>>>(out + ATT_OFF, p_v);

    // 9) x2 = x + ctx @ wo^T (K=1024, residual fused)
    gemm_tn_kernel<<<dim3(D_MODEL/128, BT/128), 256>>>(p_ctx, D_MODEL, wo, D_MODEL,
                                                       p_x2, D_MODEL, x, D_MODEL);

    // 10) norm2
    rmsnorm_kernel<<<BT, 256>>>(p_x2, n2w, p_normed2, p_rms2);

    // 11) FFN gate/up (K=1024), fuse activation
    gemm_tn_kernel<<<dim3(D_FF/128, BT/128), 256>>>(p_normed2, D_MODEL, gatew, D_MODEL,
                                                    p_gate, D_FF, nullptr, D_MODEL);
    gemm_tn_kernel<<<dim3(D_FF/128, BT/128), 256>>>(p_normed2, D_MODEL, upw, D_MODEL,
                                                    p_up, D_FF, nullptr, D_MODEL);
    gateup_kernel<<<8192, 256>>>();

    // 12) final x = x2 + h @ down^T (K=4096, residual fused) -> d_out
    gemm_tn_kernel<<<dim3(D_MODEL/128, BT/128), 256>>>(p_gate, D_FF, downw, D_FF,
                                                       out + X_OFF, D_MODEL, p_x2, D_FF);

    // 13) scalars
    finalize_kernel<<<1, 256>>>(out);
}

// round 7
// speedup vs baseline: 1.0010x; 1.0010x over previous
#include <cuda_runtime.h>
#include <math.h>
#include <float.h>
#include <stdint.h>

// ---------------- problem dims (fixed by setup_inputs) ----------------
#define D_MODEL 1024
#define N_HEADS 16
#define DH      64
#define D_FF    4096
#define NFAM    64
#define DICT    16384
#define BB      2
#define TT      2048
#define BT      (BB*TT)          // 4096 tokens
#define TOPK    8
#define EPS_F   1e-6f

// output layout (tuple flattened: x, attn, family_scores, sparsity, e1, e2)
#define X_N     ((size_t)BT * D_MODEL)                    // 4,194,304
#define ATT_N   ((size_t)BB * N_HEADS * TT * TT)          // 134,217,728
#define FS_N    ((size_t)BT * NFAM)                       // 262,144
#define X_OFF   ((size_t)0)
#define ATT_OFF (X_N)
#define FS_OFF  (X_N + ATT_N)
#define SC_OFF  (X_N + ATT_N + FS_N)                      // sparsity, e1, e2

// ---------------- device scratch (no allocation allowed) ----------------
__device__ float g_resid  [BT * D_MODEL];
__device__ float g_basis  [BT * D_MODEL];
__device__ float g_xrec   [BT * D_MODEL];
__device__ float g_normed [BT * D_MODEL];
__device__ float g_q      [BT * D_MODEL];
__device__ float g_k      [BT * D_MODEL];
__device__ float g_v      [BT * D_MODEL];
__device__ float g_kmod   [BT * D_MODEL];   // [b,h,t,dh] contiguous
__device__ float g_ctx    [BT * D_MODEL];
__device__ float g_x2     [BT * D_MODEL];
__device__ float g_normed2[BT * D_MODEL];
__device__ float g_coeffs [(size_t)BT * DICT];   // 256 MB
__device__ float g_gate   [(size_t)BT * D_FF];   // 64 MB (reused for h)
__device__ float g_up     [(size_t)BT * D_FF];   // 64 MB
__device__ float g_rms1   [BT];
__device__ float g_rms2   [BT];
__device__ float g_spars  [BT];

// =====================================================================
// Generic SGEMM: C[M,N] = A[M,K] @ B[N,K]^T (+ res), row-major.
// 128x128 block tile, BK=16, 256 threads, 8x8 per-thread microtile.
// M,N multiples of 128; K multiple of 16 (true for all call sites).
// res (optional) has row stride ldc.
// =====================================================================
__global__ void __launch_bounds__(256)
gemm_tn_kernel(const float* __restrict__ A, int lda,
               const float* __restrict__ B, int ldb,
               float* __restrict__ C, int ldc,
               const float* __restrict__ res,
               int K)
{
    __shared__ float As[16][128];
    __shared__ float Bs[16][128];
    const int bm  = blockIdx.y * 128;
    const int bn  = blockIdx.x * 128;
    const int tid = threadIdx.x;
    const int tx  = tid & 15;
    const int ty  = tid >> 4;
    const int lrow = tid >> 1;
    const int lk   = (tid & 1) << 3;

    float acc[8][8];
#pragma unroll
    for (int i = 0; i < 8; i++)
#pragma unroll
        for (int j = 0; j < 8; j++) acc[i][j] = 0.f;

    const float* aptr = A + (size_t)(bm + lrow) * lda + lk;
    const float* bptr = B + (size_t)(bn + lrow) * ldb + lk;

    for (int k0 = 0; k0 < K; k0 += 16) {
        float4 a0 = *(const float4*)(aptr + k0);
        float4 a1 = *(const float4*)(aptr + k0 + 4);
        float4 b0 = *(const float4*)(bptr + k0);
        float4 b1 = *(const float4*)(bptr + k0 + 4);
        As[lk+0][lrow]=a0.x; As[lk+1][lrow]=a0.y; As[lk+2][lrow]=a0.z; As[lk+3][lrow]=a0.w;
        As[lk+4][lrow]=a1.x; As[lk+5][lrow]=a1.y; As[lk+6][lrow]=a1.z; As[lk+7][lrow]=a1.w;
        Bs[lk+0][lrow]=b0.x; Bs[lk+1][lrow]=b0.y; Bs[lk+2][lrow]=b0.z; Bs[lk+3][lrow]=b0.w;
        Bs[lk+4][lrow]=b1.x; Bs[lk+5][lrow]=b1.y; Bs[lk+6][lrow]=b1.z; Bs[lk+7][lrow]=b1.w;
        __syncthreads();
#pragma unroll
        for (int k = 0; k < 16; k++) {
            float ra[8], rb[8];
            *(float4*)(ra)   = *(const float4*)&As[k][ty*8];
            *(float4*)(ra+4) = *(const float4*)&As[k][ty*8+4];
            *(float4*)(rb)   = *(const float4*)&Bs[k][tx*8];
            *(float4*)(rb+4) = *(const float4*)&Bs[k][tx*8+4];
#pragma unroll
            for (int i = 0; i < 8; i++)
#pragma unroll
                for (int j = 0; j < 8; j++) acc[i][j] += ra[i] * rb[j];
        }
        __syncthreads();
    }

#pragma unroll
    for (int i = 0; i < 8; i++) {
        const int row = bm + ty*8 + i;
        float* crow = C + (size_t)row * ldc + bn + tx*8;
        if (res) {
            const float* rrow = res + (size_t)row * ldc + bn + tx*8;
#pragma unroll
            for (int j = 0; j < 8; j++) acc[i][j] += rrow[j];
        }
        *(float4*)(crow)     = make_float4(acc[i][0], acc[i][1], acc[i][2], acc[i][3]);
        *(float4*)(crow + 4) = make_float4(acc[i][4], acc[i][5], acc[i][6], acc[i][7]);
    }
}

// =====================================================================
// Family basis pool
// =====================================================================
__global__ void __launch_bounds__(256)
family_kernel(const float* __restrict__ x, const float* __restrict__ fgw,
              const float* __restrict__ proto, float* __restrict__ fs_out)
{
    __shared__ float xs[D_MODEL];
    __shared__ float sc[NFAM];
    const int row = blockIdx.x;
    const int tid = threadIdx.x;
    const float* xr = x + (size_t)row * D_MODEL;
    for (int d = tid; d < D_MODEL; d += 256) xs[d] = xr[d];
    __syncthreads();

    const int warp = tid >> 5, lane = tid & 31;
    for (int f = warp; f < NFAM; f += 8) {
        const float* w = fgw + (size_t)f * D_MODEL;
        float s = 0.f;
        for (int d = lane; d < D_MODEL; d += 32) s += xs[d] * w[d];
#pragma unroll
        for (int o = 16; o; o >>= 1) s += __shfl_xor_sync(0xffffffffu, s, o);
        if (lane == 0) sc[f] = s;
    }
    __syncthreads();

    if (tid < 32) {
        float m = fmaxf(sc[tid], sc[tid + 32]);
#pragma unroll
        for (int o = 16; o; o >>= 1) m = fmaxf(m, __shfl_xor_sync(0xffffffffu, m, o));
        const float e0 = __expf(sc[tid] - m);
        const float e1 = __expf(sc[tid + 32] - m);
        float s = e0 + e1;
#pragma unroll
        for (int o = 16; o; o >>= 1) s += __shfl_xor_sync(0xffffffffu, s, o);
        const float inv = 1.f / s;
        sc[tid]      = e0 * inv;
        sc[tid + 32] = e1 * inv;
    }
    __syncthreads();

    if (tid < NFAM) fs_out[(size_t)row * NFAM + tid] = sc[tid];

    for (int d = tid; d < D_MODEL; d += 256) {
        float b = 0.f;
#pragma unroll 8
        for (int f = 0; f < NFAM; f++) b += sc[f] * proto[f * D_MODEL + d];
        g_basis[(size_t)row * D_MODEL + d] = b;
        g_resid[(size_t)row * D_MODEL + d] = xs[d] - b;
    }
}

// =====================================================================
// Top-8 + offset gather + x_rec + sparsity
// =====================================================================
__global__ void __launch_bounds__(256)
topk_kernel(const float* __restrict__ dict_w, const float* __restrict__ bias)
{
    __shared__ float sval[2048];
    __shared__ int   sidx[2048];
    __shared__ float rv[256];
    __shared__ int   ri[256];
    __shared__ int   rp[256];
    __shared__ float selv[TOPK];
    __shared__ int   seli[TOPK];

    const int row = blockIdx.x;
    const int tid = threadIdx.x;
    const float* cr = g_coeffs + (size_t)row * DICT;

    float lv[TOPK]; int li[TOPK];
#pragma unroll
    for (int r = 0; r < TOPK; r++) { lv[r] = -FLT_MAX; li[r] = 0x7fffffff; }
    for (int j = tid; j < DICT; j += 256) {
        const float v = cr[j];
        if (v > lv[TOPK-1]) {
            int p = TOPK - 1;
            while (p > 0 && lv[p-1] < v) { lv[p] = lv[p-1]; li[p] = li[p-1]; p--; }
            lv[p] = v; li[p] = j;
        }
    }
#pragma unroll
    for (int r = 0; r < TOPK; r++) { sval[tid*TOPK + r] = lv[r]; sidx[tid*TOPK + r] = li[r]; }
    __syncthreads();

    for (int sel = 0; sel < TOPK; sel++) {
        float bv = -FLT_MAX; int bi = 0x7fffffff; int bp = 0;
#pragma unroll
        for (int r = 0; r < TOPK; r++) {
            const int p = tid*TOPK + r;
            const float v = sval[p]; const int ix = sidx[p];
            if (v > bv || (v == bv && ix < bi)) { bv = v; bi = ix; bp = p; }
        }
        rv[tid] = bv; ri[tid] = bi; rp[tid] = bp;
        __syncthreads();
        for (int s = 128; s > 0; s >>= 1) {
            if (tid < s) {
                if (rv[tid+s] > rv[tid] || (rv[tid+s] == rv[tid] && ri[tid+s] < ri[tid])) {
                    rv[tid] = rv[tid+s]; ri[tid] = ri[tid+s]; rp[tid] = rp[tid+s];
                }
            }
            __syncthreads();
        }
        if (tid == 0) {
            selv[sel] = rv[0]; seli[sel] = ri[0];
            sval[rp[0]] = -FLT_MAX; sidx[rp[0]] = 0x7fffffff;
        }
        __syncthreads();
    }

    for (int d = tid; d < D_MODEL; d += 256) {
        float o = g_basis[(size_t)row * D_MODEL + d] + bias[d];
#pragma unroll
        for (int j = 0; j < TOPK; j++) o += selv[j] * dict_w[(size_t)seli[j] * D_MODEL + d];
        g_xrec[(size_t)row * D_MODEL + d] = o;
    }
    if (tid == 0) {
        float s = 0.f;
#pragma unroll
        for (int j = 0; j < TOPK; j++) s += fabsf(selv[j]);
        g_spars[row] = s;
    }
}

// =====================================================================
// RMSNorm
// =====================================================================
__global__ void __launch_bounds__(256)
rmsnorm_kernel(const float* __restrict__ in, const float* __restrict__ w,
               float* __restrict__ out, float* __restrict__ rmsbuf)
{
    __shared__ float red[256];
    const int row = blockIdx.x, tid = threadIdx.x;
    const float* xr = in + (size_t)row * D_MODEL;
    float s = 0.f;
    for (int d = tid; d < D_MODEL; d += 256) { const float v = xr[d]; s += v * v; }
    red[tid] = s;
    __syncthreads();
    for (int st = 128; st > 0; st >>= 1) { if (tid < st) red[tid] += red[tid + st]; __syncthreads(); }
    const float rms = sqrtf(red[0] / (float)D_MODEL + EPS_F);
    const float inv = 1.f / rms;
    for (int d = tid; d < D_MODEL; d += 256)
        out[(size_t)row * D_MODEL + d] = w[d] * xr[d] * inv;
    if (tid == 0) rmsbuf[row] = rms;
}

// =====================================================================
// k_mod[b,h,t,e] = sum_d k[b,t,h*64+d] * templ[h,d,e]
// =====================================================================
__global__ void __launch_bounds__(256)
kmod_kernel(const float* __restrict__ kbuf, const float* __restrict__ rel)
{
    __shared__ float ks[64][65];
    __shared__ float ts[64][65];
    const int bh = blockIdx.y, b = bh >> 4, h = bh & 15;
    const int t0 = blockIdx.x * 64;
    const int tid = threadIdx.x;
    for (int i = tid; i < 4096; i += 256) {
        const int r = i >> 6, c = i & 63;
        ks[r][c] = kbuf[(size_t)(b*TT + t0 + r) * D_MODEL + h*DH + c];
        ts[r][c] = rel[(size_t)h*DH*DH + r*DH + c];
    }
    __syncthreads();
    const int tx = tid & 15, ty = tid >> 4;
    float acc[4][4] = {};
#pragma unroll
    for (int d = 0; d < 64; d++) {
        float ra[4], rb[4];
#pragma unroll
        for (int i = 0; i < 4; i++) ra[i] = ks[ty*4 + i][d];
#pragma unroll
        for (int j = 0; j < 4; j++) rb[j] = ts[d][tx*4 + j];
#pragma unroll
        for (int i = 0; i < 4; i++)
#pragma unroll
            for (int j = 0; j < 4; j++) acc[i][j] += ra[i] * rb[j];
    }
#pragma unroll
    for (int i = 0; i < 4; i++)
#pragma unroll
        for (int j = 0; j < 4; j++)
            g_kmod[((size_t)bh*TT + t0 + ty*4 + i) * DH + tx*4 + j] = acc[i][j];
}

// =====================================================================
// Attention logits
// =====================================================================
__global__ void __launch_bounds__(256)
logits_kernel(const float* __restrict__ qbuf, float* __restrict__ P)
{
    __shared__ float qs[64][65];
    __shared__ float ks[64][65];
    const int bh = blockIdx.z, b = bh >> 4, h = bh & 15;
    const int tq0 = blockIdx.y * 64, tk0 = blockIdx.x * 64;
    const int tid = threadIdx.x;
    for (int i = tid; i < 4096; i += 256) {
        const int r = i >> 6, c = i & 63;
        qs[r][c] = qbuf[(size_t)(b*TT + tq0 + r) * D_MODEL + h*DH + c];
        ks[r][c] = g_kmod[((size_t)bh*TT + tk0 + r) * DH + c];
    }
    __syncthreads();
    const int tx = tid & 15, ty = tid >> 4;
    float acc[4][4] = {};
#pragma unroll
    for (int d = 0; d < 64; d++) {
        float ra[4], rb[4];
#pragma unroll
        for (int i = 0; i < 4; i++) ra[i] = qs[ty*4 + i][d];
#pragma unroll
        for (int j = 0; j < 4; j++) rb[j] = ks[tx*4 + j][d];
#pragma unroll
        for (int i = 0; i < 4; i++)
#pragma unroll
            for (int j = 0; j < 4; j++) acc[i][j] += ra[i] * rb[j];
    }
#pragma unroll
    for (int i = 0; i < 4; i++)
#pragma unroll
        for (int j = 0; j < 4; j++)
            P[((size_t)bh*TT + tq0 + ty*4 + i) * TT + tk0 + tx*4 + j] = acc[i][j] * 0.125f;
}

// =====================================================================
// Row softmax over 2048, in place
// =====================================================================
__global__ void __launch_bounds__(256)
softmax_kernel(float* __restrict__ P)
{
    __shared__ float red[256];
    const size_t row = blockIdx.x;
    float* p = P + row * (size_t)TT;
    const int tid = threadIdx.x;
    float v[8];
#pragma unroll
    for (int i = 0; i < 8; i++) v[i] = p[tid + i*256];
    float m = v[0];
#pragma unroll
    for (int i = 1; i < 8; i++) m = fmaxf(m, v[i]);
    red[tid] = m;
    __syncthreads();
    for (int st = 128; st > 0; st >>= 1) { if (tid < st) red[tid] = fmaxf(red[tid], red[tid+st]); __syncthreads(); }
    m = red[0];
    __syncthreads();
    float s = 0.f;
#pragma unroll
    for (int i = 0; i < 8; i++) { v[i] = __expf(v[i] - m); s += v[i]; }
    red[tid] = s;
    __syncthreads();
    for (int st = 128; st > 0; st >>= 1) { if (tid < st) red[tid] += red[tid+st]; __syncthreads(); }
    const float inv = 1.f / red[0];
#pragma unroll
    for (int i = 0; i < 8; i++) p[tid + i*256] = v[i] * inv;
}

// =====================================================================
// ctx = attn @ v
// =====================================================================
__global__ void __launch_bounds__(256)
av_kernel(const float* __restrict__ P, const float* __restrict__ vbuf)
{
    __shared__ float ps[64][65];
    __shared__ float vs[64][65];
    const int bh = blockIdx.y, b = bh >> 4, h = bh & 15;
    const int tq0 = blockIdx.x * 64;
    const int tid = threadIdx.x;
    const int tx = tid & 15, ty = tid >> 4;
    float acc[4][4] = {};
    for (int kt = 0; kt < TT; kt += 64) {
        for (int i = tid; i < 4096; i += 256) {
            const int r = i >> 6, c = i & 63;
            ps[r][c] = P[((size_t)bh*TT + tq0 + r) * TT + kt + c];
            vs[r][c] = vbuf[(size_t)(b*TT + kt + r) * D_MODEL + h*DH + c];
        }
        __syncthreads();
#pragma unroll
        for (int kk = 0; kk < 64; kk++) {
            float ra[4], rb[4];
#pragma unroll
            for (int i = 0; i < 4; i++) ra[i] = ps[ty*4 + i][kk];
#pragma unroll
            for (int j = 0; j < 4; j++) rb[j] = vs[kk][tx*4 + j];
#pragma unroll
            for (int i = 0; i < 4; i++)
#pragma unroll
                for (int j = 0; j < 4; j++) acc[i][j] += ra[i] * rb[j];
        }
        __syncthreads();
    }
#pragma unroll
    for (int i = 0; i < 4; i++)
#pragma unroll
        for (int j = 0; j < 4; j++)
            g_ctx[(size_t)(b*TT + tq0 + ty*4 + i) * D_MODEL + h*DH + tx*4 + j] = acc[i][j];
}

// =====================================================================
// h = sigmoid(gate) * silu(up)  (over g_gate)
// =====================================================================
__global__ void __launch_bounds__(256)
gateup_kernel()
{
    const size_t n = (size_t)BT * D_FF;
    for (size_t i = (size_t)blockIdx.x * blockDim.x + threadIdx.x; i < n;
         i += (size_t)gridDim.x * blockDim.x) {
        const float g = g_gate[i], u = g_up[i];
        const float sg = 1.f / (1.f + __expf(-g));
        const float su = u / (1.f + __expf(-u));
        g_gate[i] = sg * su;
    }
}

// =====================================================================
// Final scalars
// =====================================================================
__global__ void __launch_bounds__(256)
finalize_kernel(float* __restrict__ out)
{
    __shared__ float s1[256], s2[256], s3[256];
    const int tid = threadIdx.x;
    float a = 0.f, b = 0.f, c = 0.f;
    for (int i = tid; i < BT; i += 256) { a += g_spars[i]; b += g_rms1[i]; c += g_rms2[i]; }
    s1[tid] = a; s2[tid] = b; s3[tid] = c;
    __syncthreads();
    for (int st = 128; st > 0; st >>= 1) {
        if (tid < st) { s1[tid] += s1[tid+st]; s2[tid] += s2[tid+st]; s3[tid] += s3[tid+st]; }
        __syncthreads();
    }
    if (tid == 0) {
        out[SC_OFF + 0] = s1[0] / ((float)BB * (float)TT * (float)DICT);
        out[SC_OFF + 1] = s2[0] / (float)BT;
        out[SC_OFF + 2] = s3[0] / (float)BT;
    }
}

// =====================================================================
// host launcher
// =====================================================================
extern "C" void kernel_launch(void* const* d_in, const int* in_sizes, int n_in,
                              void* d_out, int out_size)
{
    (void)in_sizes; (void)n_in; (void)out_size;
    const float* x     = (const float*)d_in[0];
    // d_in[1] = top_k (int32 scalar, fixed at 8; compiled in)
    const float* proto = (const float*)d_in[2];
    const float* fgw   = (const float*)d_in[3];
    const float* dictw = (const float*)d_in[4];
    const float* encw  = (const float*)d_in[5];
    const float* wq    = (const float*)d_in[6];
    const float* wk    = (const float*)d_in[7];
    const float* wv    = (const float*)d_in[8];
    const float* wo    = (const float*)d_in[9];
    const float* rel   = (const float*)d_in[10];
    const float* gatew = (const float*)d_in[11];
    const float* upw   = (const float*)d_in[12];
    const float* downw = (const float*)d_in[13];
    const float* n1w   = (const float*)d_in[14];
    const float* n2w   = (const float*)d_in[15];
    const float* bias  = (const float*)d_in[16];
    float* out = (float*)d_out;

    float *p_resid, *p_coeffs, *p_xrec, *p_normed, *p_q, *p_k, *p_v, *p_ctx,
          *p_x2, *p_normed2, *p_gate, *p_up, *p_rms1, *p_rms2;
    cudaGetSymbolAddress((void**)&p_resid,   g_resid);
    cudaGetSymbolAddress((void**)&p_coeffs,  g_coeffs);
    cudaGetSymbolAddress((void**)&p_xrec,    g_xrec);
    cudaGetSymbolAddress((void**)&p_normed,  g_normed);
    cudaGetSymbolAddress((void**)&p_q,       g_q);
    cudaGetSymbolAddress((void**)&p_k,       g_k);
    cudaGetSymbolAddress((void**)&p_v,       g_v);
    cudaGetSymbolAddress((void**)&p_ctx,     g_ctx);
    cudaGetSymbolAddress((void**)&p_x2,      g_x2);
    cudaGetSymbolAddress((void**)&p_normed2, g_normed2);
    cudaGetSymbolAddress((void**)&p_gate,    g_gate);
    cudaGetSymbolAddress((void**)&p_up,      g_up);
    cudaGetSymbolAddress((void**)&p_rms1,    g_rms1);
    cudaGetSymbolAddress((void**)&p_rms2,    g_rms2);

    // 1) family pool: scores -> d_out, basis, resid
    family_kernel<<<BT, 256>>>(x, fgw, proto, out + FS_OFF);

    // 2) coeffs = resid @ enc_w^T   [4096 x 16384], K=1024
    gemm_tn_kernel<<<dim3(DICT/128, BT/128), 256>>>(p_resid, D_MODEL, encw, D_MODEL,
                                                    p_coeffs, DICT, nullptr, D_MODEL);

    // 3) top-8 + offset gather -> x_rec, sparsity
    topk_kernel<<<BT, 256>>>(dictw, bias);

    // 4) norm1
    rmsnorm_kernel<<<BT, 256>>>(p_xrec, n1w, p_normed, p_rms1);

    // 5) q,k,v projections (K=1024)
    gemm_tn_kernel<<<dim3(D_MODEL/128, BT/128), 256>>>(p_normed, D_MODEL, wq, D_MODEL,
                                                       p_q, D_MODEL, nullptr, D_MODEL);
    gemm_tn_kernel<<<dim3(D_MODEL/128, BT/128), 256>>>(p_normed, D_MODEL, wk, D_MODEL,
                                                       p_k, D_MODEL, nullptr, D_MODEL);
    gemm_tn_kernel<<<dim3(D_MODEL/128, BT/128), 256>>>(p_normed, D_MODEL, wv, D_MODEL,
                                                       p_v, D_MODEL, nullptr, D_MODEL);

    // 6) k_mod
    kmod_kernel<<<dim3(TT/64, BB*N_HEADS), 256>>>(p_k, rel);

    // 7) attn logits -> d_out, softmax in place
    logits_kernel<<<dim3(TT/64, TT/64, BB*N_HEADS), 256>>>(p_q, out + ATT_OFF);
    softmax_kernel<<<BB*N_HEADS*TT, 256>>>(out + ATT_OFF);

    // 8) ctx = attn @ v
    av_kernel<<<dim3(TT/64, BB*N_HEADS), 256>>>(out + ATT_OFF, p_v);

    // 9) x2 = x + ctx @ wo^T (K=1024, residual fused)
    gemm_tn_kernel<<<dim3(D_MODEL/128, BT/128), 256>>>(p_ctx, D_MODEL, wo, D_MODEL,
                                                       p_x2, D_MODEL, x, D_MODEL);

    // 10) norm2
    rmsnorm_kernel<<<BT, 256>>>(p_x2, n2w, p_normed2, p_rms2);

    // 11) FFN gate/up (K=1024), fuse activation
    gemm_tn_kernel<<<dim3(D_FF/128, BT/128), 256>>>(p_normed2, D_MODEL, gatew, D_MODEL,
                                                    p_gate, D_FF, nullptr, D_MODEL);
    gemm_tn_kernel<<<dim3(D_FF/128, BT/128), 256>>>(p_normed2, D_MODEL, upw, D_MODEL,
                                                    p_up, D_FF, nullptr, D_MODEL);
    gateup_kernel<<<8192, 256>>>();

    // 12) final x = x2 + h @ down^T (K=4096, residual fused) -> d_out
    gemm_tn_kernel<<<dim3(D_MODEL/128, BT/128), 256>>>(p_gate, D_FF, downw, D_FF,
                                                       out + X_OFF, D_MODEL, p_x2, D_FF);

    // 13) scalars
    finalize_kernel<<<1, 256>>>(out);
}

// round 9
// speedup vs baseline: 1.4606x; 1.4592x over previous
#include <cuda_runtime.h>
#include <cuda_bf16.h>
#include <math.h>
#include <float.h>
#include <stdint.h>

// ---------------- problem dims (fixed by setup_inputs) ----------------
#define D_MODEL 1024
#define N_HEADS 16
#define DH      64
#define D_FF    4096
#define NFAM    64
#define DICT    16384
#define BB      2
#define TT      2048
#define BT      (BB*TT)
#define TOPK    8
#define NCAND   16
#define EPS_F   1e-6f

#define X_N     ((size_t)BT * D_MODEL)
#define ATT_N   ((size_t)BB * N_HEADS * TT * TT)
#define FS_N    ((size_t)BT * NFAM)
#define X_OFF   ((size_t)0)
#define ATT_OFF (X_N)
#define FS_OFF  (X_N + ATT_N)
#define SC_OFF  (X_N + ATT_N + FS_N)

// ---------------- device scratch (no allocation allowed) ----------------
__device__ float g_resid  [BT * D_MODEL];
__device__ float g_basis  [BT * D_MODEL];
__device__ float g_xrec   [BT * D_MODEL];
__device__ float g_normed [BT * D_MODEL];
__device__ float g_normed2[BT * D_MODEL];
__device__ float g_q      [BT * D_MODEL];
__device__ float g_k      [BT * D_MODEL];
__device__ float g_v      [BT * D_MODEL];
__device__ float g_kmod   [BT * D_MODEL];   // [bh][t][64]
__device__ float g_vt     [BT * D_MODEL];   // [bh][64][t]
__device__ float g_ctx    [BT * D_MODEL];
__device__ float g_x2     [BT * D_MODEL];
__device__ float g_coeffs [(size_t)BT * DICT];
__device__ float g_gate   [(size_t)BT * D_FF];
__device__ float g_up     [(size_t)BT * D_FF];
__device__ float g_rms1   [BT];
__device__ float g_rms2   [BT];
__device__ float g_spars  [BT];

// ===================== mma.sync helpers (baseline PTX, sm_80+) =========
__device__ __forceinline__ uint32_t smem_u32(const void* p) {
    uint32_t a;
    asm("{ .reg .u64 t; cvta.to.shared.u64 t, %1; cvt.u32.u64 %0, t; }" : "=r"(a) : "l"(p));
    return a;
}
__device__ __forceinline__ void ldsm_x4(uint32_t& r0, uint32_t& r1, uint32_t& r2,
                                        uint32_t& r3, uint32_t addr) {
    asm volatile("ldmatrix.sync.aligned.m8n8.x4.shared.b16 {%0,%1,%2,%3}, [%4];"
                 : "=r"(r0), "=r"(r1), "=r"(r2), "=r"(r3) : "r"(addr));
}
__device__ __forceinline__ void mma_bf16(float* d, const uint32_t* a, uint32_t b0, uint32_t b1) {
    asm volatile("mma.sync.aligned.m16n8k16.row.col.f32.bf16.bf16.f32 "
                 "{%0,%1,%2,%3},{%4,%5,%6,%7},{%8,%9},{%0,%1,%2,%3};"
                 : "+f"(d[0]), "+f"(d[1]), "+f"(d[2]), "+f"(d[3])
                 : "r"(a[0]), "r"(a[1]), "r"(a[2]), "r"(a[3]), "r"(b0), "r"(b1));
}

// =====================================================================
// Split-precision bf16 mma GEMM: C[M,N] = alpha*(A[M,K] @ B[N,K]^T) (+res)
// fp32 inputs converted on the fly to bf16 hi(/lo) planes in smem.
// NP=1: single pass (hi*hi).  NP=3: hi*hi + hi*lo + lo*hi (fp32-grade).
// Tile 128 x BN (BN in {64,128}), BK=32, 256 threads, 2-stage pipeline.
// aHead/cHead: base = (z>>4)*TT*ld + (z&15)*DH (per-head slicing of [token][1024]).
// =====================================================================
template<int NP, int BN>
__global__ void __launch_bounds__(256)
mma_gemm(const float* __restrict__ A, int lda, size_t aZ, int aHead,
         const float* __restrict__ B, int ldb, size_t bZ,
         float* __restrict__ C, int ldc, size_t cZ, int cHead,
         const float* __restrict__ res, int K, float alpha)
{
    constexpr int NPL = (NP == 1) ? 1 : 2;
    constexpr int APL = 128 * 64;            // bytes per A plane (128 rows x 64B)
    constexpr int BPL = BN * 64;
    constexpr int STG = NPL * (APL + BPL);   // bytes per stage
    constexpr int AU  = 128 * 4;             // A 16B-column units
    constexpr int UNITS = AU + BN * 4;
    constexpr int UPT = UNITS / 256;
    constexpr int MF = (BN == 128) ? 4 : 2;  // m16 frags per warp
    constexpr int NF = 4;                    // n8 frags per warp (32 cols)

    extern __shared__ char sm[];
    const int tid = threadIdx.x, wid = tid >> 5, lane = tid & 31;
    const int bm = blockIdx.y * 128, bn = blockIdx.x * BN;
    const int z = blockIdx.z;
    const uint32_t smb = smem_u32(sm);

    const size_t abase = aHead ? ((size_t)(z >> 4) * TT * lda + (size_t)(z & 15) * DH)
                               : (size_t)z * aZ;
    const float* Ab = A + abase + (size_t)bm * lda;
    const float* Bb = B + (size_t)z * bZ + (size_t)bn * ldb;

    const int wr = (BN == 128) ? (wid >> 2) : (wid >> 1);
    const int wc = (BN == 128) ? (wid & 3)  : (wid & 1);
    const int mrow0 = wr * (MF * 16);
    const int ncol0 = wc * 32;

    float acc[MF][NF][4];
#pragma unroll
    for (int m = 0; m < MF; m++)
#pragma unroll
        for (int n = 0; n < NF; n++)
#pragma unroll
            for (int q = 0; q < 4; q++) acc[m][n][q] = 0.f;

    float4 pf[UPT][2];
    // prologue: prefetch chunk 0
#pragma unroll
    for (int u = 0; u < UPT; u++) {
        const int idx = u * 256 + tid;
        const float* p = (idx < AU)
            ? Ab + (size_t)(idx >> 2) * lda + (idx & 3) * 8
            : Bb + (size_t)((idx - AU) >> 2) * ldb + ((idx - AU) & 3) * 8;
        pf[u][0] = *(const float4*)p;
        pf[u][1] = *(const float4*)(p + 4);
    }

    const int NC = K >> 5;
    for (int c = 0; c < NC; ++c) {
        const int s = c & 1;
        // ---- convert + store to smem (SW-swizzled 64B rows) ----
#pragma unroll
        for (int u = 0; u < UPT; u++) {
            const int idx = u * 256 + tid;
            int r, c4, pbase, plsz;
            if (idx < AU) { r = idx >> 2; c4 = idx & 3; pbase = s * STG; plsz = APL; }
            else { const int j = idx - AU; r = j >> 2; c4 = j & 3; pbase = s * STG + NPL * APL; plsz = BPL; }
            const uint32_t off = (uint32_t)(r * 64 + ((c4 ^ ((r >> 1) & 3)) << 4));
            const float* f = (const float*)pf[u];
            uint32_t hi[4], lo[4];
#pragma unroll
            for (int q = 0; q < 4; q++) {
                __nv_bfloat162 hh;
                hh.x = __float2bfloat16(f[2*q]);
                hh.y = __float2bfloat16(f[2*q+1]);
                hi[q] = *(const uint32_t*)&hh;
                if (NPL == 2) {
                    __nv_bfloat162 ll;
                    ll.x = __float2bfloat16(f[2*q]   - __bfloat162float(hh.x));
                    ll.y = __float2bfloat16(f[2*q+1] - __bfloat162float(hh.y));
                    lo[q] = *(const uint32_t*)&ll;
                }
            }
            *(uint4*)(sm + pbase + off) = make_uint4(hi[0], hi[1], hi[2], hi[3]);
            if (NPL == 2)
                *(uint4*)(sm + pbase + plsz + off) = make_uint4(lo[0], lo[1], lo[2], lo[3]);
        }
        __syncthreads();
        // ---- prefetch next chunk (overlaps with MMA below) ----
        if (c + 1 < NC) {
            const int k0 = (c + 1) << 5;
#pragma unroll
            for (int u = 0; u < UPT; u++) {
                const int idx = u * 256 + tid;
                const float* p = (idx < AU)
                    ? Ab + (size_t)(idx >> 2) * lda + k0 + (idx & 3) * 8
                    : Bb + (size_t)((idx - AU) >> 2) * ldb + k0 + ((idx - AU) & 3) * 8;
                pf[u][0] = *(const float4*)p;
                pf[u][1] = *(const float4*)(p + 4);
            }
        }
        // ---- MMA on stage s ----
        const uint32_t aBase0 = smb + s * STG;
        const uint32_t bBase0 = aBase0 + NPL * APL;
#pragma unroll
        for (int p = 0; p < NP; p++) {
            const int pa = (p == 2) ? 1 : 0;
            const int pb = (p == 1) ? 1 : 0;
            const uint32_t aB = aBase0 + pa * APL;
            const uint32_t bB = bBase0 + pb * BPL;
#pragma unroll
            for (int ks = 0; ks < 2; ks++) {
                uint32_t af[MF][4];
#pragma unroll
                for (int m = 0; m < MF; m++) {
                    const int row = mrow0 + m * 16 + (lane & 15);
                    const int c16 = ks * 2 + (lane >> 4);
                    ldsm_x4(af[m][0], af[m][1], af[m][2], af[m][3],
                            aB + row * 64 + ((c16 ^ ((row >> 1) & 3)) << 4));
                }
                uint32_t bf[2][4];
#pragma unroll
                for (int g = 0; g < 2; g++) {
                    const int row = ncol0 + g * 16 + (lane & 15);
                    const int c16 = ks * 2 + (lane >> 4);
                    ldsm_x4(bf[g][0], bf[g][1], bf[g][2], bf[g][3],
                            bB + row * 64 + ((c16 ^ ((row >> 1) & 3)) << 4));
                }
#pragma unroll
                for (int m = 0; m < MF; m++)
#pragma unroll
                    for (int nf = 0; nf < NF; nf++)
                        mma_bf16(acc[m][nf], af[m], bf[nf >> 1][nf & 1], bf[nf >> 1][(nf & 1) + 2]);
            }
        }
    }

    // ---- epilogue ----
    const size_t cbase = cHead ? ((size_t)(z >> 4) * TT * ldc + (size_t)(z & 15) * DH)
                               : (size_t)z * cZ;
    float* Cb = C + cbase + (size_t)bm * ldc + bn;
    const float* Rb = res ? res + cbase + (size_t)bm * ldc + bn : (const float*)0;
#pragma unroll
    for (int m = 0; m < MF; m++) {
        const int r0 = mrow0 + m * 16 + (lane >> 2);
#pragma unroll
        for (int h = 0; h < 2; h++) {
            const int r = r0 + h * 8;
            float* crow = Cb + (size_t)r * ldc;
            const float* rrow = Rb ? Rb + (size_t)r * ldc : (const float*)0;
#pragma unroll
            for (int nf = 0; nf < NF; nf++) {
                const int col = ncol0 + nf * 8 + (lane & 3) * 2;
                float2 v;
                v.x = acc[m][nf][2*h + 0] * alpha;
                v.y = acc[m][nf][2*h + 1] * alpha;
                if (rrow) { v.x += rrow[col]; v.y += rrow[col + 1]; }
                *(float2*)(crow + col) = v;
            }
        }
    }
}

// =====================================================================
// Family basis pool -> scores, basis, resid (fp32)
// =====================================================================
__global__ void __launch_bounds__(256)
family_kernel(const float* __restrict__ x, const float* __restrict__ fgw,
              const float* __restrict__ proto, float* __restrict__ fs_out)
{
    __shared__ float xs[D_MODEL];
    __shared__ float sc[NFAM];
    const int row = blockIdx.x;
    const int tid = threadIdx.x;
    const float* xr = x + (size_t)row * D_MODEL;
    for (int d = tid; d < D_MODEL; d += 256) xs[d] = xr[d];
    __syncthreads();

    const int warp = tid >> 5, lane = tid & 31;
    for (int f = warp; f < NFAM; f += 8) {
        const float* w = fgw + (size_t)f * D_MODEL;
        float s = 0.f;
        for (int d = lane; d < D_MODEL; d += 32) s += xs[d] * w[d];
#pragma unroll
        for (int o = 16; o; o >>= 1) s += __shfl_xor_sync(0xffffffffu, s, o);
        if (lane == 0) sc[f] = s;
    }
    __syncthreads();

    if (tid < 32) {
        float m = fmaxf(sc[tid], sc[tid + 32]);
#pragma unroll
        for (int o = 16; o; o >>= 1) m = fmaxf(m, __shfl_xor_sync(0xffffffffu, m, o));
        const float e0 = __expf(sc[tid] - m);
        const float e1 = __expf(sc[tid + 32] - m);
        float s = e0 + e1;
#pragma unroll
        for (int o = 16; o; o >>= 1) s += __shfl_xor_sync(0xffffffffu, s, o);
        const float inv = 1.f / s;
        sc[tid]      = e0 * inv;
        sc[tid + 32] = e1 * inv;
    }
    __syncthreads();

    if (tid < NFAM) fs_out[(size_t)row * NFAM + tid] = sc[tid];

    for (int d = tid; d < D_MODEL; d += 256) {
        float b = 0.f;
#pragma unroll 8
        for (int f = 0; f < NFAM; f++) b += sc[f] * proto[f * D_MODEL + d];
        const size_t idx = (size_t)row * D_MODEL + d;
        g_basis[idx] = b;
        g_resid[idx] = xs[d] - b;
    }
}

// =====================================================================
// Top-16 candidates from approx coeffs, exact fp32 re-rank to top-8,
// gather offset + x_rec + sparsity.
// =====================================================================
__global__ void __launch_bounds__(256)
topk_kernel(const float* __restrict__ dict_w, const float* __restrict__ enc_w,
            const float* __restrict__ bias)
{
    __shared__ float sval[256 * NCAND];
    __shared__ int   sidx[256 * NCAND];
    __shared__ float rv[256];
    __shared__ int   ri[256];
    __shared__ int   rp[256];
    __shared__ int   candi[NCAND];
    __shared__ float exv[NCAND];
    __shared__ float selv[TOPK];
    __shared__ int   seli[TOPK];

    const int row = blockIdx.x;
    const int tid = threadIdx.x;
    const float* cr = g_coeffs + (size_t)row * DICT;

    // local top-16 (insertion)
    float lv[NCAND]; int li[NCAND];
#pragma unroll
    for (int r = 0; r < NCAND; r++) { lv[r] = -FLT_MAX; li[r] = 0x7fffffff; }
    for (int j = tid; j < DICT; j += 256) {
        const float v = cr[j];
        if (v > lv[NCAND-1]) {
            int p = NCAND - 1;
            while (p > 0 && lv[p-1] < v) { lv[p] = lv[p-1]; li[p] = li[p-1]; p--; }
            lv[p] = v; li[p] = j;
        }
    }
#pragma unroll
    for (int r = 0; r < NCAND; r++) { sval[tid*NCAND + r] = lv[r]; sidx[tid*NCAND + r] = li[r]; }
    __syncthreads();

    // 16 rounds of deterministic block argmax
    for (int sel = 0; sel < NCAND; sel++) {
        float bv = -FLT_MAX; int bi = 0x7fffffff; int bp = 0;
#pragma unroll
        for (int r = 0; r < NCAND; r++) {
            const int p = tid*NCAND + r;
            const float v = sval[p]; const int ix = sidx[p];
            if (v > bv || (v == bv && ix < bi)) { bv = v; bi = ix; bp = p; }
        }
        rv[tid] = bv; ri[tid] = bi; rp[tid] = bp;
        __syncthreads();
        for (int s = 128; s > 0; s >>= 1) {
            if (tid < s) {
                if (rv[tid+s] > rv[tid] || (rv[tid+s] == rv[tid] && ri[tid+s] < ri[tid])) {
                    rv[tid] = rv[tid+s]; ri[tid] = ri[tid+s]; rp[tid] = rp[tid+s];
                }
            }
            __syncthreads();
        }
        if (tid == 0) {
            candi[sel] = ri[0];
            sval[rp[0]] = -FLT_MAX; sidx[rp[0]] = 0x7fffffff;
        }
        __syncthreads();
    }

    // exact fp32 re-computation of the 16 candidate dot products
    {
        const int warp = tid >> 5, lane = tid & 31;
        const float* rr = g_resid + (size_t)row * D_MODEL;
        for (int j = warp; j < NCAND; j += 8) {
            const float* er = enc_w + (size_t)candi[j] * D_MODEL;
            float s = 0.f;
            for (int d = lane; d < D_MODEL; d += 32) s += rr[d] * er[d];
#pragma unroll
            for (int o = 16; o; o >>= 1) s += __shfl_xor_sync(0xffffffffu, s, o);
            if (lane == 0) exv[j] = s;
        }
    }
    __syncthreads();

    // thread 0: pick top-8 by (exact val desc, idx asc)
    if (tid == 0) {
        unsigned used = 0;
        float ssum = 0.f;
        for (int sel = 0; sel < TOPK; sel++) {
            float bv = -FLT_MAX; int bi = 0x7fffffff; int bp = -1;
            for (int j = 0; j < NCAND; j++) {
                if (used & (1u << j)) continue;
                const float v = exv[j]; const int ix = candi[j];
                if (v > bv || (v == bv && ix < bi)) { bv = v; bi = ix; bp = j; }
            }
            used |= (1u << bp);
            selv[sel] = bv; seli[sel] = bi;
            ssum += fabsf(bv);
        }
        g_spars[row] = ssum;
    }
    __syncthreads();

    for (int d = tid; d < D_MODEL; d += 256) {
        float o = g_basis[(size_t)row * D_MODEL + d] + bias[d];
#pragma unroll
        for (int j = 0; j < TOPK; j++) o += selv[j] * dict_w[(size_t)seli[j] * D_MODEL + d];
        g_xrec[(size_t)row * D_MODEL + d] = o;
    }
}

// =====================================================================
// RMSNorm (fp32 out)
// =====================================================================
__global__ void __launch_bounds__(256)
rmsnorm_kernel(const float* __restrict__ in, const float* __restrict__ w,
               float* __restrict__ out, float* __restrict__ rmsbuf)
{
    __shared__ float red[256];
    const int row = blockIdx.x, tid = threadIdx.x;
    const float* xr = in + (size_t)row * D_MODEL;
    float s = 0.f;
    for (int d = tid; d < D_MODEL; d += 256) { const float v = xr[d]; s += v * v; }
    red[tid] = s;
    __syncthreads();
    for (int st = 128; st > 0; st >>= 1) { if (tid < st) red[tid] += red[tid + st]; __syncthreads(); }
    const float rms = sqrtf(red[0] / (float)D_MODEL + EPS_F);
    const float inv = 1.f / rms;
    for (int d = tid; d < D_MODEL; d += 256)
        out[(size_t)row * D_MODEL + d] = w[d] * xr[d] * inv;
    if (tid == 0) rmsbuf[row] = rms;
}

// =====================================================================
// k_mod[bh][t][e] = sum_d k[b,t,h*64+d] * templ[h,d,e]   (fp32)
// =====================================================================
__global__ void __launch_bounds__(256)
kmod_kernel(const float* __restrict__ kbuf, const float* __restrict__ rel)
{
    __shared__ float ks[64][65];
    __shared__ float ts[64][65];
    const int bh = blockIdx.y, b = bh >> 4, h = bh & 15;
    const int t0 = blockIdx.x * 64;
    const int tid = threadIdx.x;
    for (int i = tid; i < 4096; i += 256) {
        const int r = i >> 6, c = i & 63;
        ks[r][c] = kbuf[(size_t)(b*TT + t0 + r) * D_MODEL + h*DH + c];
        ts[r][c] = rel[(size_t)h*DH*DH + r*DH + c];
    }
    __syncthreads();
    const int tx = tid & 15, ty = tid >> 4;
    float acc[4][4] = {};
#pragma unroll
    for (int d = 0; d < 64; d++) {
        float ra[4], rb[4];
#pragma unroll
        for (int i = 0; i < 4; i++) ra[i] = ks[ty*4 + i][d];
#pragma unroll
        for (int j = 0; j < 4; j++) rb[j] = ts[d][tx*4 + j];
#pragma unroll
        for (int i = 0; i < 4; i++)
#pragma unroll
            for (int j = 0; j < 4; j++) acc[i][j] += ra[i] * rb[j];
    }
#pragma unroll
    for (int i = 0; i < 4; i++)
#pragma unroll
        for (int j = 0; j < 4; j++)
            g_kmod[((size_t)bh*TT + t0 + ty*4 + i) * DH + tx*4 + j] = acc[i][j];
}

// =====================================================================
// V transpose pack: g_v [b,t,h*64+e] -> g_vt [bh][e][t]
// =====================================================================
__global__ void __launch_bounds__(256)
vtrans_kernel(const float* __restrict__ v)
{
    __shared__ float t[64][65];
    const int z = blockIdx.y, b = z >> 4, h = z & 15;
    const int t0 = blockIdx.x * 64;
    for (int i = threadIdx.x; i < 4096; i += 256) {
        const int r = i >> 6, c = i & 63;
        t[r][c] = v[(size_t)(b*TT + t0 + r) * D_MODEL + h*DH + c];
    }
    __syncthreads();
    for (int i = threadIdx.x; i < 4096; i += 256) {
        const int e = i >> 6, r = i & 63;
        g_vt[(size_t)z * DH * TT + (size_t)e * TT + t0 + r] = t[r][e];
    }
}

// =====================================================================
// Row softmax over 2048, in place
// =====================================================================
__global__ void __launch_bounds__(256)
softmax_kernel(float* __restrict__ P)
{
    __shared__ float red[256];
    const size_t row = blockIdx.x;
    float* p = P + row * (size_t)TT;
    const int tid = threadIdx.x;
    float v[8];
#pragma unroll
    for (int i = 0; i < 8; i++) v[i] = p[tid + i*256];
    float m = v[0];
#pragma unroll
    for (int i = 1; i < 8; i++) m = fmaxf(m, v[i]);
    red[tid] = m;
    __syncthreads();
    for (int st = 128; st > 0; st >>= 1) { if (tid < st) red[tid] = fmaxf(red[tid], red[tid+st]); __syncthreads(); }
    m = red[0];
    __syncthreads();
    float s = 0.f;
#pragma unroll
    for (int i = 0; i < 8; i++) { v[i] = __expf(v[i] - m); s += v[i]; }
    red[tid] = s;
    __syncthreads();
    for (int st = 128; st > 0; st >>= 1) { if (tid < st) red[tid] += red[tid+st]; __syncthreads(); }
    const float inv = 1.f / red[0];
#pragma unroll
    for (int i = 0; i < 8; i++) p[tid + i*256] = v[i] * inv;
}

// =====================================================================
// h = sigmoid(gate) * silu(up)  (in place over g_gate)
// =====================================================================
__global__ void __launch_bounds__(256)
gateup_kernel()
{
    const size_t n = (size_t)BT * D_FF;
    for (size_t i = (size_t)blockIdx.x * blockDim.x + threadIdx.x; i < n;
         i += (size_t)gridDim.x * blockDim.x) {
        const float g = g_gate[i], u = g_up[i];
        const float sg = 1.f / (1.f + __expf(-g));
        const float su = u / (1.f + __expf(-u));
        g_gate[i] = sg * su;
    }
}

// =====================================================================
// Final scalars
// =====================================================================
__global__ void __launch_bounds__(256)
finalize_kernel(float* __restrict__ out)
{
    __shared__ float s1[256], s2[256], s3[256];
    const int tid = threadIdx.x;
    float a = 0.f, b = 0.f, c = 0.f;
    for (int i = tid; i < BT; i += 256) { a += g_spars[i]; b += g_rms1[i]; c += g_rms2[i]; }
    s1[tid] = a; s2[tid] = b; s3[tid] = c;
    __syncthreads();
    for (int st = 128; st > 0; st >>= 1) {
        if (tid < st) { s1[tid] += s1[tid+st]; s2[tid] += s2[tid+st]; s3[tid] += s3[tid+st]; }
        __syncthreads();
    }
    if (tid == 0) {
        out[SC_OFF + 0] = s1[0] / ((float)BB * (float)TT * (float)DICT);
        out[SC_OFF + 1] = s2[0] / (float)BT;
        out[SC_OFF + 2] = s3[0] / (float)BT;
    }
}

// =====================================================================
// host launcher
// =====================================================================
extern "C" void kernel_launch(void* const* d_in, const int* in_sizes, int n_in,
                              void* d_out, int out_size)
{
    (void)in_sizes; (void)n_in; (void)out_size;
    const float* x     = (const float*)d_in[0];
    const float* proto = (const float*)d_in[2];
    const float* fgw   = (const float*)d_in[3];
    const float* dictw = (const float*)d_in[4];
    const float* encw  = (const float*)d_in[5];
    const float* wq    = (const float*)d_in[6];
    const float* wk    = (const float*)d_in[7];
    const float* wv    = (const float*)d_in[8];
    const float* wo    = (const float*)d_in[9];
    const float* rel   = (const float*)d_in[10];
    const float* gatew = (const float*)d_in[11];
    const float* upw   = (const float*)d_in[12];
    const float* downw = (const float*)d_in[13];
    const float* n1w   = (const float*)d_in[14];
    const float* n2w   = (const float*)d_in[15];
    const float* bias  = (const float*)d_in[16];
    float* out = (float*)d_out;

    const int SM_1_128 = 2 * (1 * (128*64 + 128*64));   // 32 KB
    const int SM_3_128 = 2 * (2 * (128*64 + 128*64));   // 64 KB
    const int SM_3_64  = 2 * (2 * (128*64 +  64*64));   // 48 KB
    cudaFuncSetAttribute(mma_gemm<1,128>, cudaFuncAttributeMaxDynamicSharedMemorySize, SM_1_128);
    cudaFuncSetAttribute(mma_gemm<3,128>, cudaFuncAttributeMaxDynamicSharedMemorySize, SM_3_128);
    cudaFuncSetAttribute(mma_gemm<3,64>,  cudaFuncAttributeMaxDynamicSharedMemorySize, SM_3_64);

    float *p_resid, *p_xrec, *p_normed, *p_normed2, *p_q, *p_k, *p_v, *p_kmod,
          *p_vt, *p_ctx, *p_x2, *p_coeffs, *p_gate, *p_up, *p_rms1, *p_rms2;
    cudaGetSymbolAddress((void**)&p_resid,   g_resid);
    cudaGetSymbolAddress((void**)&p_xrec,    g_xrec);
    cudaGetSymbolAddress((void**)&p_normed,  g_normed);
    cudaGetSymbolAddress((void**)&p_normed2, g_normed2);
    cudaGetSymbolAddress((void**)&p_q,       g_q);
    cudaGetSymbolAddress((void**)&p_k,       g_k);
    cudaGetSymbolAddress((void**)&p_v,       g_v);
    cudaGetSymbolAddress((void**)&p_kmod,    g_kmod);
    cudaGetSymbolAddress((void**)&p_vt,      g_vt);
    cudaGetSymbolAddress((void**)&p_ctx,     g_ctx);
    cudaGetSymbolAddress((void**)&p_x2,      g_x2);
    cudaGetSymbolAddress((void**)&p_coeffs,  g_coeffs);
    cudaGetSymbolAddress((void**)&p_gate,    g_gate);
    cudaGetSymbolAddress((void**)&p_up,      g_up);
    cudaGetSymbolAddress((void**)&p_rms1,    g_rms1);
    cudaGetSymbolAddress((void**)&p_rms2,    g_rms2);

    // 1) family pool: scores -> d_out, basis, resid
    family_kernel<<<BT, 256>>>(x, fgw, proto, out + FS_OFF);

    // 2) approx coeffs = resid @ enc^T (bf16 1-pass; exact re-rank in topk)
    mma_gemm<1,128><<<dim3(DICT/128, BT/128, 1), 256, SM_1_128>>>(
        p_resid, D_MODEL, 0, 0, encw, D_MODEL, 0, p_coeffs, DICT, 0, 0,
        nullptr, D_MODEL, 1.0f);

    // 3) top-16 candidates + exact fp32 re-rank -> x_rec, sparsity
    topk_kernel<<<BT, 256>>>(dictw, encw, bias);

    // 4) norm1
    rmsnorm_kernel<<<BT, 256>>>(p_xrec, n1w, p_normed, p_rms1);

    // 5) q,k,v projections (split-precision)
    mma_gemm<3,128><<<dim3(D_MODEL/128, BT/128, 1), 256, SM_3_128>>>(
        p_normed, D_MODEL, 0, 0, wq, D_MODEL, 0, p_q, D_MODEL, 0, 0, nullptr, D_MODEL, 1.0f);
    mma_gemm<3,128><<<dim3(D_MODEL/128, BT/128, 1), 256, SM_3_128>>>(
        p_normed, D_MODEL, 0, 0, wk, D_MODEL, 0, p_k, D_MODEL, 0, 0, nullptr, D_MODEL, 1.0f);
    mma_gemm<3,128><<<dim3(D_MODEL/128, BT/128, 1), 256, SM_3_128>>>(
        p_normed, D_MODEL, 0, 0, wv, D_MODEL, 0, p_v, D_MODEL, 0, 0, nullptr, D_MODEL, 1.0f);

    // 6) k_mod (fp32) + V transpose pack
    kmod_kernel<<<dim3(TT/64, BB*N_HEADS), 256>>>(p_k, rel);
    vtrans_kernel<<<dim3(TT/64, BB*N_HEADS), 256>>>(p_v);

    // 7) attn logits (batched, per-head A slice) -> d_out, softmax in place
    mma_gemm<3,128><<<dim3(TT/128, TT/128, BB*N_HEADS), 256, SM_3_128>>>(
        p_q, D_MODEL, 0, 1, p_kmod, DH, (size_t)TT*DH,
        out + ATT_OFF, TT, (size_t)TT*TT, 0, nullptr, DH, 0.125f);
    softmax_kernel<<<BB*N_HEADS*TT, 256>>>(out + ATT_OFF);

    // 8) ctx = attn @ v (batched, head-sliced C)
    mma_gemm<3,64><<<dim3(1, TT/128, BB*N_HEADS), 256, SM_3_64>>>(
        out + ATT_OFF, TT, (size_t)TT*TT, 0, p_vt, TT, (size_t)DH*TT,
        p_ctx, D_MODEL, 0, 1, nullptr, TT, 1.0f);

    // 9) x2 = x + ctx @ wo^T
    mma_gemm<3,128><<<dim3(D_MODEL/128, BT/128, 1), 256, SM_3_128>>>(
        p_ctx, D_MODEL, 0, 0, wo, D_MODEL, 0, p_x2, D_MODEL, 0, 0, x, D_MODEL, 1.0f);

    // 10) norm2
    rmsnorm_kernel<<<BT, 256>>>(p_x2, n2w, p_normed2, p_rms2);

    // 11) FFN
    mma_gemm<3,128><<<dim3(D_FF/128, BT/128, 1), 256, SM_3_128>>>(
        p_normed2, D_MODEL, 0, 0, gatew, D_MODEL, 0, p_gate, D_FF, 0, 0, nullptr, D_MODEL, 1.0f);
    mma_gemm<3,128><<<dim3(D_FF/128, BT/128, 1), 256, SM_3_128>>>(
        p_normed2, D_MODEL, 0, 0, upw, D_MODEL, 0, p_up, D_FF, 0, 0, nullptr, D_MODEL, 1.0f);
    gateup_kernel<<<8192, 256>>>();

    // 12) final x = x2 + h @ down^T -> d_out
    mma_gemm<3,128><<<dim3(D_MODEL/128, BT/128, 1), 256, SM_3_128>>>(
        p_gate, D_FF, 0, 0, downw, D_FF, 0, out + X_OFF, D_MODEL, 0, 0, p_x2, D_FF, 1.0f);

    // 13) scalars
    finalize_kernel<<<1, 256>>>(out);
}

// round 10
// speedup vs baseline: 1.6425x; 1.1245x over previous
#include <cuda_runtime.h>
#include <cuda_bf16.h>
#include <math.h>
#include <float.h>
#include <stdint.h>

// ---------------- problem dims (fixed by setup_inputs) ----------------
#define D_MODEL 1024
#define N_HEADS 16
#define DH      64
#define D_FF    4096
#define NFAM    64
#define DICT    16384
#define BB      2
#define TT      2048
#define BT      (BB*TT)
#define TOPK    8
#define NCAND   16
#define EPS_F   1e-6f

#define X_N     ((size_t)BT * D_MODEL)
#define ATT_N   ((size_t)BB * N_HEADS * TT * TT)
#define FS_N    ((size_t)BT * NFAM)
#define X_OFF   ((size_t)0)
#define ATT_OFF (X_N)
#define FS_OFF  (X_N + ATT_N)
#define SC_OFF  (X_N + ATT_N + FS_N)

#define PD   ((size_t)BT * D_MODEL)
#define PW   ((size_t)D_MODEL * D_MODEL)
#define PF   ((size_t)D_FF * D_MODEL)
#define PH   ((size_t)BT * D_FF)
#define PE   ((size_t)DICT * D_MODEL)

// ---------------- fp32 scratch ----------------
__device__ float g_resid  [BT * D_MODEL];
__device__ float g_basis  [BT * D_MODEL];
__device__ float g_xrec   [BT * D_MODEL];
__device__ float g_k      [BT * D_MODEL];
__device__ float g_v      [BT * D_MODEL];
__device__ float g_x2     [BT * D_MODEL];
__device__ float g_coeffs [(size_t)BT * DICT];
__device__ float g_gate   [(size_t)BT * D_FF];
__device__ float g_up     [(size_t)BT * D_FF];
__device__ float g_rms1   [BT];
__device__ float g_rms2   [BT];
__device__ float g_spars  [BT];

// ---------------- bf16 planes (hi at [0], lo at [+plane]) ----------------
__device__ __align__(16) __nv_bfloat16 b_resid_h[PD];
__device__ __align__(16) __nv_bfloat16 b_enc_h  [PE];
__device__ __align__(16) __nv_bfloat16 b_normed [2 * PD];
__device__ __align__(16) __nv_bfloat16 b_normed2[2 * PD];
__device__ __align__(16) __nv_bfloat16 b_q      [2 * PD];
__device__ __align__(16) __nv_bfloat16 b_kmod   [2 * PD];   // [bh][t][64]
__device__ __align__(16) __nv_bfloat16 b_vt     [2 * PD];   // [bh][64][t]
__device__ __align__(16) __nv_bfloat16 b_ctx    [2 * PD];
__device__ __align__(16) __nv_bfloat16 b_h      [2 * PH];
__device__ __align__(16) __nv_bfloat16 b_wq     [2 * PW];
__device__ __align__(16) __nv_bfloat16 b_wk     [2 * PW];
__device__ __align__(16) __nv_bfloat16 b_wv     [2 * PW];
__device__ __align__(16) __nv_bfloat16 b_wo     [2 * PW];
__device__ __align__(16) __nv_bfloat16 b_gw     [2 * PF];
__device__ __align__(16) __nv_bfloat16 b_uw     [2 * PF];
__device__ __align__(16) __nv_bfloat16 b_dw     [2 * PF];
__device__ __align__(16) __nv_bfloat16 b_attn   [2 * ATT_N];

// ===================== helpers (baseline PTX, sm_80+) =========
__device__ __forceinline__ uint32_t smem_u32(const void* p) {
    uint32_t a;
    asm("{ .reg .u64 t; cvta.to.shared.u64 t, %1; cvt.u32.u64 %0, t; }" : "=r"(a) : "l"(p));
    return a;
}
__device__ __forceinline__ void ldsm_x4(uint32_t& r0, uint32_t& r1, uint32_t& r2,
                                        uint32_t& r3, uint32_t addr) {
    asm volatile("ldmatrix.sync.aligned.m8n8.x4.shared.b16 {%0,%1,%2,%3}, [%4];"
                 : "=r"(r0), "=r"(r1), "=r"(r2), "=r"(r3) : "r"(addr));
}
__device__ __forceinline__ void mma_bf16(float* d, const uint32_t* a, uint32_t b0, uint32_t b1) {
    asm volatile("mma.sync.aligned.m16n8k16.row.col.f32.bf16.bf16.f32 "
                 "{%0,%1,%2,%3},{%4,%5,%6,%7},{%8,%9},{%0,%1,%2,%3};"
                 : "+f"(d[0]), "+f"(d[1]), "+f"(d[2]), "+f"(d[3])
                 : "r"(a[0]), "r"(a[1]), "r"(a[2]), "r"(a[3]), "r"(b0), "r"(b1));
}
__device__ __forceinline__ void cpa16(uint32_t dst, const void* src) {
    asm volatile("cp.async.cg.shared.global [%0], [%1], 16;" :: "r"(dst), "l"(src) : "memory");
}
__device__ __forceinline__ void cpa_commit() { asm volatile("cp.async.commit_group;" ::: "memory"); }
__device__ __forceinline__ void cpa_wait1()  { asm volatile("cp.async.wait_group 1;" ::: "memory"); }
__device__ __forceinline__ void cpa_wait0()  { asm volatile("cp.async.wait_group 0;" ::: "memory"); }

// =====================================================================
// Split-precision bf16 mma GEMM on pre-split planes.
// C[M,N] = alpha*(A @ B^T) (+res).  A,B: bf16 hi plane ptr, lo at +plane.
// NP=1: hi*hi.  NP=3: hh + h*l + l*h.  BK=32, 3-stage cp.async pipeline.
// OUT=0: fp32 C.  OUT=1: bf16 hi/lo planes Cp / Cp+cPlane.
// aHead/cHead: base = (z>>4)*TT*ld + (z&15)*DH.
// =====================================================================
template<int NP, int BN, int OUT>
__global__ void __launch_bounds__(256, 2)
mma_gemm(const __nv_bfloat16* __restrict__ A, size_t aPlane, int lda, size_t aZ, int aHead,
         const __nv_bfloat16* __restrict__ B, size_t bPlane, int ldb, size_t bZ,
         float* __restrict__ C, int ldc, size_t cZ, int cHead,
         __nv_bfloat16* __restrict__ Cp, size_t cPlane,
         const float* __restrict__ res, int K, float alpha)
{
    constexpr int NPL = (NP == 1) ? 1 : 2;
    constexpr int APL = 128 * 64;                  // bytes per A plane tile
    constexpr int BPL = BN * 64;
    constexpr int STG = NPL * (APL + BPL);
    constexpr int AUNITS = NPL * 128 * 4;          // 16B units
    constexpr int BUN1 = BN * 4;
    constexpr int UNITS = AUNITS + NPL * BUN1;
    constexpr int MF = (BN == 128) ? 4 : 2;
    constexpr int NF = 4;

    extern __shared__ char sm[];
    const int tid = threadIdx.x, wid = tid >> 5, lane = tid & 31;
    const int bm = blockIdx.y * 128, bn = blockIdx.x * BN;
    const int z = blockIdx.z;
    const uint32_t smb = smem_u32(sm);

    const size_t abase = aHead ? ((size_t)(z >> 4) * TT * lda + (size_t)(z & 15) * DH)
                               : (size_t)z * aZ;
    const __nv_bfloat16* Ab = A + abase + (size_t)bm * lda;
    const __nv_bfloat16* Bb = B + (size_t)z * bZ + (size_t)bn * ldb;

    const int wr = (BN == 128) ? (wid >> 2) : (wid >> 1);
    const int wc = (BN == 128) ? (wid & 3)  : (wid & 1);
    const int mrow0 = wr * (MF * 16);
    const int ncol0 = wc * 32;

    float acc[MF][NF][4];
#pragma unroll
    for (int m = 0; m < MF; m++)
#pragma unroll
        for (int n = 0; n < NF; n++)
#pragma unroll
            for (int q = 0; q < 4; q++) acc[m][n][q] = 0.f;

    const int NC = K >> 5;

    // ---- async load of one chunk into a stage ----
    auto issue = [&](int c, int stage) {
        const int k0 = c << 5;
        const uint32_t sb = smb + stage * STG;
#pragma unroll
        for (int u = 0; u < UNITS / 256; u++) {
            const int idx = u * 256 + tid;
            if (idx < AUNITS) {
                const int p = idx >> 9;
                const int j = idx & 511;
                const int r = j >> 2, c4 = j & 3;
                const uint32_t off = (uint32_t)(r * 64 + (((c4) ^ ((r >> 1) & 3)) << 4));
                cpa16(sb + p * APL + off,
                      Ab + (size_t)p * aPlane + (size_t)r * lda + k0 + c4 * 8);
            } else {
                const int j = idx - AUNITS;
                const int p = (BN == 128) ? (j >> 9) : (j >> 8);
                const int jj = j & (BUN1 - 1);
                const int r = jj >> 2, c4 = jj & 3;
                const uint32_t off = (uint32_t)(r * 64 + (((c4) ^ ((r >> 1) & 3)) << 4));
                cpa16(sb + NPL * APL + p * BPL + off,
                      Bb + (size_t)p * bPlane + (size_t)r * ldb + k0 + c4 * 8);
            }
        }
        cpa_commit();
    };

    // prologue: chunks 0,1 (NC >= 2 at all call sites)
    issue(0, 0);
    issue(1, 1);

    for (int c = 0; c < NC; ++c) {
        if (c < NC - 1) cpa_wait1(); else cpa_wait0();
        __syncthreads();
        if (c + 2 < NC) issue(c + 2, (c + 2) % 3);

        const uint32_t aBase0 = smb + (c % 3) * STG;
        const uint32_t bBase0 = aBase0 + NPL * APL;
#pragma unroll
        for (int p = 0; p < NP; p++) {
            const int pa = (p == 2) ? 1 : 0;
            const int pb = (p == 1) ? 1 : 0;
            const uint32_t aB = aBase0 + pa * APL;
            const uint32_t bB = bBase0 + pb * BPL;
#pragma unroll
            for (int ks = 0; ks < 2; ks++) {
                uint32_t af[MF][4];
#pragma unroll
                for (int m = 0; m < MF; m++) {
                    const int row = mrow0 + m * 16 + (lane & 15);
                    const int c16 = ks * 2 + (lane >> 4);
                    ldsm_x4(af[m][0], af[m][1], af[m][2], af[m][3],
                            aB + row * 64 + ((c16 ^ ((row >> 1) & 3)) << 4));
                }
                uint32_t bf[2][4];
#pragma unroll
                for (int g = 0; g < 2; g++) {
                    const int row = ncol0 + g * 16 + (lane & 15);
                    const int c16 = ks * 2 + (lane >> 4);
                    ldsm_x4(bf[g][0], bf[g][1], bf[g][2], bf[g][3],
                            bB + row * 64 + ((c16 ^ ((row >> 1) & 3)) << 4));
                }
#pragma unroll
                for (int m = 0; m < MF; m++)
#pragma unroll
                    for (int nf = 0; nf < NF; nf++)
                        mma_bf16(acc[m][nf], af[m], bf[nf >> 1][nf & 1], bf[nf >> 1][(nf & 1) + 2]);
            }
        }
    }

    // ---- epilogue ----
    const size_t cbase = cHead ? ((size_t)(z >> 4) * TT * ldc + (size_t)(z & 15) * DH)
                               : (size_t)z * cZ;
    if (OUT == 0) {
        float* Cb = C + cbase + (size_t)bm * ldc + bn;
        const float* Rb = res ? res + cbase + (size_t)bm * ldc + bn : (const float*)0;
#pragma unroll
        for (int m = 0; m < MF; m++) {
            const int r0 = mrow0 + m * 16 + (lane >> 2);
#pragma unroll
            for (int h = 0; h < 2; h++) {
                const int r = r0 + h * 8;
                float* crow = Cb + (size_t)r * ldc;
                const float* rrow = Rb ? Rb + (size_t)r * ldc : (const float*)0;
#pragma unroll
                for (int nf = 0; nf < NF; nf++) {
                    const int col = ncol0 + nf * 8 + (lane & 3) * 2;
                    float2 v;
                    v.x = acc[m][nf][2*h + 0] * alpha;
                    v.y = acc[m][nf][2*h + 1] * alpha;
                    if (rrow) { v.x += rrow[col]; v.y += rrow[col + 1]; }
                    *(float2*)(crow + col) = v;
                }
            }
        }
    } else {
        __nv_bfloat16* Ch = Cp + cbase + (size_t)bm * ldc + bn;
        __nv_bfloat16* Cl = Ch + cPlane;
#pragma unroll
        for (int m = 0; m < MF; m++) {
            const int r0 = mrow0 + m * 16 + (lane >> 2);
#pragma unroll
            for (int h = 0; h < 2; h++) {
                const int r = r0 + h * 8;
#pragma unroll
                for (int nf = 0; nf < NF; nf++) {
                    const int col = ncol0 + nf * 8 + (lane & 3) * 2;
                    const float vx = acc[m][nf][2*h + 0];
                    const float vy = acc[m][nf][2*h + 1];
                    __nv_bfloat162 hh, ll;
                    hh.x = __float2bfloat16(vx);
                    hh.y = __float2bfloat16(vy);
                    ll.x = __float2bfloat16(vx - __bfloat162float(hh.x));
                    ll.y = __float2bfloat16(vy - __bfloat162float(hh.y));
                    *(__nv_bfloat162*)(Ch + (size_t)r * ldc + col) = hh;
                    *(__nv_bfloat162*)(Cl + (size_t)r * ldc + col) = ll;
                }
            }
        }
    }
}

// =====================================================================
// weight split kernels
// =====================================================================
__global__ void __launch_bounds__(256)
split2_kernel(const float* __restrict__ s, __nv_bfloat16* __restrict__ hi,
              __nv_bfloat16* __restrict__ lo, size_t n2)
{
    const float2* s2 = (const float2*)s;
    __nv_bfloat162* h2 = (__nv_bfloat162*)hi;
    __nv_bfloat162* l2 = (__nv_bfloat162*)lo;
    for (size_t i = (size_t)blockIdx.x * 256 + threadIdx.x; i < n2; i += (size_t)gridDim.x * 256) {
        const float2 v = s2[i];
        __nv_bfloat162 h, l;
        h.x = __float2bfloat16(v.x); h.y = __float2bfloat16(v.y);
        l.x = __float2bfloat16(v.x - __bfloat162float(h.x));
        l.y = __float2bfloat16(v.y - __bfloat162float(h.y));
        h2[i] = h; l2[i] = l;
    }
}
__global__ void __launch_bounds__(256)
split1_kernel(const float* __restrict__ s, __nv_bfloat16* __restrict__ hi, size_t n2)
{
    const float2* s2 = (const float2*)s;
    __nv_bfloat162* h2 = (__nv_bfloat162*)hi;
    for (size_t i = (size_t)blockIdx.x * 256 + threadIdx.x; i < n2; i += (size_t)gridDim.x * 256) {
        const float2 v = s2[i];
        __nv_bfloat162 h;
        h.x = __float2bfloat16(v.x); h.y = __float2bfloat16(v.y);
        h2[i] = h;
    }
}

// =====================================================================
// Family basis pool -> scores, basis, resid fp32 + resid hi plane
// =====================================================================
__global__ void __launch_bounds__(256)
family_kernel(const float* __restrict__ x, const float* __restrict__ fgw,
              const float* __restrict__ proto, float* __restrict__ fs_out)
{
    __shared__ float xs[D_MODEL];
    __shared__ float sc[NFAM];
    const int row = blockIdx.x;
    const int tid = threadIdx.x;
    const float* xr = x + (size_t)row * D_MODEL;
    for (int d = tid; d < D_MODEL; d += 256) xs[d] = xr[d];
    __syncthreads();

    const int warp = tid >> 5, lane = tid & 31;
    for (int f = warp; f < NFAM; f += 8) {
        const float* w = fgw + (size_t)f * D_MODEL;
        float s = 0.f;
        for (int d = lane; d < D_MODEL; d += 32) s += xs[d] * w[d];
#pragma unroll
        for (int o = 16; o; o >>= 1) s += __shfl_xor_sync(0xffffffffu, s, o);
        if (lane == 0) sc[f] = s;
    }
    __syncthreads();

    if (tid < 32) {
        float m = fmaxf(sc[tid], sc[tid + 32]);
#pragma unroll
        for (int o = 16; o; o >>= 1) m = fmaxf(m, __shfl_xor_sync(0xffffffffu, m, o));
        const float e0 = __expf(sc[tid] - m);
        const float e1 = __expf(sc[tid + 32] - m);
        float s = e0 + e1;
#pragma unroll
        for (int o = 16; o; o >>= 1) s += __shfl_xor_sync(0xffffffffu, s, o);
        const float inv = 1.f / s;
        sc[tid]      = e0 * inv;
        sc[tid + 32] = e1 * inv;
    }
    __syncthreads();

    if (tid < NFAM) fs_out[(size_t)row * NFAM + tid] = sc[tid];

    for (int d = tid; d < D_MODEL; d += 256) {
        float b = 0.f;
#pragma unroll 8
        for (int f = 0; f < NFAM; f++) b += sc[f] * proto[f * D_MODEL + d];
        const size_t idx = (size_t)row * D_MODEL + d;
        g_basis[idx] = b;
        const float r = xs[d] - b;
        g_resid[idx] = r;
        b_resid_h[idx] = __float2bfloat16(r);
    }
}

// =====================================================================
// Top-16 candidates from approx coeffs, exact fp32 re-rank to top-8.
// =====================================================================
__global__ void __launch_bounds__(256)
topk_kernel(const float* __restrict__ dict_w, const float* __restrict__ enc_w,
            const float* __restrict__ bias)
{
    __shared__ float sval[256 * NCAND];
    __shared__ int   sidx[256 * NCAND];
    __shared__ float rv[256];
    __shared__ int   ri[256];
    __shared__ int   rp[256];
    __shared__ int   candi[NCAND];
    __shared__ float exv[NCAND];
    __shared__ float selv[TOPK];
    __shared__ int   seli[TOPK];

    const int row = blockIdx.x;
    const int tid = threadIdx.x;
    const float* cr = g_coeffs + (size_t)row * DICT;

    float lv[NCAND]; int li[NCAND];
#pragma unroll
    for (int r = 0; r < NCAND; r++) { lv[r] = -FLT_MAX; li[r] = 0x7fffffff; }
    for (int j = tid; j < DICT; j += 256) {
        const float v = cr[j];
        if (v > lv[NCAND-1]) {
            int p = NCAND - 1;
            while (p > 0 && lv[p-1] < v) { lv[p] = lv[p-1]; li[p] = li[p-1]; p--; }
            lv[p] = v; li[p] = j;
        }
    }
#pragma unroll
    for (int r = 0; r < NCAND; r++) { sval[tid*NCAND + r] = lv[r]; sidx[tid*NCAND + r] = li[r]; }
    __syncthreads();

    for (int sel = 0; sel < NCAND; sel++) {
        float bv = -FLT_MAX; int bi = 0x7fffffff; int bp = 0;
#pragma unroll
        for (int r = 0; r < NCAND; r++) {
            const int p = tid*NCAND + r;
            const float v = sval[p]; const int ix = sidx[p];
            if (v > bv || (v == bv && ix < bi)) { bv = v; bi = ix; bp = p; }
        }
        rv[tid] = bv; ri[tid] = bi; rp[tid] = bp;
        __syncthreads();
        for (int s = 128; s > 0; s >>= 1) {
            if (tid < s) {
                if (rv[tid+s] > rv[tid] || (rv[tid+s] == rv[tid] && ri[tid+s] < ri[tid])) {
                    rv[tid] = rv[tid+s]; ri[tid] = ri[tid+s]; rp[tid] = rp[tid+s];
                }
            }
            __syncthreads();
        }
        if (tid == 0) {
            candi[sel] = ri[0];
            sval[rp[0]] = -FLT_MAX; sidx[rp[0]] = 0x7fffffff;
        }
        __syncthreads();
    }

    {
        const int warp = tid >> 5, lane = tid & 31;
        const float* rr = g_resid + (size_t)row * D_MODEL;
        for (int j = warp; j < NCAND; j += 8) {
            const float* er = enc_w + (size_t)candi[j] * D_MODEL;
            float s = 0.f;
            for (int d = lane; d < D_MODEL; d += 32) s += rr[d] * er[d];
#pragma unroll
            for (int o = 16; o; o >>= 1) s += __shfl_xor_sync(0xffffffffu, s, o);
            if (lane == 0) exv[j] = s;
        }
    }
    __syncthreads();

    if (tid == 0) {
        unsigned used = 0;
        float ssum = 0.f;
        for (int sel = 0; sel < TOPK; sel++) {
            float bv = -FLT_MAX; int bi = 0x7fffffff; int bp = -1;
            for (int j = 0; j < NCAND; j++) {
                if (used & (1u << j)) continue;
                const float v = exv[j]; const int ix = candi[j];
                if (v > bv || (v == bv && ix < bi)) { bv = v; bi = ix; bp = j; }
            }
            used |= (1u << bp);
            selv[sel] = bv; seli[sel] = bi;
            ssum += fabsf(bv);
        }
        g_spars[row] = ssum;
    }
    __syncthreads();

    for (int d = tid; d < D_MODEL; d += 256) {
        float o = g_basis[(size_t)row * D_MODEL + d] + bias[d];
#pragma unroll
        for (int j = 0; j < TOPK; j++) o += selv[j] * dict_w[(size_t)seli[j] * D_MODEL + d];
        g_xrec[(size_t)row * D_MODEL + d] = o;
    }
}

// =====================================================================
// RMSNorm -> bf16 hi/lo planes
// =====================================================================
__global__ void __launch_bounds__(256)
rmsnorm_kernel(const float* __restrict__ in, const float* __restrict__ w,
               __nv_bfloat16* __restrict__ hi, __nv_bfloat16* __restrict__ lo,
               float* __restrict__ rmsbuf)
{
    __shared__ float red[256];
    const int row = blockIdx.x, tid = threadIdx.x;
    const float* xr = in + (size_t)row * D_MODEL;
    float s = 0.f;
    for (int d = tid; d < D_MODEL; d += 256) { const float v = xr[d]; s += v * v; }
    red[tid] = s;
    __syncthreads();
    for (int st = 128; st > 0; st >>= 1) { if (tid < st) red[tid] += red[tid + st]; __syncthreads(); }
    const float rms = sqrtf(red[0] / (float)D_MODEL + EPS_F);
    const float inv = 1.f / rms;
    for (int d = tid; d < D_MODEL; d += 256) {
        const float v = w[d] * xr[d] * inv;
        const size_t idx = (size_t)row * D_MODEL + d;
        const __nv_bfloat16 h = __float2bfloat16(v);
        hi[idx] = h;
        lo[idx] = __float2bfloat16(v - __bfloat162float(h));
    }
    if (tid == 0) rmsbuf[row] = rms;
}

// =====================================================================
// k_mod -> bf16 hi/lo planes  [bh][t][64]
// =====================================================================
__global__ void __launch_bounds__(256)
kmod_kernel(const float* __restrict__ kbuf, const float* __restrict__ rel)
{
    __shared__ float ks[64][65];
    __shared__ float ts[64][65];
    const int bh = blockIdx.y, b = bh >> 4, h = bh & 15;
    const int t0 = blockIdx.x * 64;
    const int tid = threadIdx.x;
    for (int i = tid; i < 4096; i += 256) {
        const int r = i >> 6, c = i & 63;
        ks[r][c] = kbuf[(size_t)(b*TT + t0 + r) * D_MODEL + h*DH + c];
        ts[r][c] = rel[(size_t)h*DH*DH + r*DH + c];
    }
    __syncthreads();
    const int tx = tid & 15, ty = tid >> 4;
    float acc[4][4] = {};
#pragma unroll
    for (int d = 0; d < 64; d++) {
        float ra[4], rb[4];
#pragma unroll
        for (int i = 0; i < 4; i++) ra[i] = ks[ty*4 + i][d];
#pragma unroll
        for (int j = 0; j < 4; j++) rb[j] = ts[d][tx*4 + j];
#pragma unroll
        for (int i = 0; i < 4; i++)
#pragma unroll
            for (int j = 0; j < 4; j++) acc[i][j] += ra[i] * rb[j];
    }
#pragma unroll
    for (int i = 0; i < 4; i++)
#pragma unroll
        for (int j = 0; j < 4; j++) {
            const size_t idx = ((size_t)bh*TT + t0 + ty*4 + i) * DH + tx*4 + j;
            const float v = acc[i][j];
            const __nv_bfloat16 hh = __float2bfloat16(v);
            b_kmod[idx] = hh;
            b_kmod[PD + idx] = __float2bfloat16(v - __bfloat162float(hh));
        }
}

// =====================================================================
// V transpose -> bf16 hi/lo planes  [bh][64][t]
// =====================================================================
__global__ void __launch_bounds__(256)
vtrans_kernel(const float* __restrict__ v)
{
    __shared__ float t[64][65];
    const int z = blockIdx.y, b = z >> 4, h = z & 15;
    const int t0 = blockIdx.x * 64;
    for (int i = threadIdx.x; i < 4096; i += 256) {
        const int r = i >> 6, c = i & 63;
        t[r][c] = v[(size_t)(b*TT + t0 + r) * D_MODEL + h*DH + c];
    }
    __syncthreads();
    for (int i = threadIdx.x; i < 4096; i += 256) {
        const int e = i >> 6, r = i & 63;
        const size_t idx = (size_t)z * DH * TT + (size_t)e * TT + t0 + r;
        const float vv = t[r][e];
        const __nv_bfloat16 hh = __float2bfloat16(vv);
        b_vt[idx] = hh;
        b_vt[PD + idx] = __float2bfloat16(vv - __bfloat162float(hh));
    }
}

// =====================================================================
// Row softmax over 2048, fp32 in place + bf16 hi/lo plane copies
// =====================================================================
__global__ void __launch_bounds__(256)
softmax_kernel(float* __restrict__ P, __nv_bfloat16* __restrict__ ph,
               __nv_bfloat16* __restrict__ pl)
{
    __shared__ float red[256];
    const size_t row = blockIdx.x;
    float* p = P + row * (size_t)TT;
    __nv_bfloat16* oh = ph + row * (size_t)TT;
    __nv_bfloat16* ol = pl + row * (size_t)TT;
    const int tid = threadIdx.x;
    float v[8];
#pragma unroll
    for (int i = 0; i < 8; i++) v[i] = p[tid + i*256];
    float m = v[0];
#pragma unroll
    for (int i = 1; i < 8; i++) m = fmaxf(m, v[i]);
    red[tid] = m;
    __syncthreads();
    for (int st = 128; st > 0; st >>= 1) { if (tid < st) red[tid] = fmaxf(red[tid], red[tid+st]); __syncthreads(); }
    m = red[0];
    __syncthreads();
    float s = 0.f;
#pragma unroll
    for (int i = 0; i < 8; i++) { v[i] = __expf(v[i] - m); s += v[i]; }
    red[tid] = s;
    __syncthreads();
    for (int st = 128; st > 0; st >>= 1) { if (tid < st) red[tid] += red[tid+st]; __syncthreads(); }
    const float inv = 1.f / red[0];
#pragma unroll
    for (int i = 0; i < 8; i++) {
        const float vv = v[i] * inv;
        p[tid + i*256] = vv;
        const __nv_bfloat16 hh = __float2bfloat16(vv);
        oh[tid + i*256] = hh;
        ol[tid + i*256] = __float2bfloat16(vv - __bfloat162float(hh));
    }
}

// =====================================================================
// h = sigmoid(gate) * silu(up) -> bf16 hi/lo planes
// =====================================================================
__global__ void __launch_bounds__(256)
gateup_kernel()
{
    const size_t n = (size_t)BT * D_FF;
    for (size_t i = (size_t)blockIdx.x * blockDim.x + threadIdx.x; i < n;
         i += (size_t)gridDim.x * blockDim.x) {
        const float g = g_gate[i], u = g_up[i];
        const float sg = 1.f / (1.f + __expf(-g));
        const float su = u / (1.f + __expf(-u));
        const float v = sg * su;
        const __nv_bfloat16 hh = __float2bfloat16(v);
        b_h[i] = hh;
        b_h[PH + i] = __float2bfloat16(v - __bfloat162float(hh));
    }
}

// =====================================================================
// Final scalars
// =====================================================================
__global__ void __launch_bounds__(256)
finalize_kernel(float* __restrict__ out)
{
    __shared__ float s1[256], s2[256], s3[256];
    const int tid = threadIdx.x;
    float a = 0.f, b = 0.f, c = 0.f;
    for (int i = tid; i < BT; i += 256) { a += g_spars[i]; b += g_rms1[i]; c += g_rms2[i]; }
    s1[tid] = a; s2[tid] = b; s3[tid] = c;
    __syncthreads();
    for (int st = 128; st > 0; st >>= 1) {
        if (tid < st) { s1[tid] += s1[tid+st]; s2[tid] += s2[tid+st]; s3[tid] += s3[tid+st]; }
        __syncthreads();
    }
    if (tid == 0) {
        out[SC_OFF + 0] = s1[0] / ((float)BB * (float)TT * (float)DICT);
        out[SC_OFF + 1] = s2[0] / (float)BT;
        out[SC_OFF + 2] = s3[0] / (float)BT;
    }
}

// =====================================================================
// host launcher
// =====================================================================
extern "C" void kernel_launch(void* const* d_in, const int* in_sizes, int n_in,
                              void* d_out, int out_size)
{
    (void)in_sizes; (void)n_in; (void)out_size;
    const float* x     = (const float*)d_in[0];
    const float* proto = (const float*)d_in[2];
    const float* fgw   = (const float*)d_in[3];
    const float* dictw = (const float*)d_in[4];
    const float* encw  = (const float*)d_in[5];
    const float* wq    = (const float*)d_in[6];
    const float* wk    = (const float*)d_in[7];
    const float* wv    = (const float*)d_in[8];
    const float* wo    = (const float*)d_in[9];
    const float* rel   = (const float*)d_in[10];
    const float* gatew = (const float*)d_in[11];
    const float* upw   = (const float*)d_in[12];
    const float* downw = (const float*)d_in[13];
    const float* n1w   = (const float*)d_in[14];
    const float* n2w   = (const float*)d_in[15];
    const float* bias  = (const float*)d_in[16];
    float* out = (float*)d_out;

    const int SM_1_128  = 3 * 1 * (128*64 + 128*64);   // 49152
    const int SM_3_128  = 3 * 2 * (128*64 + 128*64);   // 98304
    const int SM_3_64   = 3 * 2 * (128*64 +  64*64);   // 73728
    cudaFuncSetAttribute(mma_gemm<1,128,0>, cudaFuncAttributeMaxDynamicSharedMemorySize, SM_1_128);
    cudaFuncSetAttribute(mma_gemm<3,128,0>, cudaFuncAttributeMaxDynamicSharedMemorySize, SM_3_128);
    cudaFuncSetAttribute(mma_gemm<3,128,1>, cudaFuncAttributeMaxDynamicSharedMemorySize, SM_3_128);
    cudaFuncSetAttribute(mma_gemm<3,64,1>,  cudaFuncAttributeMaxDynamicSharedMemorySize, SM_3_64);

    float *p_xrec, *p_k, *p_v, *p_x2, *p_coeffs, *p_gate, *p_up, *p_rms1, *p_rms2;
    cudaGetSymbolAddress((void**)&p_xrec,   g_xrec);
    cudaGetSymbolAddress((void**)&p_k,      g_k);
    cudaGetSymbolAddress((void**)&p_v,      g_v);
    cudaGetSymbolAddress((void**)&p_x2,     g_x2);
    cudaGetSymbolAddress((void**)&p_coeffs, g_coeffs);
    cudaGetSymbolAddress((void**)&p_gate,   g_gate);
    cudaGetSymbolAddress((void**)&p_up,     g_up);
    cudaGetSymbolAddress((void**)&p_rms1,   g_rms1);
    cudaGetSymbolAddress((void**)&p_rms2,   g_rms2);

    __nv_bfloat16 *pb_resid, *pb_enc, *pb_normed, *pb_normed2, *pb_q, *pb_kmod,
                  *pb_vt, *pb_ctx, *pb_h, *pb_attn,
                  *pb_wq, *pb_wk, *pb_wv, *pb_wo, *pb_gw, *pb_uw, *pb_dw;
    cudaGetSymbolAddress((void**)&pb_resid,   b_resid_h);
    cudaGetSymbolAddress((void**)&pb_enc,     b_enc_h);
    cudaGetSymbolAddress((void**)&pb_normed,  b_normed);
    cudaGetSymbolAddress((void**)&pb_normed2, b_normed2);
    cudaGetSymbolAddress((void**)&pb_q,       b_q);
    cudaGetSymbolAddress((void**)&pb_kmod,    b_kmod);
    cudaGetSymbolAddress((void**)&pb_vt,      b_vt);
    cudaGetSymbolAddress((void**)&pb_ctx,     b_ctx);
    cudaGetSymbolAddress((void**)&pb_h,       b_h);
    cudaGetSymbolAddress((void**)&pb_attn,    b_attn);
    cudaGetSymbolAddress((void**)&pb_wq,      b_wq);
    cudaGetSymbolAddress((void**)&pb_wk,      b_wk);
    cudaGetSymbolAddress((void**)&pb_wv,      b_wv);
    cudaGetSymbolAddress((void**)&pb_wo,      b_wo);
    cudaGetSymbolAddress((void**)&pb_gw,      b_gw);
    cudaGetSymbolAddress((void**)&pb_uw,      b_uw);
    cudaGetSymbolAddress((void**)&pb_dw,      b_dw);

    // 0) weight splits
    split1_kernel<<<1024, 256>>>(encw, pb_enc, PE/2);
    split2_kernel<<<256, 256>>>(wq,    pb_wq, pb_wq + PW, PW/2);
    split2_kernel<<<256, 256>>>(wk,    pb_wk, pb_wk + PW, PW/2);
    split2_kernel<<<256, 256>>>(wv,    pb_wv, pb_wv + PW, PW/2);
    split2_kernel<<<256, 256>>>(wo,    pb_wo, pb_wo + PW, PW/2);
    split2_kernel<<<512, 256>>>(gatew, pb_gw, pb_gw + PF, PF/2);
    split2_kernel<<<512, 256>>>(upw,   pb_uw, pb_uw + PF, PF/2);
    split2_kernel<<<512, 256>>>(downw, pb_dw, pb_dw + PF, PF/2);

    // 1) family pool
    family_kernel<<<BT, 256>>>(x, fgw, proto, out + FS_OFF);

    // 2) approx coeffs (bf16 hi planes, 1-pass)
    mma_gemm<1,128,0><<<dim3(DICT/128, BT/128, 1), 256, SM_1_128>>>(
        pb_resid, 0, D_MODEL, 0, 0, pb_enc, 0, D_MODEL, 0,
        p_coeffs, DICT, 0, 0, nullptr, 0, nullptr, D_MODEL, 1.0f);

    // 3) top-16 + exact fp32 re-rank -> x_rec, sparsity
    topk_kernel<<<BT, 256>>>(dictw, encw, bias);

    // 4) norm1 -> planes
    rmsnorm_kernel<<<BT, 256>>>(p_xrec, n1w, pb_normed, pb_normed + PD, p_rms1);

    // 5) q (planes out), k, v (fp32 out)
    mma_gemm<3,128,1><<<dim3(D_MODEL/128, BT/128, 1), 256, SM_3_128>>>(
        pb_normed, PD, D_MODEL, 0, 0, pb_wq, PW, D_MODEL, 0,
        nullptr, D_MODEL, 0, 0, pb_q, PD, nullptr, D_MODEL, 1.0f);
    mma_gemm<3,128,0><<<dim3(D_MODEL/128, BT/128, 1), 256, SM_3_128>>>(
        pb_normed, PD, D_MODEL, 0, 0, pb_wk, PW, D_MODEL, 0,
        p_k, D_MODEL, 0, 0, nullptr, 0, nullptr, D_MODEL, 1.0f);
    mma_gemm<3,128,0><<<dim3(D_MODEL/128, BT/128, 1), 256, SM_3_128>>>(
        pb_normed, PD, D_MODEL, 0, 0, pb_wv, PW, D_MODEL, 0,
        p_v, D_MODEL, 0, 0, nullptr, 0, nullptr, D_MODEL, 1.0f);

    // 6) k_mod + V transpose (fused splits)
    kmod_kernel<<<dim3(TT/64, BB*N_HEADS), 256>>>(p_k, rel);
    vtrans_kernel<<<dim3(TT/64, BB*N_HEADS), 256>>>(p_v);

    // 7) logits -> d_out fp32, softmax -> fp32 + planes
    mma_gemm<3,128,0><<<dim3(TT/128, TT/128, BB*N_HEADS), 256, SM_3_128>>>(
        pb_q, PD, D_MODEL, 0, 1, pb_kmod, PD, DH, (size_t)TT*DH,
        out + ATT_OFF, TT, (size_t)TT*TT, 0, nullptr, 0, nullptr, DH, 0.125f);
    softmax_kernel<<<BB*N_HEADS*TT, 256>>>(out + ATT_OFF, pb_attn, pb_attn + ATT_N);

    // 8) ctx = attn @ v (planes out, head-sliced)
    mma_gemm<3,64,1><<<dim3(1, TT/128, BB*N_HEADS), 256, SM_3_64>>>(
        pb_attn, ATT_N, TT, (size_t)TT*TT, 0, pb_vt, PD, TT, (size_t)DH*TT,
        nullptr, D_MODEL, 0, 1, pb_ctx, PD, nullptr, TT, 1.0f);

    // 9) x2 = x + ctx @ wo^T
    mma_gemm<3,128,0><<<dim3(D_MODEL/128, BT/128, 1), 256, SM_3_128>>>(
        pb_ctx, PD, D_MODEL, 0, 0, pb_wo, PW, D_MODEL, 0,
        p_x2, D_MODEL, 0, 0, nullptr, 0, x, D_MODEL, 1.0f);

    // 10) norm2 -> planes
    rmsnorm_kernel<<<BT, 256>>>(p_x2, n2w, pb_normed2, pb_normed2 + PD, p_rms2);

    // 11) FFN
    mma_gemm<3,128,0><<<dim3(D_FF/128, BT/128, 1), 256, SM_3_128>>>(
        pb_normed2, PD, D_MODEL, 0, 0, pb_gw, PF, D_MODEL, 0,
        p_gate, D_FF, 0, 0, nullptr, 0, nullptr, D_MODEL, 1.0f);
    mma_gemm<3,128,0><<<dim3(D_FF/128, BT/128, 1), 256, SM_3_128>>>(
        pb_normed2, PD, D_MODEL, 0, 0, pb_uw, PF, D_MODEL, 0,
        p_up, D_FF, 0, 0, nullptr, 0, nullptr, D_MODEL, 1.0f);
    gateup_kernel<<<8192, 256>>>();

    // 12) final x = x2 + h @ down^T -> d_out
    mma_gemm<3,128,0><<<dim3(D_MODEL/128, BT/128, 1), 256, SM_3_128>>>(
        pb_h, PH, D_FF, 0, 0, pb_dw, PF, D_FF, 0,
        out + X_OFF, D_MODEL, 0, 0, nullptr, 0, p_x2, D_FF, 1.0f);

    // 13) scalars
    finalize_kernel<<<1, 256>>>(out);
}

// round 11
// speedup vs baseline: 1.8654x; 1.1357x over previous
#include <cuda_runtime.h>
#include <cuda_bf16.h>
#include <math.h>
#include <float.h>
#include <stdint.h>

// ---------------- problem dims (fixed by setup_inputs) ----------------
#define D_MODEL 1024
#define N_HEADS 16
#define DH      64
#define D_FF    4096
#define NFAM    64
#define DICT    16384
#define BB      2
#define TT      2048
#define BT      (BB*TT)
#define TOPK    8
#define NCAND   16
#define EPS_F   1e-6f

#define X_N     ((size_t)BT * D_MODEL)
#define ATT_N   ((size_t)BB * N_HEADS * TT * TT)
#define FS_N    ((size_t)BT * NFAM)
#define X_OFF   ((size_t)0)
#define ATT_OFF (X_N)
#define FS_OFF  (X_N + ATT_N)
#define SC_OFF  (X_N + ATT_N + FS_N)

#define PD   ((size_t)BT * D_MODEL)
#define PW   ((size_t)D_MODEL * D_MODEL)
#define PF   ((size_t)D_FF * D_MODEL)
#define PH   ((size_t)BT * D_FF)
#define PE   ((size_t)DICT * D_MODEL)

// ---------------- fp32 scratch ----------------
__device__ float g_resid  [BT * D_MODEL];
__device__ float g_basis  [BT * D_MODEL];
__device__ float g_xrec   [BT * D_MODEL];
__device__ float g_k      [BT * D_MODEL];
__device__ float g_v      [BT * D_MODEL];
__device__ float g_x2     [BT * D_MODEL];
__device__ float g_coeffs [(size_t)BT * DICT];
__device__ float g_gate   [(size_t)BT * D_FF];
__device__ float g_up     [(size_t)BT * D_FF];
__device__ float g_rms1   [BT];
__device__ float g_rms2   [BT];
__device__ float g_spars  [BT];

// ---------------- bf16 planes ----------------
// A-side operands: hi plane only. B-side operands: hi at [0], lo at [+plane].
__device__ __align__(16) __nv_bfloat16 b_resid_h[PD];
__device__ __align__(16) __nv_bfloat16 b_enc_h  [PE];
__device__ __align__(16) __nv_bfloat16 b_normed [PD];
__device__ __align__(16) __nv_bfloat16 b_normed2[PD];
__device__ __align__(16) __nv_bfloat16 b_q      [PD];
__device__ __align__(16) __nv_bfloat16 b_kmod   [2 * PD];   // [bh][t][64], B-side
__device__ __align__(16) __nv_bfloat16 b_vt     [2 * PD];   // [bh][64][t], B-side
__device__ __align__(16) __nv_bfloat16 b_ctx    [PD];
__device__ __align__(16) __nv_bfloat16 b_h      [PH];
__device__ __align__(16) __nv_bfloat16 b_wq     [2 * PW];
__device__ __align__(16) __nv_bfloat16 b_wk     [2 * PW];
__device__ __align__(16) __nv_bfloat16 b_wv     [2 * PW];
__device__ __align__(16) __nv_bfloat16 b_wo     [2 * PW];
__device__ __align__(16) __nv_bfloat16 b_gw     [2 * PF];
__device__ __align__(16) __nv_bfloat16 b_uw     [2 * PF];
__device__ __align__(16) __nv_bfloat16 b_dw     [2 * PF];
__device__ __align__(16) __nv_bfloat16 b_attn   [ATT_N];

// ===================== helpers (baseline PTX, sm_80+) =========
__device__ __forceinline__ uint32_t smem_u32(const void* p) {
    uint32_t a;
    asm("{ .reg .u64 t; cvta.to.shared.u64 t, %1; cvt.u32.u64 %0, t; }" : "=r"(a) : "l"(p));
    return a;
}
__device__ __forceinline__ void ldsm_x4(uint32_t& r0, uint32_t& r1, uint32_t& r2,
                                        uint32_t& r3, uint32_t addr) {
    asm volatile("ldmatrix.sync.aligned.m8n8.x4.shared.b16 {%0,%1,%2,%3}, [%4];"
                 : "=r"(r0), "=r"(r1), "=r"(r2), "=r"(r3) : "r"(addr));
}
__device__ __forceinline__ void mma_bf16(float* d, const uint32_t* a, uint32_t b0, uint32_t b1) {
    asm volatile("mma.sync.aligned.m16n8k16.row.col.f32.bf16.bf16.f32 "
                 "{%0,%1,%2,%3},{%4,%5,%6,%7},{%8,%9},{%0,%1,%2,%3};"
                 : "+f"(d[0]), "+f"(d[1]), "+f"(d[2]), "+f"(d[3])
                 : "r"(a[0]), "r"(a[1]), "r"(a[2]), "r"(a[3]), "r"(b0), "r"(b1));
}
__device__ __forceinline__ void cpa16(uint32_t dst, const void* src) {
    asm volatile("cp.async.cg.shared.global [%0], [%1], 16;" :: "r"(dst), "l"(src) : "memory");
}
__device__ __forceinline__ void cpa_commit() { asm volatile("cp.async.commit_group;" ::: "memory"); }
__device__ __forceinline__ void cpa_wait1()  { asm volatile("cp.async.wait_group 1;" ::: "memory"); }
__device__ __forceinline__ void cpa_wait0()  { asm volatile("cp.async.wait_group 0;" ::: "memory"); }

// =====================================================================
// bf16 mma GEMM: C[M,N] = alpha*(A @ B^T) (+res), row-major.
// A: bf16 hi plane only. B: bf16 hi plane (+lo at B+bPlane when NP=2).
// NP passes: p=0 uses B-hi, p=1 uses B-lo (A-hi both times).
// Tile 128 x BN, BK=32, 3-stage cp.async pipeline, A-frag reuse across passes.
// OUT=0: fp32 C (+res, *alpha).  OUT=2: bf16 hi-only store to Cp.
// aHead/cHead: base = (z>>4)*TT*ld + (z&15)*DH (per-head slice of [token][1024]).
// =====================================================================
template<int NP, int BN, int OUT>
__global__ void __launch_bounds__(256, 2)
mma_gemm(const __nv_bfloat16* __restrict__ A, int lda, size_t aZ, int aHead,
         const __nv_bfloat16* __restrict__ B, size_t bPlane, int ldb, size_t bZ,
         float* __restrict__ C, int ldc, size_t cZ, int cHead,
         __nv_bfloat16* __restrict__ Cp,
         const float* __restrict__ res, int K, float alpha)
{
    constexpr int APL = 128 * 64;              // bytes, A tile (one plane)
    constexpr int BPL = BN * 64;
    constexpr int STG = APL + NP * BPL;
    constexpr int BUN = NP * BN * 4;           // B 16B units
    constexpr int UNITS = 512 + BUN;
    constexpr int MF = (BN == 128) ? 4 : 2;
    constexpr int NF = 4;

    extern __shared__ char sm[];
    const int tid = threadIdx.x, wid = tid >> 5, lane = tid & 31;
    const int bm = blockIdx.y * 128, bn = blockIdx.x * BN;
    const int z = blockIdx.z;
    const uint32_t smb = smem_u32(sm);

    const size_t abase = aHead ? ((size_t)(z >> 4) * TT * lda + (size_t)(z & 15) * DH)
                               : (size_t)z * aZ;
    const __nv_bfloat16* Ab = A + abase + (size_t)bm * lda;
    const __nv_bfloat16* Bb = B + (size_t)z * bZ + (size_t)bn * ldb;

    const int wr = (BN == 128) ? (wid >> 2) : (wid >> 1);
    const int wc = (BN == 128) ? (wid & 3)  : (wid & 1);
    const int mrow0 = wr * (MF * 16);
    const int ncol0 = wc * 32;

    float acc[MF][NF][4];
#pragma unroll
    for (int m = 0; m < MF; m++)
#pragma unroll
        for (int n = 0; n < NF; n++)
#pragma unroll
            for (int q = 0; q < 4; q++) acc[m][n][q] = 0.f;

    const int NC = K >> 5;

    auto issue = [&](int c, int stage) {
        const int k0 = c << 5;
        const uint32_t sb = smb + stage * STG;
#pragma unroll
        for (int u = 0; u < UNITS / 256; u++) {
            const int idx = u * 256 + tid;
            if (idx < 512) {
                const int r = idx >> 2, c4 = idx & 3;
                const uint32_t off = (uint32_t)(r * 64 + ((c4 ^ ((r >> 1) & 3)) << 4));
                cpa16(sb + off, Ab + (size_t)r * lda + k0 + c4 * 8);
            } else {
                const int j = idx - 512;
                const int p = j / (BN * 4);
                const int jj = j & (BN * 4 - 1);
                const int r = jj >> 2, c4 = jj & 3;
                const uint32_t off = (uint32_t)(r * 64 + ((c4 ^ ((r >> 1) & 3)) << 4));
                cpa16(sb + APL + p * BPL + off,
                      Bb + (size_t)p * bPlane + (size_t)r * ldb + k0 + c4 * 8);
            }
        }
        cpa_commit();
    };

    issue(0, 0);
    issue(1, 1);

    for (int c = 0; c < NC; ++c) {
        if (c < NC - 1) cpa_wait1(); else cpa_wait0();
        __syncthreads();
        if (c + 2 < NC) issue(c + 2, (c + 2) % 3);

        const uint32_t aB  = smb + (c % 3) * STG;
        const uint32_t bB0 = aB + APL;
#pragma unroll
        for (int ks = 0; ks < 2; ks++) {
            uint32_t af[MF][4];
#pragma unroll
            for (int m = 0; m < MF; m++) {
                const int row = mrow0 + m * 16 + (lane & 15);
                const int c16 = ks * 2 + (lane >> 4);
                ldsm_x4(af[m][0], af[m][1], af[m][2], af[m][3],
                        aB + row * 64 + ((c16 ^ ((row >> 1) & 3)) << 4));
            }
#pragma unroll
            for (int p = 0; p < NP; p++) {
                const uint32_t bB = bB0 + p * BPL;
                uint32_t bf[2][4];
#pragma unroll
                for (int g = 0; g < 2; g++) {
                    const int row = ncol0 + g * 16 + (lane & 15);
                    const int c16 = ks * 2 + (lane >> 4);
                    ldsm_x4(bf[g][0], bf[g][1], bf[g][2], bf[g][3],
                            bB + row * 64 + ((c16 ^ ((row >> 1) & 3)) << 4));
                }
#pragma unroll
                for (int m = 0; m < MF; m++)
#pragma unroll
                    for (int nf = 0; nf < NF; nf++)
                        mma_bf16(acc[m][nf], af[m], bf[nf >> 1][nf & 1], bf[nf >> 1][(nf & 1) + 2]);
            }
        }
    }

    // ---- epilogue ----
    const size_t cbase = cHead ? ((size_t)(z >> 4) * TT * ldc + (size_t)(z & 15) * DH)
                               : (size_t)z * cZ;
    if (OUT == 0) {
        float* Cb = C + cbase + (size_t)bm * ldc + bn;
        const float* Rb = res ? res + cbase + (size_t)bm * ldc + bn : (const float*)0;
#pragma unroll
        for (int m = 0; m < MF; m++) {
            const int r0 = mrow0 + m * 16 + (lane >> 2);
#pragma unroll
            for (int h = 0; h < 2; h++) {
                const int r = r0 + h * 8;
                float* crow = Cb + (size_t)r * ldc;
                const float* rrow = Rb ? Rb + (size_t)r * ldc : (const float*)0;
#pragma unroll
                for (int nf = 0; nf < NF; nf++) {
                    const int col = ncol0 + nf * 8 + (lane & 3) * 2;
                    float2 v;
                    v.x = acc[m][nf][2*h + 0] * alpha;
                    v.y = acc[m][nf][2*h + 1] * alpha;
                    if (rrow) { v.x += rrow[col]; v.y += rrow[col + 1]; }
                    *(float2*)(crow + col) = v;
                }
            }
        }
    } else {
        __nv_bfloat16* Ch = Cp + cbase + (size_t)bm * ldc + bn;
#pragma unroll
        for (int m = 0; m < MF; m++) {
            const int r0 = mrow0 + m * 16 + (lane >> 2);
#pragma unroll
            for (int h = 0; h < 2; h++) {
                const int r = r0 + h * 8;
#pragma unroll
                for (int nf = 0; nf < NF; nf++) {
                    const int col = ncol0 + nf * 8 + (lane & 3) * 2;
                    __nv_bfloat162 hh;
                    hh.x = __float2bfloat16(acc[m][nf][2*h + 0] * alpha);
                    hh.y = __float2bfloat16(acc[m][nf][2*h + 1] * alpha);
                    *(__nv_bfloat162*)(Ch + (size_t)r * ldc + col) = hh;
                }
            }
        }
    }
}

// =====================================================================
// weight split kernels (B-side: hi+lo; coeffs enc: hi only)
// =====================================================================
__global__ void __launch_bounds__(256)
split2_kernel(const float* __restrict__ s, __nv_bfloat16* __restrict__ hi,
              __nv_bfloat16* __restrict__ lo, size_t n2)
{
    const float2* s2 = (const float2*)s;
    __nv_bfloat162* h2 = (__nv_bfloat162*)hi;
    __nv_bfloat162* l2 = (__nv_bfloat162*)lo;
    for (size_t i = (size_t)blockIdx.x * 256 + threadIdx.x; i < n2; i += (size_t)gridDim.x * 256) {
        const float2 v = s2[i];
        __nv_bfloat162 h, l;
        h.x = __float2bfloat16(v.x); h.y = __float2bfloat16(v.y);
        l.x = __float2bfloat16(v.x - __bfloat162float(h.x));
        l.y = __float2bfloat16(v.y - __bfloat162float(h.y));
        h2[i] = h; l2[i] = l;
    }
}
__global__ void __launch_bounds__(256)
split1_kernel(const float* __restrict__ s, __nv_bfloat16* __restrict__ hi, size_t n2)
{
    const float2* s2 = (const float2*)s;
    __nv_bfloat162* h2 = (__nv_bfloat162*)hi;
    for (size_t i = (size_t)blockIdx.x * 256 + threadIdx.x; i < n2; i += (size_t)gridDim.x * 256) {
        const float2 v = s2[i];
        __nv_bfloat162 h;
        h.x = __float2bfloat16(v.x); h.y = __float2bfloat16(v.y);
        h2[i] = h;
    }
}

// =====================================================================
// Family basis pool -> scores, basis, resid fp32 + resid hi plane
// =====================================================================
__global__ void __launch_bounds__(256)
family_kernel(const float* __restrict__ x, const float* __restrict__ fgw,
              const float* __restrict__ proto, float* __restrict__ fs_out)
{
    __shared__ float xs[D_MODEL];
    __shared__ float sc[NFAM];
    const int row = blockIdx.x;
    const int tid = threadIdx.x;
    const float* xr = x + (size_t)row * D_MODEL;
    for (int d = tid; d < D_MODEL; d += 256) xs[d] = xr[d];
    __syncthreads();

    const int warp = tid >> 5, lane = tid & 31;
    for (int f = warp; f < NFAM; f += 8) {
        const float* w = fgw + (size_t)f * D_MODEL;
        float s = 0.f;
        for (int d = lane; d < D_MODEL; d += 32) s += xs[d] * w[d];
#pragma unroll
        for (int o = 16; o; o >>= 1) s += __shfl_xor_sync(0xffffffffu, s, o);
        if (lane == 0) sc[f] = s;
    }
    __syncthreads();

    if (tid < 32) {
        float m = fmaxf(sc[tid], sc[tid + 32]);
#pragma unroll
        for (int o = 16; o; o >>= 1) m = fmaxf(m, __shfl_xor_sync(0xffffffffu, m, o));
        const float e0 = __expf(sc[tid] - m);
        const float e1 = __expf(sc[tid + 32] - m);
        float s = e0 + e1;
#pragma unroll
        for (int o = 16; o; o >>= 1) s += __shfl_xor_sync(0xffffffffu, s, o);
        const float inv = 1.f / s;
        sc[tid]      = e0 * inv;
        sc[tid + 32] = e1 * inv;
    }
    __syncthreads();

    if (tid < NFAM) fs_out[(size_t)row * NFAM + tid] = sc[tid];

    for (int d = tid; d < D_MODEL; d += 256) {
        float b = 0.f;
#pragma unroll 8
        for (int f = 0; f < NFAM; f++) b += sc[f] * proto[f * D_MODEL + d];
        const size_t idx = (size_t)row * D_MODEL + d;
        g_basis[idx] = b;
        const float r = xs[d] - b;
        g_resid[idx] = r;
        b_resid_h[idx] = __float2bfloat16(r);
    }
}

// =====================================================================
// Top-16 candidates from approx coeffs, exact fp32 re-rank to top-8.
// =====================================================================
__global__ void __launch_bounds__(256)
topk_kernel(const float* __restrict__ dict_w, const float* __restrict__ enc_w,
            const float* __restrict__ bias)
{
    __shared__ float sval[256 * NCAND];
    __shared__ int   sidx[256 * NCAND];
    __shared__ float rv[256];
    __shared__ int   ri[256];
    __shared__ int   rp[256];
    __shared__ int   candi[NCAND];
    __shared__ float exv[NCAND];
    __shared__ float selv[TOPK];
    __shared__ int   seli[TOPK];

    const int row = blockIdx.x;
    const int tid = threadIdx.x;
    const float* cr = g_coeffs + (size_t)row * DICT;

    float lv[NCAND]; int li[NCAND];
#pragma unroll
    for (int r = 0; r < NCAND; r++) { lv[r] = -FLT_MAX; li[r] = 0x7fffffff; }
    for (int j = tid; j < DICT; j += 256) {
        const float v = cr[j];
        if (v > lv[NCAND-1]) {
            int p = NCAND - 1;
            while (p > 0 && lv[p-1] < v) { lv[p] = lv[p-1]; li[p] = li[p-1]; p--; }
            lv[p] = v; li[p] = j;
        }
    }
#pragma unroll
    for (int r = 0; r < NCAND; r++) { sval[tid*NCAND + r] = lv[r]; sidx[tid*NCAND + r] = li[r]; }
    __syncthreads();

    for (int sel = 0; sel < NCAND; sel++) {
        float bv = -FLT_MAX; int bi = 0x7fffffff; int bp = 0;
#pragma unroll
        for (int r = 0; r < NCAND; r++) {
            const int p = tid*NCAND + r;
            const float v = sval[p]; const int ix = sidx[p];
            if (v > bv || (v == bv && ix < bi)) { bv = v; bi = ix; bp = p; }
        }
        rv[tid] = bv; ri[tid] = bi; rp[tid] = bp;
        __syncthreads();
        for (int s = 128; s > 0; s >>= 1) {
            if (tid < s) {
                if (rv[tid+s] > rv[tid] || (rv[tid+s] == rv[tid] && ri[tid+s] < ri[tid])) {
                    rv[tid] = rv[tid+s]; ri[tid] = ri[tid+s]; rp[tid] = rp[tid+s];
                }
            }
            __syncthreads();
        }
        if (tid == 0) {
            candi[sel] = ri[0];
            sval[rp[0]] = -FLT_MAX; sidx[rp[0]] = 0x7fffffff;
        }
        __syncthreads();
    }

    {
        const int warp = tid >> 5, lane = tid & 31;
        const float* rr = g_resid + (size_t)row * D_MODEL;
        for (int j = warp; j < NCAND; j += 8) {
            const float* er = enc_w + (size_t)candi[j] * D_MODEL;
            float s = 0.f;
            for (int d = lane; d < D_MODEL; d += 32) s += rr[d] * er[d];
#pragma unroll
            for (int o = 16; o; o >>= 1) s += __shfl_xor_sync(0xffffffffu, s, o);
            if (lane == 0) exv[j] = s;
        }
    }
    __syncthreads();

    if (tid == 0) {
        unsigned used = 0;
        float ssum = 0.f;
        for (int sel = 0; sel < TOPK; sel++) {
            float bv = -FLT_MAX; int bi = 0x7fffffff; int bp = -1;
            for (int j = 0; j < NCAND; j++) {
                if (used & (1u << j)) continue;
                const float v = exv[j]; const int ix = candi[j];
                if (v > bv || (v == bv && ix < bi)) { bv = v; bi = ix; bp = j; }
            }
            used |= (1u << bp);
            selv[sel] = bv; seli[sel] = bi;
            ssum += fabsf(bv);
        }
        g_spars[row] = ssum;
    }
    __syncthreads();

    for (int d = tid; d < D_MODEL; d += 256) {
        float o = g_basis[(size_t)row * D_MODEL + d] + bias[d];
#pragma unroll
        for (int j = 0; j < TOPK; j++) o += selv[j] * dict_w[(size_t)seli[j] * D_MODEL + d];
        g_xrec[(size_t)row * D_MODEL + d] = o;
    }
}

// =====================================================================
// RMSNorm -> bf16 hi plane only
// =====================================================================
__global__ void __launch_bounds__(256)
rmsnorm_kernel(const float* __restrict__ in, const float* __restrict__ w,
               __nv_bfloat16* __restrict__ hi, float* __restrict__ rmsbuf)
{
    __shared__ float red[256];
    const int row = blockIdx.x, tid = threadIdx.x;
    const float* xr = in + (size_t)row * D_MODEL;
    float s = 0.f;
    for (int d = tid; d < D_MODEL; d += 256) { const float v = xr[d]; s += v * v; }
    red[tid] = s;
    __syncthreads();
    for (int st = 128; st > 0; st >>= 1) { if (tid < st) red[tid] += red[tid + st]; __syncthreads(); }
    const float rms = sqrtf(red[0] / (float)D_MODEL + EPS_F);
    const float inv = 1.f / rms;
    for (int d = tid; d < D_MODEL; d += 256) {
        const float v = w[d] * xr[d] * inv;
        hi[(size_t)row * D_MODEL + d] = __float2bfloat16(v);
    }
    if (tid == 0) rmsbuf[row] = rms;
}

// =====================================================================
// k_mod -> bf16 hi/lo planes  [bh][t][64]   (B-side of logits)
// =====================================================================
__global__ void __launch_bounds__(256)
kmod_kernel(const float* __restrict__ kbuf, const float* __restrict__ rel)
{
    __shared__ float ks[64][65];
    __shared__ float ts[64][65];
    const int bh = blockIdx.y, b = bh >> 4, h = bh & 15;
    const int t0 = blockIdx.x * 64;
    const int tid = threadIdx.x;
    for (int i = tid; i < 4096; i += 256) {
        const int r = i >> 6, c = i & 63;
        ks[r][c] = kbuf[(size_t)(b*TT + t0 + r) * D_MODEL + h*DH + c];
        ts[r][c] = rel[(size_t)h*DH*DH + r*DH + c];
    }
    __syncthreads();
    const int tx = tid & 15, ty = tid >> 4;
    float acc[4][4] = {};
#pragma unroll
    for (int d = 0; d < 64; d++) {
        float ra[4], rb[4];
#pragma unroll
        for (int i = 0; i < 4; i++) ra[i] = ks[ty*4 + i][d];
#pragma unroll
        for (int j = 0; j < 4; j++) rb[j] = ts[d][tx*4 + j];
#pragma unroll
        for (int i = 0; i < 4; i++)
#pragma unroll
            for (int j = 0; j < 4; j++) acc[i][j] += ra[i] * rb[j];
    }
#pragma unroll
    for (int i = 0; i < 4; i++)
#pragma unroll
        for (int j = 0; j < 4; j++) {
            const size_t idx = ((size_t)bh*TT + t0 + ty*4 + i) * DH + tx*4 + j;
            const float v = acc[i][j];
            const __nv_bfloat16 hh = __float2bfloat16(v);
            b_kmod[idx] = hh;
            b_kmod[PD + idx] = __float2bfloat16(v - __bfloat162float(hh));
        }
}

// =====================================================================
// V transpose -> bf16 hi/lo planes  [bh][64][t]   (B-side of AV)
// =====================================================================
__global__ void __launch_bounds__(256)
vtrans_kernel(const float* __restrict__ v)
{
    __shared__ float t[64][65];
    const int z = blockIdx.y, b = z >> 4, h = z & 15;
    const int t0 = blockIdx.x * 64;
    for (int i = threadIdx.x; i < 4096; i += 256) {
        const int r = i >> 6, c = i & 63;
        t[r][c] = v[(size_t)(b*TT + t0 + r) * D_MODEL + h*DH + c];
    }
    __syncthreads();
    for (int i = threadIdx.x; i < 4096; i += 256) {
        const int e = i >> 6, r = i & 63;
        const size_t idx = (size_t)z * DH * TT + (size_t)e * TT + t0 + r;
        const float vv = t[r][e];
        const __nv_bfloat16 hh = __float2bfloat16(vv);
        b_vt[idx] = hh;
        b_vt[PD + idx] = __float2bfloat16(vv - __bfloat162float(hh));
    }
}

// =====================================================================
// Row softmax over 2048, fp32 in place + bf16 hi plane copy
// =====================================================================
__global__ void __launch_bounds__(256)
softmax_kernel(float* __restrict__ P, __nv_bfloat16* __restrict__ ph)
{
    __shared__ float red[256];
    const size_t row = blockIdx.x;
    float* p = P + row * (size_t)TT;
    __nv_bfloat16* oh = ph + row * (size_t)TT;
    const int tid = threadIdx.x;
    float v[8];
#pragma unroll
    for (int i = 0; i < 8; i++) v[i] = p[tid + i*256];
    float m = v[0];
#pragma unroll
    for (int i = 1; i < 8; i++) m = fmaxf(m, v[i]);
    red[tid] = m;
    __syncthreads();
    for (int st = 128; st > 0; st >>= 1) { if (tid < st) red[tid] = fmaxf(red[tid], red[tid+st]); __syncthreads(); }
    m = red[0];
    __syncthreads();
    float s = 0.f;
#pragma unroll
    for (int i = 0; i < 8; i++) { v[i] = __expf(v[i] - m); s += v[i]; }
    red[tid] = s;
    __syncthreads();
    for (int st = 128; st > 0; st >>= 1) { if (tid < st) red[tid] += red[tid+st]; __syncthreads(); }
    const float inv = 1.f / red[0];
#pragma unroll
    for (int i = 0; i < 8; i++) {
        const float vv = v[i] * inv;
        p[tid + i*256] = vv;
        oh[tid + i*256] = __float2bfloat16(vv);
    }
}

// =====================================================================
// h = sigmoid(gate) * silu(up) -> bf16 hi plane
// =====================================================================
__global__ void __launch_bounds__(256)
gateup_kernel()
{
    const size_t n = (size_t)BT * D_FF;
    for (size_t i = (size_t)blockIdx.x * blockDim.x + threadIdx.x; i < n;
         i += (size_t)gridDim.x * blockDim.x) {
        const float g = g_gate[i], u = g_up[i];
        const float sg = 1.f / (1.f + __expf(-g));
        const float su = u / (1.f + __expf(-u));
        b_h[i] = __float2bfloat16(sg * su);
    }
}

// =====================================================================
// Final scalars
// =====================================================================
__global__ void __launch_bounds__(256)
finalize_kernel(float* __restrict__ out)
{
    __shared__ float s1[256], s2[256], s3[256];
    const int tid = threadIdx.x;
    float a = 0.f, b = 0.f, c = 0.f;
    for (int i = tid; i < BT; i += 256) { a += g_spars[i]; b += g_rms1[i]; c += g_rms2[i]; }
    s1[tid] = a; s2[tid] = b; s3[tid] = c;
    __syncthreads();
    for (int st = 128; st > 0; st >>= 1) {
        if (tid < st) { s1[tid] += s1[tid+st]; s2[tid] += s2[tid+st]; s3[tid] += s3[tid+st]; }
        __syncthreads();
    }
    if (tid == 0) {
        out[SC_OFF + 0] = s1[0] / ((float)BB * (float)TT * (float)DICT);
        out[SC_OFF + 1] = s2[0] / (float)BT;
        out[SC_OFF + 2] = s3[0] / (float)BT;
    }
}

// =====================================================================
// host launcher
// =====================================================================
extern "C" void kernel_launch(void* const* d_in, const int* in_sizes, int n_in,
                              void* d_out, int out_size)
{
    (void)in_sizes; (void)n_in; (void)out_size;
    const float* x     = (const float*)d_in[0];
    const float* proto = (const float*)d_in[2];
    const float* fgw   = (const float*)d_in[3];
    const float* dictw = (const float*)d_in[4];
    const float* encw  = (const float*)d_in[5];
    const float* wq    = (const float*)d_in[6];
    const float* wk    = (const float*)d_in[7];
    const float* wv    = (const float*)d_in[8];
    const float* wo    = (const float*)d_in[9];
    const float* rel   = (const float*)d_in[10];
    const float* gatew = (const float*)d_in[11];
    const float* upw   = (const float*)d_in[12];
    const float* downw = (const float*)d_in[13];
    const float* n1w   = (const float*)d_in[14];
    const float* n2w   = (const float*)d_in[15];
    const float* bias  = (const float*)d_in[16];
    float* out = (float*)d_out;

    const int SM_1_128 = 3 * (8192 + 1 * 8192);   // 49152
    const int SM_2_128 = 3 * (8192 + 2 * 8192);   // 73728
    const int SM_2_64  = 3 * (8192 + 2 * 4096);   // 49152
    cudaFuncSetAttribute(mma_gemm<1,128,0>, cudaFuncAttributeMaxDynamicSharedMemorySize, SM_1_128);
    cudaFuncSetAttribute(mma_gemm<2,128,0>, cudaFuncAttributeMaxDynamicSharedMemorySize, SM_2_128);
    cudaFuncSetAttribute(mma_gemm<2,128,2>, cudaFuncAttributeMaxDynamicSharedMemorySize, SM_2_128);
    cudaFuncSetAttribute(mma_gemm<2,64,2>,  cudaFuncAttributeMaxDynamicSharedMemorySize, SM_2_64);

    float *p_xrec, *p_k, *p_v, *p_x2, *p_coeffs, *p_gate, *p_up, *p_rms1, *p_rms2;
    cudaGetSymbolAddress((void**)&p_xrec,   g_xrec);
    cudaGetSymbolAddress((void**)&p_k,      g_k);
    cudaGetSymbolAddress((void**)&p_v,      g_v);
    cudaGetSymbolAddress((void**)&p_x2,     g_x2);
    cudaGetSymbolAddress((void**)&p_coeffs, g_coeffs);
    cudaGetSymbolAddress((void**)&p_gate,   g_gate);
    cudaGetSymbolAddress((void**)&p_up,     g_up);
    cudaGetSymbolAddress((void**)&p_rms1,   g_rms1);
    cudaGetSymbolAddress((void**)&p_rms2,   g_rms2);

    __nv_bfloat16 *pb_resid, *pb_enc, *pb_normed, *pb_normed2, *pb_q, *pb_kmod,
                  *pb_vt, *pb_ctx, *pb_h, *pb_attn,
                  *pb_wq, *pb_wk, *pb_wv, *pb_wo, *pb_gw, *pb_uw, *pb_dw;
    cudaGetSymbolAddress((void**)&pb_resid,   b_resid_h);
    cudaGetSymbolAddress((void**)&pb_enc,     b_enc_h);
    cudaGetSymbolAddress((void**)&pb_normed,  b_normed);
    cudaGetSymbolAddress((void**)&pb_normed2, b_normed2);
    cudaGetSymbolAddress((void**)&pb_q,       b_q);
    cudaGetSymbolAddress((void**)&pb_kmod,    b_kmod);
    cudaGetSymbolAddress((void**)&pb_vt,      b_vt);
    cudaGetSymbolAddress((void**)&pb_ctx,     b_ctx);
    cudaGetSymbolAddress((void**)&pb_h,       b_h);
    cudaGetSymbolAddress((void**)&pb_attn,    b_attn);
    cudaGetSymbolAddress((void**)&pb_wq,      b_wq);
    cudaGetSymbolAddress((void**)&pb_wk,      b_wk);
    cudaGetSymbolAddress((void**)&pb_wv,      b_wv);
    cudaGetSymbolAddress((void**)&pb_wo,      b_wo);
    cudaGetSymbolAddress((void**)&pb_gw,      b_gw);
    cudaGetSymbolAddress((void**)&pb_uw,      b_uw);
    cudaGetSymbolAddress((void**)&pb_dw,      b_dw);

    // 0) weight splits (B-side operands: hi+lo)
    split1_kernel<<<1024, 256>>>(encw, pb_enc, PE/2);
    split2_kernel<<<256, 256>>>(wq,    pb_wq, pb_wq + PW, PW/2);
    split2_kernel<<<256, 256>>>(wk,    pb_wk, pb_wk + PW, PW/2);
    split2_kernel<<<256, 256>>>(wv,    pb_wv, pb_wv + PW, PW/2);
    split2_kernel<<<256, 256>>>(wo,    pb_wo, pb_wo + PW, PW/2);
    split2_kernel<<<512, 256>>>(gatew, pb_gw, pb_gw + PF, PF/2);
    split2_kernel<<<512, 256>>>(upw,   pb_uw, pb_uw + PF, PF/2);
    split2_kernel<<<512, 256>>>(downw, pb_dw, pb_dw + PF, PF/2);

    // 1) family pool
    family_kernel<<<BT, 256>>>(x, fgw, proto, out + FS_OFF);

    // 2) approx coeffs (1-pass; exact re-rank in topk)
    mma_gemm<1,128,0><<<dim3(DICT/128, BT/128, 1), 256, SM_1_128>>>(
        pb_resid, D_MODEL, 0, 0, pb_enc, 0, D_MODEL, 0,
        p_coeffs, DICT, 0, 0, nullptr, nullptr, D_MODEL, 1.0f);

    // 3) top-16 + exact fp32 re-rank -> x_rec, sparsity
    topk_kernel<<<BT, 256>>>(dictw, encw, bias);

    // 4) norm1 -> hi plane
    rmsnorm_kernel<<<BT, 256>>>(p_xrec, n1w, pb_normed, p_rms1);

    // 5) q (bf16 out), k, v (fp32 out); 2-pass
    mma_gemm<2,128,2><<<dim3(D_MODEL/128, BT/128, 1), 256, SM_2_128>>>(
        pb_normed, D_MODEL, 0, 0, pb_wq, PW, D_MODEL, 0,
        nullptr, D_MODEL, 0, 0, pb_q, nullptr, D_MODEL, 1.0f);
    mma_gemm<2,128,0><<<dim3(D_MODEL/128, BT/128, 1), 256, SM_2_128>>>(
        pb_normed, D_MODEL, 0, 0, pb_wk, PW, D_MODEL, 0,
        p_k, D_MODEL, 0, 0, nullptr, nullptr, D_MODEL, 1.0f);
    mma_gemm<2,128,0><<<dim3(D_MODEL/128, BT/128, 1), 256, SM_2_128>>>(
        pb_normed, D_MODEL, 0, 0, pb_wv, PW, D_MODEL, 0,
        p_v, D_MODEL, 0, 0, nullptr, nullptr, D_MODEL, 1.0f);

    // 6) k_mod + V transpose (hi+lo, B-side)
    kmod_kernel<<<dim3(TT/64, BB*N_HEADS), 256>>>(p_k, rel);
    vtrans_kernel<<<dim3(TT/64, BB*N_HEADS), 256>>>(p_v);

    // 7) logits -> d_out fp32, softmax -> fp32 + hi plane
    mma_gemm<2,128,0><<<dim3(TT/128, TT/128, BB*N_HEADS), 256, SM_2_128>>>(
        pb_q, D_MODEL, 0, 1, pb_kmod, PD, DH, (size_t)TT*DH,
        out + ATT_OFF, TT, (size_t)TT*TT, 0, nullptr, nullptr, DH, 0.125f);
    softmax_kernel<<<BB*N_HEADS*TT, 256>>>(out + ATT_OFF, pb_attn);

    // 8) ctx = attn @ v (bf16 out, head-sliced)
    mma_gemm<2,64,2><<<dim3(1, TT/128, BB*N_HEADS), 256, SM_2_64>>>(
        pb_attn, TT, (size_t)TT*TT, 0, pb_vt, PD, TT, (size_t)DH*TT,
        nullptr, D_MODEL, 0, 1, pb_ctx, nullptr, TT, 1.0f);

    // 9) x2 = x + ctx @ wo^T
    mma_gemm<2,128,0><<<dim3(D_MODEL/128, BT/128, 1), 256, SM_2_128>>>(
        pb_ctx, D_MODEL, 0, 0, pb_wo, PW, D_MODEL, 0,
        p_x2, D_MODEL, 0, 0, nullptr, x, D_MODEL, 1.0f);

    // 10) norm2 -> hi plane
    rmsnorm_kernel<<<BT, 256>>>(p_x2, n2w, pb_normed2, p_rms2);

    // 11) FFN
    mma_gemm<2,128,0><<<dim3(D_FF/128, BT/128, 1), 256, SM_2_128>>>(
        pb_normed2, D_MODEL, 0, 0, pb_gw, PF, D_MODEL, 0,
        p_gate, D_FF, 0, 0, nullptr, nullptr, D_MODEL, 1.0f);
    mma_gemm<2,128,0><<<dim3(D_FF/128, BT/128, 1), 256, SM_2_128>>>(
        pb_normed2, D_MODEL, 0, 0, pb_uw, PF, D_MODEL, 0,
        p_up, D_FF, 0, 0, nullptr, nullptr, D_MODEL, 1.0f);
    gateup_kernel<<<8192, 256>>>();

    // 12) final x = x2 + h @ down^T -> d_out
    mma_gemm<2,128,0><<<dim3(D_MODEL/128, BT/128, 1), 256, SM_2_128>>>(
        pb_h, D_FF, 0, 0, pb_dw, PF, D_FF, 0,
        out + X_OFF, D_MODEL, 0, 0, nullptr, p_x2, D_FF, 1.0f);

    // 13) scalars
    finalize_kernel<<<1, 256>>>(out);
}

// round 12
// speedup vs baseline: 2.0368x; 1.0919x over previous
#include <cuda_runtime.h>
#include <cuda_fp16.h>
#include <math.h>
#include <float.h>
#include <stdint.h>

// ---------------- problem dims (fixed by setup_inputs) ----------------
#define D_MODEL 1024
#define N_HEADS 16
#define DH      64
#define D_FF    4096
#define NFAM    64
#define DICT    16384
#define BB      2
#define TT      2048
#define BT      (BB*TT)
#define TOPK    8
#define NCAND   16
#define EPS_F   1e-6f

#define X_N     ((size_t)BT * D_MODEL)
#define ATT_N   ((size_t)BB * N_HEADS * TT * TT)
#define FS_N    ((size_t)BT * NFAM)
#define X_OFF   ((size_t)0)
#define ATT_OFF (X_N)
#define FS_OFF  (X_N + ATT_N)
#define SC_OFF  (X_N + ATT_N + FS_N)

#define PD   ((size_t)BT * D_MODEL)
#define PW   ((size_t)D_MODEL * D_MODEL)
#define PF   ((size_t)D_FF * D_MODEL)
#define PH   ((size_t)BT * D_FF)
#define PE   ((size_t)DICT * D_MODEL)

// ---------------- fp32 scratch ----------------
__device__ float g_resid  [BT * D_MODEL];
__device__ float g_basis  [BT * D_MODEL];
__device__ float g_xrec   [BT * D_MODEL];
__device__ float g_k      [BT * D_MODEL];
__device__ float g_v      [BT * D_MODEL];
__device__ float g_x2     [BT * D_MODEL];
__device__ float g_coeffs [(size_t)BT * DICT];
__device__ float g_gate   [(size_t)BT * D_FF];
__device__ float g_up     [(size_t)BT * D_FF];
__device__ float g_rms1   [BT];
__device__ float g_rms2   [BT];
__device__ float g_spars  [BT];

// ---------------- fp16 planes (single plane per operand) ----------------
__device__ __align__(16) __half b_resid_h[PD];
__device__ __align__(16) __half b_enc_h  [PE];
__device__ __align__(16) __half b_normed [PD];
__device__ __align__(16) __half b_normed2[PD];
__device__ __align__(16) __half b_q      [PD];
__device__ __align__(16) __half b_kmod   [PD];   // [bh][t][64]
__device__ __align__(16) __half b_vt     [PD];   // [bh][64][t]
__device__ __align__(16) __half b_ctx    [PD];
__device__ __align__(16) __half b_h      [PH];
__device__ __align__(16) __half b_wq     [PW];
__device__ __align__(16) __half b_wk     [PW];
__device__ __align__(16) __half b_wv     [PW];
__device__ __align__(16) __half b_wo     [PW];
__device__ __align__(16) __half b_gw     [PF];
__device__ __align__(16) __half b_uw     [PF];
__device__ __align__(16) __half b_dw     [PF];
__device__ __align__(16) __half b_attn   [ATT_N];

// ===================== helpers (baseline PTX, sm_80+) =========
__device__ __forceinline__ uint32_t smem_u32(const void* p) {
    uint32_t a;
    asm("{ .reg .u64 t; cvta.to.shared.u64 t, %1; cvt.u32.u64 %0, t; }" : "=r"(a) : "l"(p));
    return a;
}
__device__ __forceinline__ void ldsm_x4(uint32_t& r0, uint32_t& r1, uint32_t& r2,
                                        uint32_t& r3, uint32_t addr) {
    asm volatile("ldmatrix.sync.aligned.m8n8.x4.shared.b16 {%0,%1,%2,%3}, [%4];"
                 : "=r"(r0), "=r"(r1), "=r"(r2), "=r"(r3) : "r"(addr));
}
__device__ __forceinline__ void mma_f16(float* d, const uint32_t* a, uint32_t b0, uint32_t b1) {
    asm volatile("mma.sync.aligned.m16n8k16.row.col.f32.f16.f16.f32 "
                 "{%0,%1,%2,%3},{%4,%5,%6,%7},{%8,%9},{%0,%1,%2,%3};"
                 : "+f"(d[0]), "+f"(d[1]), "+f"(d[2]), "+f"(d[3])
                 : "r"(a[0]), "r"(a[1]), "r"(a[2]), "r"(a[3]), "r"(b0), "r"(b1));
}
__device__ __forceinline__ void cpa16(uint32_t dst, const void* src) {
    asm volatile("cp.async.cg.shared.global [%0], [%1], 16;" :: "r"(dst), "l"(src) : "memory");
}
__device__ __forceinline__ void cpa_commit() { asm volatile("cp.async.commit_group;" ::: "memory"); }
__device__ __forceinline__ void cpa_wait1()  { asm volatile("cp.async.wait_group 1;" ::: "memory"); }
__device__ __forceinline__ void cpa_wait0()  { asm volatile("cp.async.wait_group 0;" ::: "memory"); }

// =====================================================================
// fp16 mma GEMM: C[M,N] = alpha*(A @ B^T) (+res), row-major, single pass.
// Tile 128 x BN (BN in {64,128}), BK=32, 3-stage cp.async pipeline.
// OUT=0: fp32 C (+res, *alpha).  OUT=2: fp16 store to Cp (*alpha).
// aHead/cHead: base = (z>>4)*TT*ld + (z&15)*DH (per-head slice of [token][1024]).
// =====================================================================
template<int BN, int OUT>
__global__ void __launch_bounds__(256, 2)
mma_gemm(const __half* __restrict__ A, int lda, size_t aZ, int aHead,
         const __half* __restrict__ B, int ldb, size_t bZ,
         float* __restrict__ C, int ldc, size_t cZ, int cHead,
         __half* __restrict__ Cp,
         const float* __restrict__ res, int K, float alpha)
{
    constexpr int APL = 128 * 64;              // bytes, A tile
    constexpr int BPL = BN * 64;
    constexpr int STG = APL + BPL;
    constexpr int UNITS = 512 + BN * 4;        // 16B units per chunk
    constexpr int MF = (BN == 128) ? 4 : 2;
    constexpr int NF = 4;

    extern __shared__ char sm[];
    const int tid = threadIdx.x, wid = tid >> 5, lane = tid & 31;
    const int bm = blockIdx.y * 128, bn = blockIdx.x * BN;
    const int z = blockIdx.z;
    const uint32_t smb = smem_u32(sm);

    const size_t abase = aHead ? ((size_t)(z >> 4) * TT * lda + (size_t)(z & 15) * DH)
                               : (size_t)z * aZ;
    const __half* Ab = A + abase + (size_t)bm * lda;
    const __half* Bb = B + (size_t)z * bZ + (size_t)bn * ldb;

    const int wr = (BN == 128) ? (wid >> 2) : (wid >> 1);
    const int wc = (BN == 128) ? (wid & 3)  : (wid & 1);
    const int mrow0 = wr * (MF * 16);
    const int ncol0 = wc * 32;

    float acc[MF][NF][4];
#pragma unroll
    for (int m = 0; m < MF; m++)
#pragma unroll
        for (int n = 0; n < NF; n++)
#pragma unroll
            for (int q = 0; q < 4; q++) acc[m][n][q] = 0.f;

    const int NC = K >> 5;

    auto issue = [&](int c, int stage) {
        const int k0 = c << 5;
        const uint32_t sb = smb + stage * STG;
#pragma unroll
        for (int u = 0; u < UNITS / 256; u++) {
            const int idx = u * 256 + tid;
            if (idx < 512) {
                const int r = idx >> 2, c4 = idx & 3;
                const uint32_t off = (uint32_t)(r * 64 + ((c4 ^ ((r >> 1) & 3)) << 4));
                cpa16(sb + off, Ab + (size_t)r * lda + k0 + c4 * 8);
            } else {
                const int j = idx - 512;
                const int r = j >> 2, c4 = j & 3;
                const uint32_t off = (uint32_t)(r * 64 + ((c4 ^ ((r >> 1) & 3)) << 4));
                cpa16(sb + APL + off, Bb + (size_t)r * ldb + k0 + c4 * 8);
            }
        }
        cpa_commit();
    };

    issue(0, 0);
    issue(1, 1);

    for (int c = 0; c < NC; ++c) {
        if (c < NC - 1) cpa_wait1(); else cpa_wait0();
        __syncthreads();
        if (c + 2 < NC) issue(c + 2, (c + 2) % 3);

        const uint32_t aB = smb + (c % 3) * STG;
        const uint32_t bB = aB + APL;
#pragma unroll
        for (int ks = 0; ks < 2; ks++) {
            uint32_t af[MF][4];
#pragma unroll
            for (int m = 0; m < MF; m++) {
                const int row = mrow0 + m * 16 + (lane & 15);
                const int c16 = ks * 2 + (lane >> 4);
                ldsm_x4(af[m][0], af[m][1], af[m][2], af[m][3],
                        aB + row * 64 + ((c16 ^ ((row >> 1) & 3)) << 4));
            }
            uint32_t bf[2][4];
#pragma unroll
            for (int g = 0; g < 2; g++) {
                const int row = ncol0 + g * 16 + (lane & 15);
                const int c16 = ks * 2 + (lane >> 4);
                ldsm_x4(bf[g][0], bf[g][1], bf[g][2], bf[g][3],
                        bB + row * 64 + ((c16 ^ ((row >> 1) & 3)) << 4));
            }
#pragma unroll
            for (int m = 0; m < MF; m++)
#pragma unroll
                for (int nf = 0; nf < NF; nf++)
                    mma_f16(acc[m][nf], af[m], bf[nf >> 1][nf & 1], bf[nf >> 1][(nf & 1) + 2]);
        }
    }

    // ---- epilogue ----
    const size_t cbase = cHead ? ((size_t)(z >> 4) * TT * ldc + (size_t)(z & 15) * DH)
                               : (size_t)z * cZ;
    if (OUT == 0) {
        float* Cb = C + cbase + (size_t)bm * ldc + bn;
        const float* Rb = res ? res + cbase + (size_t)bm * ldc + bn : (const float*)0;
#pragma unroll
        for (int m = 0; m < MF; m++) {
            const int r0 = mrow0 + m * 16 + (lane >> 2);
#pragma unroll
            for (int h = 0; h < 2; h++) {
                const int r = r0 + h * 8;
                float* crow = Cb + (size_t)r * ldc;
                const float* rrow = Rb ? Rb + (size_t)r * ldc : (const float*)0;
#pragma unroll
                for (int nf = 0; nf < NF; nf++) {
                    const int col = ncol0 + nf * 8 + (lane & 3) * 2;
                    float2 v;
                    v.x = acc[m][nf][2*h + 0] * alpha;
                    v.y = acc[m][nf][2*h + 1] * alpha;
                    if (rrow) { v.x += rrow[col]; v.y += rrow[col + 1]; }
                    *(float2*)(crow + col) = v;
                }
            }
        }
    } else {
        __half* Ch = Cp + cbase + (size_t)bm * ldc + bn;
#pragma unroll
        for (int m = 0; m < MF; m++) {
            const int r0 = mrow0 + m * 16 + (lane >> 2);
#pragma unroll
            for (int h = 0; h < 2; h++) {
                const int r = r0 + h * 8;
#pragma unroll
                for (int nf = 0; nf < NF; nf++) {
                    const int col = ncol0 + nf * 8 + (lane & 3) * 2;
                    __half2 hh;
                    hh.x = __float2half_rn(acc[m][nf][2*h + 0] * alpha);
                    hh.y = __float2half_rn(acc[m][nf][2*h + 1] * alpha);
                    *(__half2*)(Ch + (size_t)r * ldc + col) = hh;
                }
            }
        }
    }
}

// =====================================================================
// fp32 -> fp16 convert kernel
// =====================================================================
__global__ void __launch_bounds__(256)
half_kernel(const float* __restrict__ s, __half* __restrict__ hi, size_t n2)
{
    const float2* s2 = (const float2*)s;
    __half2* h2 = (__half2*)hi;
    for (size_t i = (size_t)blockIdx.x * 256 + threadIdx.x; i < n2; i += (size_t)gridDim.x * 256) {
        const float2 v = s2[i];
        __half2 h;
        h.x = __float2half_rn(v.x); h.y = __float2half_rn(v.y);
        h2[i] = h;
    }
}

// =====================================================================
// Family basis pool -> scores, basis, resid fp32 + resid fp16 plane
// =====================================================================
__global__ void __launch_bounds__(256)
family_kernel(const float* __restrict__ x, const float* __restrict__ fgw,
              const float* __restrict__ proto, float* __restrict__ fs_out)
{
    __shared__ float xs[D_MODEL];
    __shared__ float sc[NFAM];
    const int row = blockIdx.x;
    const int tid = threadIdx.x;
    const float* xr = x + (size_t)row * D_MODEL;
    for (int d = tid; d < D_MODEL; d += 256) xs[d] = xr[d];
    __syncthreads();

    const int warp = tid >> 5, lane = tid & 31;
    for (int f = warp; f < NFAM; f += 8) {
        const float* w = fgw + (size_t)f * D_MODEL;
        float s = 0.f;
        for (int d = lane; d < D_MODEL; d += 32) s += xs[d] * w[d];
#pragma unroll
        for (int o = 16; o; o >>= 1) s += __shfl_xor_sync(0xffffffffu, s, o);
        if (lane == 0) sc[f] = s;
    }
    __syncthreads();

    if (tid < 32) {
        float m = fmaxf(sc[tid], sc[tid + 32]);
#pragma unroll
        for (int o = 16; o; o >>= 1) m = fmaxf(m, __shfl_xor_sync(0xffffffffu, m, o));
        const float e0 = __expf(sc[tid] - m);
        const float e1 = __expf(sc[tid + 32] - m);
        float s = e0 + e1;
#pragma unroll
        for (int o = 16; o; o >>= 1) s += __shfl_xor_sync(0xffffffffu, s, o);
        const float inv = 1.f / s;
        sc[tid]      = e0 * inv;
        sc[tid + 32] = e1 * inv;
    }
    __syncthreads();

    if (tid < NFAM) fs_out[(size_t)row * NFAM + tid] = sc[tid];

    for (int d = tid; d < D_MODEL; d += 256) {
        float b = 0.f;
#pragma unroll 8
        for (int f = 0; f < NFAM; f++) b += sc[f] * proto[f * D_MODEL + d];
        const size_t idx = (size_t)row * D_MODEL + d;
        g_basis[idx] = b;
        const float r = xs[d] - b;
        g_resid[idx] = r;
        b_resid_h[idx] = __float2half_rn(r);
    }
}

// =====================================================================
// Top-16 candidates from approx coeffs, exact fp32 re-rank to top-8.
// =====================================================================
__global__ void __launch_bounds__(256)
topk_kernel(const float* __restrict__ dict_w, const float* __restrict__ enc_w,
            const float* __restrict__ bias)
{
    __shared__ float sval[256 * NCAND];
    __shared__ int   sidx[256 * NCAND];
    __shared__ float rv[256];
    __shared__ int   ri[256];
    __shared__ int   rp[256];
    __shared__ int   candi[NCAND];
    __shared__ float exv[NCAND];
    __shared__ float selv[TOPK];
    __shared__ int   seli[TOPK];

    const int row = blockIdx.x;
    const int tid = threadIdx.x;
    const float* cr = g_coeffs + (size_t)row * DICT;

    float lv[NCAND]; int li[NCAND];
#pragma unroll
    for (int r = 0; r < NCAND; r++) { lv[r] = -FLT_MAX; li[r] = 0x7fffffff; }
    for (int j = tid; j < DICT; j += 256) {
        const float v = cr[j];
        if (v > lv[NCAND-1]) {
            int p = NCAND - 1;
            while (p > 0 && lv[p-1] < v) { lv[p] = lv[p-1]; li[p] = li[p-1]; p--; }
            lv[p] = v; li[p] = j;
        }
    }
#pragma unroll
    for (int r = 0; r < NCAND; r++) { sval[tid*NCAND + r] = lv[r]; sidx[tid*NCAND + r] = li[r]; }
    __syncthreads();

    for (int sel = 0; sel < NCAND; sel++) {
        float bv = -FLT_MAX; int bi = 0x7fffffff; int bp = 0;
#pragma unroll
        for (int r = 0; r < NCAND; r++) {
            const int p = tid*NCAND + r;
            const float v = sval[p]; const int ix = sidx[p];
            if (v > bv || (v == bv && ix < bi)) { bv = v; bi = ix; bp = p; }
        }
        rv[tid] = bv; ri[tid] = bi; rp[tid] = bp;
        __syncthreads();
        for (int s = 128; s > 0; s >>= 1) {
            if (tid < s) {
                if (rv[tid+s] > rv[tid] || (rv[tid+s] == rv[tid] && ri[tid+s] < ri[tid])) {
                    rv[tid] = rv[tid+s]; ri[tid] = ri[tid+s]; rp[tid] = rp[tid+s];
                }
            }
            __syncthreads();
        }
        if (tid == 0) {
            candi[sel] = ri[0];
            sval[rp[0]] = -FLT_MAX; sidx[rp[0]] = 0x7fffffff;
        }
        __syncthreads();
    }

    {
        const int warp = tid >> 5, lane = tid & 31;
        const float* rr = g_resid + (size_t)row * D_MODEL;
        for (int j = warp; j < NCAND; j += 8) {
            const float* er = enc_w + (size_t)candi[j] * D_MODEL;
            float s = 0.f;
            for (int d = lane; d < D_MODEL; d += 32) s += rr[d] * er[d];
#pragma unroll
            for (int o = 16; o; o >>= 1) s += __shfl_xor_sync(0xffffffffu, s, o);
            if (lane == 0) exv[j] = s;
        }
    }
    __syncthreads();

    if (tid == 0) {
        unsigned used = 0;
        float ssum = 0.f;
        for (int sel = 0; sel < TOPK; sel++) {
            float bv = -FLT_MAX; int bi = 0x7fffffff; int bp = -1;
            for (int j = 0; j < NCAND; j++) {
                if (used & (1u << j)) continue;
                const float v = exv[j]; const int ix = candi[j];
                if (v > bv || (v == bv && ix < bi)) { bv = v; bi = ix; bp = j; }
            }
            used |= (1u << bp);
            selv[sel] = bv; seli[sel] = bi;
            ssum += fabsf(bv);
        }
        g_spars[row] = ssum;
    }
    __syncthreads();

    for (int d = tid; d < D_MODEL; d += 256) {
        float o = g_basis[(size_t)row * D_MODEL + d] + bias[d];
#pragma unroll
        for (int j = 0; j < TOPK; j++) o += selv[j] * dict_w[(size_t)seli[j] * D_MODEL + d];
        g_xrec[(size_t)row * D_MODEL + d] = o;
    }
}

// =====================================================================
// RMSNorm -> fp16 plane
// =====================================================================
__global__ void __launch_bounds__(256)
rmsnorm_kernel(const float* __restrict__ in, const float* __restrict__ w,
               __half* __restrict__ hi, float* __restrict__ rmsbuf)
{
    __shared__ float red[256];
    const int row = blockIdx.x, tid = threadIdx.x;
    const float* xr = in + (size_t)row * D_MODEL;
    float s = 0.f;
    for (int d = tid; d < D_MODEL; d += 256) { const float v = xr[d]; s += v * v; }
    red[tid] = s;
    __syncthreads();
    for (int st = 128; st > 0; st >>= 1) { if (tid < st) red[tid] += red[tid + st]; __syncthreads(); }
    const float rms = sqrtf(red[0] / (float)D_MODEL + EPS_F);
    const float inv = 1.f / rms;
    for (int d = tid; d < D_MODEL; d += 256)
        hi[(size_t)row * D_MODEL + d] = __float2half_rn(w[d] * xr[d] * inv);
    if (tid == 0) rmsbuf[row] = rms;
}

// =====================================================================
// k_mod -> fp16 plane  [bh][t][64]
// =====================================================================
__global__ void __launch_bounds__(256)
kmod_kernel(const float* __restrict__ kbuf, const float* __restrict__ rel)
{
    __shared__ float ks[64][65];
    __shared__ float ts[64][65];
    const int bh = blockIdx.y, b = bh >> 4, h = bh & 15;
    const int t0 = blockIdx.x * 64;
    const int tid = threadIdx.x;
    for (int i = tid; i < 4096; i += 256) {
        const int r = i >> 6, c = i & 63;
        ks[r][c] = kbuf[(size_t)(b*TT + t0 + r) * D_MODEL + h*DH + c];
        ts[r][c] = rel[(size_t)h*DH*DH + r*DH + c];
    }
    __syncthreads();
    const int tx = tid & 15, ty = tid >> 4;
    float acc[4][4] = {};
#pragma unroll
    for (int d = 0; d < 64; d++) {
        float ra[4], rb[4];
#pragma unroll
        for (int i = 0; i < 4; i++) ra[i] = ks[ty*4 + i][d];
#pragma unroll
        for (int j = 0; j < 4; j++) rb[j] = ts[d][tx*4 + j];
#pragma unroll
        for (int i = 0; i < 4; i++)
#pragma unroll
            for (int j = 0; j < 4; j++) acc[i][j] += ra[i] * rb[j];
    }
#pragma unroll
    for (int i = 0; i < 4; i++)
#pragma unroll
        for (int j = 0; j < 4; j++)
            b_kmod[((size_t)bh*TT + t0 + ty*4 + i) * DH + tx*4 + j] = __float2half_rn(acc[i][j]);
}

// =====================================================================
// V transpose -> fp16 plane  [bh][64][t]
// =====================================================================
__global__ void __launch_bounds__(256)
vtrans_kernel(const float* __restrict__ v)
{
    __shared__ float t[64][65];
    const int z = blockIdx.y, b = z >> 4, h = z & 15;
    const int t0 = blockIdx.x * 64;
    for (int i = threadIdx.x; i < 4096; i += 256) {
        const int r = i >> 6, c = i & 63;
        t[r][c] = v[(size_t)(b*TT + t0 + r) * D_MODEL + h*DH + c];
    }
    __syncthreads();
    for (int i = threadIdx.x; i < 4096; i += 256) {
        const int e = i >> 6, r = i & 63;
        b_vt[(size_t)z * DH * TT + (size_t)e * TT + t0 + r] = __float2half_rn(t[r][e]);
    }
}

// =====================================================================
// Row softmax over 2048, fp32 in place + fp16 plane copy
// =====================================================================
__global__ void __launch_bounds__(256)
softmax_kernel(float* __restrict__ P, __half* __restrict__ ph)
{
    __shared__ float red[256];
    const size_t row = blockIdx.x;
    float* p = P + row * (size_t)TT;
    __half* oh = ph + row * (size_t)TT;
    const int tid = threadIdx.x;
    float v[8];
#pragma unroll
    for (int i = 0; i < 8; i++) v[i] = p[tid + i*256];
    float m = v[0];
#pragma unroll
    for (int i = 1; i < 8; i++) m = fmaxf(m, v[i]);
    red[tid] = m;
    __syncthreads();
    for (int st = 128; st > 0; st >>= 1) { if (tid < st) red[tid] = fmaxf(red[tid], red[tid+st]); __syncthreads(); }
    m = red[0];
    __syncthreads();
    float s = 0.f;
#pragma unroll
    for (int i = 0; i < 8; i++) { v[i] = __expf(v[i] - m); s += v[i]; }
    red[tid] = s;
    __syncthreads();
    for (int st = 128; st > 0; st >>= 1) { if (tid < st) red[tid] += red[tid+st]; __syncthreads(); }
    const float inv = 1.f / red[0];
#pragma unroll
    for (int i = 0; i < 8; i++) {
        const float vv = v[i] * inv;
        p[tid + i*256] = vv;
        oh[tid + i*256] = __float2half_rn(vv);
    }
}

// =====================================================================
// h = sigmoid(gate) * silu(up) -> fp16 plane
// =====================================================================
__global__ void __launch_bounds__(256)
gateup_kernel()
{
    const size_t n = (size_t)BT * D_FF;
    for (size_t i = (size_t)blockIdx.x * blockDim.x + threadIdx.x; i < n;
         i += (size_t)gridDim.x * blockDim.x) {
        const float g = g_gate[i], u = g_up[i];
        const float sg = 1.f / (1.f + __expf(-g));
        const float su = u / (1.f + __expf(-u));
        b_h[i] = __float2half_rn(sg * su);
    }
}

// =====================================================================
// Final scalars
// =====================================================================
__global__ void __launch_bounds__(256)
finalize_kernel(float* __restrict__ out)
{
    __shared__ float s1[256], s2[256], s3[256];
    const int tid = threadIdx.x;
    float a = 0.f, b = 0.f, c = 0.f;
    for (int i = tid; i < BT; i += 256) { a += g_spars[i]; b += g_rms1[i]; c += g_rms2[i]; }
    s1[tid] = a; s2[tid] = b; s3[tid] = c;
    __syncthreads();
    for (int st = 128; st > 0; st >>= 1) {
        if (tid < st) { s1[tid] += s1[tid+st]; s2[tid] += s2[tid+st]; s3[tid] += s3[tid+st]; }
        __syncthreads();
    }
    if (tid == 0) {
        out[SC_OFF + 0] = s1[0] / ((float)BB * (float)TT * (float)DICT);
        out[SC_OFF + 1] = s2[0] / (float)BT;
        out[SC_OFF + 2] = s3[0] / (float)BT;
    }
}

// =====================================================================
// host launcher
// =====================================================================
extern "C" void kernel_launch(void* const* d_in, const int* in_sizes, int n_in,
                              void* d_out, int out_size)
{
    (void)in_sizes; (void)n_in; (void)out_size;
    const float* x     = (const float*)d_in[0];
    const float* proto = (const float*)d_in[2];
    const float* fgw   = (const float*)d_in[3];
    const float* dictw = (const float*)d_in[4];
    const float* encw  = (const float*)d_in[5];
    const float* wq    = (const float*)d_in[6];
    const float* wk    = (const float*)d_in[7];
    const float* wv    = (const float*)d_in[8];
    const float* wo    = (const float*)d_in[9];
    const float* rel   = (const float*)d_in[10];
    const float* gatew = (const float*)d_in[11];
    const float* upw   = (const float*)d_in[12];
    const float* downw = (const float*)d_in[13];
    const float* n1w   = (const float*)d_in[14];
    const float* n2w   = (const float*)d_in[15];
    const float* bias  = (const float*)d_in[16];
    float* out = (float*)d_out;

    const int SM_128 = 3 * (8192 + 8192);   // 49152
    const int SM_64  = 3 * (8192 + 4096);   // 36864
    cudaFuncSetAttribute(mma_gemm<128,0>, cudaFuncAttributeMaxDynamicSharedMemorySize, SM_128);
    cudaFuncSetAttribute(mma_gemm<128,2>, cudaFuncAttributeMaxDynamicSharedMemorySize, SM_128);
    cudaFuncSetAttribute(mma_gemm<64,2>,  cudaFuncAttributeMaxDynamicSharedMemorySize, SM_64);

    float *p_xrec, *p_k, *p_v, *p_x2, *p_coeffs, *p_gate, *p_up, *p_rms1, *p_rms2;
    cudaGetSymbolAddress((void**)&p_xrec,   g_xrec);
    cudaGetSymbolAddress((void**)&p_k,      g_k);
    cudaGetSymbolAddress((void**)&p_v,      g_v);
    cudaGetSymbolAddress((void**)&p_x2,     g_x2);
    cudaGetSymbolAddress((void**)&p_coeffs, g_coeffs);
    cudaGetSymbolAddress((void**)&p_gate,   g_gate);
    cudaGetSymbolAddress((void**)&p_up,     g_up);
    cudaGetSymbolAddress((void**)&p_rms1,   g_rms1);
    cudaGetSymbolAddress((void**)&p_rms2,   g_rms2);

    __half *pb_resid, *pb_enc, *pb_normed, *pb_normed2, *pb_q, *pb_kmod,
           *pb_vt, *pb_ctx, *pb_h, *pb_attn,
           *pb_wq, *pb_wk, *pb_wv, *pb_wo, *pb_gw, *pb_uw, *pb_dw;
    cudaGetSymbolAddress((void**)&pb_resid,   b_resid_h);
    cudaGetSymbolAddress((void**)&pb_enc,     b_enc_h);
    cudaGetSymbolAddress((void**)&pb_normed,  b_normed);
    cudaGetSymbolAddress((void**)&pb_normed2, b_normed2);
    cudaGetSymbolAddress((void**)&pb_q,       b_q);
    cudaGetSymbolAddress((void**)&pb_kmod,    b_kmod);
    cudaGetSymbolAddress((void**)&pb_vt,      b_vt);
    cudaGetSymbolAddress((void**)&pb_ctx,     b_ctx);
    cudaGetSymbolAddress((void**)&pb_h,       b_h);
    cudaGetSymbolAddress((void**)&pb_attn,    b_attn);
    cudaGetSymbolAddress((void**)&pb_wq,      b_wq);
    cudaGetSymbolAddress((void**)&pb_wk,      b_wk);
    cudaGetSymbolAddress((void**)&pb_wv,      b_wv);
    cudaGetSymbolAddress((void**)&pb_wo,      b_wo);
    cudaGetSymbolAddress((void**)&pb_gw,      b_gw);
    cudaGetSymbolAddress((void**)&pb_uw,      b_uw);
    cudaGetSymbolAddress((void**)&pb_dw,      b_dw);

    // 0) weight converts (single fp16 plane each)
    half_kernel<<<1024, 256>>>(encw,  pb_enc, PE/2);
    half_kernel<<<256, 256>>>(wq,    pb_wq, PW/2);
    half_kernel<<<256, 256>>>(wk,    pb_wk, PW/2);
    half_kernel<<<256, 256>>>(wv,    pb_wv, PW/2);
    half_kernel<<<256, 256>>>(wo,    pb_wo, PW/2);
    half_kernel<<<512, 256>>>(gatew, pb_gw, PF/2);
    half_kernel<<<512, 256>>>(upw,   pb_uw, PF/2);
    half_kernel<<<512, 256>>>(downw, pb_dw, PF/2);

    // 1) family pool
    family_kernel<<<BT, 256>>>(x, fgw, proto, out + FS_OFF);

    // 2) approx coeffs (fp16 1-pass; exact re-rank in topk)
    mma_gemm<128,0><<<dim3(DICT/128, BT/128, 1), 256, SM_128>>>(
        pb_resid, D_MODEL, 0, 0, pb_enc, D_MODEL, 0,
        p_coeffs, DICT, 0, 0, nullptr, nullptr, D_MODEL, 1.0f);

    // 3) top-16 + exact fp32 re-rank -> x_rec, sparsity
    topk_kernel<<<BT, 256>>>(dictw, encw, bias);

    // 4) norm1 -> fp16 plane
    rmsnorm_kernel<<<BT, 256>>>(p_xrec, n1w, pb_normed, p_rms1);

    // 5) q (fp16 out), k, v (fp32 out)
    mma_gemm<128,2><<<dim3(D_MODEL/128, BT/128, 1), 256, SM_128>>>(
        pb_normed, D_MODEL, 0, 0, pb_wq, D_MODEL, 0,
        nullptr, D_MODEL, 0, 0, pb_q, nullptr, D_MODEL, 1.0f);
    mma_gemm<128,0><<<dim3(D_MODEL/128, BT/128, 1), 256, SM_128>>>(
        pb_normed, D_MODEL, 0, 0, pb_wk, D_MODEL, 0,
        p_k, D_MODEL, 0, 0, nullptr, nullptr, D_MODEL, 1.0f);
    mma_gemm<128,0><<<dim3(D_MODEL/128, BT/128, 1), 256, SM_128>>>(
        pb_normed, D_MODEL, 0, 0, pb_wv, D_MODEL, 0,
        p_v, D_MODEL, 0, 0, nullptr, nullptr, D_MODEL, 1.0f);

    // 6) k_mod + V transpose (fp16 planes)
    kmod_kernel<<<dim3(TT/64, BB*N_HEADS), 256>>>(p_k, rel);
    vtrans_kernel<<<dim3(TT/64, BB*N_HEADS), 256>>>(p_v);

    // 7) logits -> d_out fp32, softmax -> fp32 + fp16 plane
    mma_gemm<128,0><<<dim3(TT/128, TT/128, BB*N_HEADS), 256, SM_128>>>(
        pb_q, D_MODEL, 0, 1, pb_kmod, DH, (size_t)TT*DH,
        out + ATT_OFF, TT, (size_t)TT*TT, 0, nullptr, nullptr, DH, 0.125f);
    softmax_kernel<<<BB*N_HEADS*TT, 256>>>(out + ATT_OFF, pb_attn);

    // 8) ctx = attn @ v (fp16 out, head-sliced)
    mma_gemm<64,2><<<dim3(1, TT/128, BB*N_HEADS), 256, SM_64>>>(
        pb_attn, TT, (size_t)TT*TT, 0, pb_vt, TT, (size_t)DH*TT,
        nullptr, D_MODEL, 0, 1, pb_ctx, nullptr, TT, 1.0f);

    // 9) x2 = x + ctx @ wo^T
    mma_gemm<128,0><<<dim3(D_MODEL/128, BT/128, 1), 256, SM_128>>>(
        pb_ctx, D_MODEL, 0, 0, pb_wo, D_MODEL, 0,
        p_x2, D_MODEL, 0, 0, nullptr, x, D_MODEL, 1.0f);

    // 10) norm2 -> fp16 plane
    rmsnorm_kernel<<<BT, 256>>>(p_x2, n2w, pb_normed2, p_rms2);

    // 11) FFN
    mma_gemm<128,0><<<dim3(D_FF/128, BT/128, 1), 256, SM_128>>>(
        pb_normed2, D_MODEL, 0, 0, pb_gw, D_MODEL, 0,
        p_gate, D_FF, 0, 0, nullptr, nullptr, D_MODEL, 1.0f);
    mma_gemm<128,0><<<dim3(D_FF/128, BT/128, 1), 256, SM_128>>>(
        pb_normed2, D_MODEL, 0, 0, pb_uw, D_MODEL, 0,
        p_up, D_FF, 0, 0, nullptr, nullptr, D_MODEL, 1.0f);
    gateup_kernel<<<8192, 256>>>();

    // 12) final x = x2 + h @ down^T -> d_out
    mma_gemm<128,0><<<dim3(D_MODEL/128, BT/128, 1), 256, SM_128>>>(
        pb_h, D_FF, 0, 0, pb_dw, D_FF, 0,
        out + X_OFF, D_MODEL, 0, 0, nullptr, p_x2, D_FF, 1.0f);

    // 13) scalars
    finalize_kernel<<<1, 256>>>(out);
}

// round 13
// speedup vs baseline: 2.1252x; 1.0434x over previous
#include <cuda_runtime.h>
#include <cuda_fp16.h>
#include <math.h>
#include <float.h>
#include <stdint.h>

// ---------------- problem dims (fixed by setup_inputs) ----------------
#define D_MODEL 1024
#define N_HEADS 16
#define DH      64
#define D_FF    4096
#define NFAM    64
#define DICT    16384
#define BB      2
#define TT      2048
#define BT      (BB*TT)
#define TOPK    8
#define NCAND   16
#define EPS_F   1e-6f

#define X_N     ((size_t)BT * D_MODEL)
#define ATT_N   ((size_t)BB * N_HEADS * TT * TT)
#define FS_N    ((size_t)BT * NFAM)
#define X_OFF   ((size_t)0)
#define ATT_OFF (X_N)
#define FS_OFF  (X_N + ATT_N)
#define SC_OFF  (X_N + ATT_N + FS_N)

#define PD   ((size_t)BT * D_MODEL)
#define PW   ((size_t)D_MODEL * D_MODEL)
#define PF   ((size_t)D_FF * D_MODEL)
#define PH   ((size_t)BT * D_FF)
#define PE   ((size_t)DICT * D_MODEL)

// ---------------- fp32 scratch ----------------
__device__ float g_resid  [BT * D_MODEL];
__device__ float g_basis  [BT * D_MODEL];
__device__ float g_xrec   [BT * D_MODEL];
__device__ float g_k      [BT * D_MODEL];
__device__ float g_v      [BT * D_MODEL];
__device__ float g_x2     [BT * D_MODEL];
__device__ float g_gate   [(size_t)BT * D_FF];
__device__ float g_rms1   [BT];
__device__ float g_rms2   [BT];
__device__ float g_spars  [BT];

// ---------------- fp16 planes ----------------
__device__ __align__(16) __half b_coeffs [(size_t)BT * DICT];   // 128 MB
__device__ __align__(16) __half b_resid_h[PD];
__device__ __align__(16) __half b_enc_h  [PE];
__device__ __align__(16) __half b_normed [PD];
__device__ __align__(16) __half b_normed2[PD];
__device__ __align__(16) __half b_q      [PD];
__device__ __align__(16) __half b_kmod   [PD];   // [bh][t][64]
__device__ __align__(16) __half b_vt     [PD];   // [bh][64][t]
__device__ __align__(16) __half b_ctx    [PD];
__device__ __align__(16) __half b_h      [PH];
__device__ __align__(16) __half b_wq     [PW];
__device__ __align__(16) __half b_wk     [PW];
__device__ __align__(16) __half b_wv     [PW];
__device__ __align__(16) __half b_wo     [PW];
__device__ __align__(16) __half b_gw     [PF];
__device__ __align__(16) __half b_uw     [PF];
__device__ __align__(16) __half b_dw     [PF];
__device__ __align__(16) __half b_attn   [ATT_N];

// ===================== helpers (baseline PTX, sm_80+) =========
__device__ __forceinline__ uint32_t smem_u32(const void* p) {
    uint32_t a;
    asm("{ .reg .u64 t; cvta.to.shared.u64 t, %1; cvt.u32.u64 %0, t; }" : "=r"(a) : "l"(p));
    return a;
}
__device__ __forceinline__ void ldsm_x4(uint32_t& r0, uint32_t& r1, uint32_t& r2,
                                        uint32_t& r3, uint32_t addr) {
    asm volatile("ldmatrix.sync.aligned.m8n8.x4.shared.b16 {%0,%1,%2,%3}, [%4];"
                 : "=r"(r0), "=r"(r1), "=r"(r2), "=r"(r3) : "r"(addr));
}
__device__ __forceinline__ void mma_f16(float* d, const uint32_t* a, uint32_t b0, uint32_t b1) {
    asm volatile("mma.sync.aligned.m16n8k16.row.col.f32.f16.f16.f32 "
                 "{%0,%1,%2,%3},{%4,%5,%6,%7},{%8,%9},{%0,%1,%2,%3};"
                 : "+f"(d[0]), "+f"(d[1]), "+f"(d[2]), "+f"(d[3])
                 : "r"(a[0]), "r"(a[1]), "r"(a[2]), "r"(a[3]), "r"(b0), "r"(b1));
}
__device__ __forceinline__ void cpa16(uint32_t dst, const void* src) {
    asm volatile("cp.async.cg.shared.global [%0], [%1], 16;" :: "r"(dst), "l"(src) : "memory");
}
__device__ __forceinline__ void cpa_commit() { asm volatile("cp.async.commit_group;" ::: "memory"); }
__device__ __forceinline__ void cpa_wait1()  { asm volatile("cp.async.wait_group 1;" ::: "memory"); }
__device__ __forceinline__ void cpa_wait0()  { asm volatile("cp.async.wait_group 0;" ::: "memory"); }

// =====================================================================
// fp16 mma GEMM: C[M,N] = alpha*(A @ B^T) (+res), row-major, single pass.
// Tile 128 x BN (BN in {64,128}), BK=64, 3-stage cp.async pipeline,
// 128-byte smem rows with (c16 ^= row&7) swizzle.
// OUT=0: fp32 C (+res, *alpha).
// OUT=2: fp16 store to Cp (*alpha).
// OUT=3: fp16 store of sigmoid(res)*silu(acc) to Cp   (FFN up+activation).
// aHead/cHead: base = (z>>4)*TT*ld + (z&15)*DH (per-head slice of [token][1024]).
// =====================================================================
template<int BN, int OUT>
__global__ void __launch_bounds__(256, 2)
mma_gemm(const __half* __restrict__ A, int lda, size_t aZ, int aHead,
         const __half* __restrict__ B, int ldb, size_t bZ,
         float* __restrict__ C, int ldc, size_t cZ, int cHead,
         __half* __restrict__ Cp,
         const float* __restrict__ res, int K, float alpha)
{
    constexpr int APL = 128 * 128;             // bytes, A tile (128 rows x 128B)
    constexpr int BPL = BN * 128;
    constexpr int STG = APL + BPL;
    constexpr int UNITS = 1024 + BN * 8;       // 16B units per chunk
    constexpr int MF = (BN == 128) ? 4 : 2;
    constexpr int NF = 4;

    extern __shared__ char sm[];
    const int tid = threadIdx.x, wid = tid >> 5, lane = tid & 31;
    const int bm = blockIdx.y * 128, bn = blockIdx.x * BN;
    const int z = blockIdx.z;
    const uint32_t smb = smem_u32(sm);

    const size_t abase = aHead ? ((size_t)(z >> 4) * TT * lda + (size_t)(z & 15) * DH)
                               : (size_t)z * aZ;
    const __half* Ab = A + abase + (size_t)bm * lda;
    const __half* Bb = B + (size_t)z * bZ + (size_t)bn * ldb;

    const int wr = (BN == 128) ? (wid >> 2) : (wid >> 1);
    const int wc = (BN == 128) ? (wid & 3)  : (wid & 1);
    const int mrow0 = wr * (MF * 16);
    const int ncol0 = wc * 32;

    float acc[MF][NF][4];
#pragma unroll
    for (int m = 0; m < MF; m++)
#pragma unroll
        for (int n = 0; n < NF; n++)
#pragma unroll
            for (int q = 0; q < 4; q++) acc[m][n][q] = 0.f;

    const int NC = K >> 6;

    auto issue = [&](int c, int stage) {
        const int k0 = c << 6;
        const uint32_t sb = smb + stage * STG;
#pragma unroll
        for (int u = 0; u < UNITS / 256; u++) {
            const int idx = u * 256 + tid;
            if (idx < 1024) {
                const int r = idx >> 3, c8 = idx & 7;
                const uint32_t off = (uint32_t)(r * 128 + ((c8 ^ (r & 7)) << 4));
                cpa16(sb + off, Ab + (size_t)r * lda + k0 + c8 * 8);
            } else {
                const int j = idx - 1024;
                const int r = j >> 3, c8 = j & 7;
                const uint32_t off = (uint32_t)(r * 128 + ((c8 ^ (r & 7)) << 4));
                cpa16(sb + APL + off, Bb + (size_t)r * ldb + k0 + c8 * 8);
            }
        }
        cpa_commit();
    };

    issue(0, 0);
    if (NC > 1) issue(1, 1);

    for (int c = 0; c < NC; ++c) {
        if (c < NC - 1) cpa_wait1(); else cpa_wait0();
        __syncthreads();
        if (c + 2 < NC) issue(c + 2, (c + 2) % 3);

        const uint32_t aB = smb + (c % 3) * STG;
        const uint32_t bB = aB + APL;
#pragma unroll
        for (int ks = 0; ks < 4; ks++) {
            uint32_t af[MF][4];
#pragma unroll
            for (int m = 0; m < MF; m++) {
                const int row = mrow0 + m * 16 + (lane & 15);
                const int c16 = ks * 2 + (lane >> 4);
                ldsm_x4(af[m][0], af[m][1], af[m][2], af[m][3],
                        aB + row * 128 + ((c16 ^ (row & 7)) << 4));
            }
            uint32_t bf[2][4];
#pragma unroll
            for (int g = 0; g < 2; g++) {
                const int row = ncol0 + g * 16 + (lane & 15);
                const int c16 = ks * 2 + (lane >> 4);
                ldsm_x4(bf[g][0], bf[g][1], bf[g][2], bf[g][3],
                        bB + row * 128 + ((c16 ^ (row & 7)) << 4));
            }
#pragma unroll
            for (int m = 0; m < MF; m++)
#pragma unroll
                for (int nf = 0; nf < NF; nf++)
                    mma_f16(acc[m][nf], af[m], bf[nf >> 1][nf & 1], bf[nf >> 1][(nf & 1) + 2]);
        }
    }

    // ---- epilogue ----
    const size_t cbase = cHead ? ((size_t)(z >> 4) * TT * ldc + (size_t)(z & 15) * DH)
                               : (size_t)z * cZ;
    if (OUT == 0) {
        float* Cb = C + cbase + (size_t)bm * ldc + bn;
        const float* Rb = res ? res + cbase + (size_t)bm * ldc + bn : (const float*)0;
#pragma unroll
        for (int m = 0; m < MF; m++) {
            const int r0 = mrow0 + m * 16 + (lane >> 2);
#pragma unroll
            for (int h = 0; h < 2; h++) {
                const int r = r0 + h * 8;
                float* crow = Cb + (size_t)r * ldc;
                const float* rrow = Rb ? Rb + (size_t)r * ldc : (const float*)0;
#pragma unroll
                for (int nf = 0; nf < NF; nf++) {
                    const int col = ncol0 + nf * 8 + (lane & 3) * 2;
                    float2 v;
                    v.x = acc[m][nf][2*h + 0] * alpha;
                    v.y = acc[m][nf][2*h + 1] * alpha;
                    if (rrow) { v.x += rrow[col]; v.y += rrow[col + 1]; }
                    *(float2*)(crow + col) = v;
                }
            }
        }
    } else if (OUT == 2) {
        __half* Ch = Cp + cbase + (size_t)bm * ldc + bn;
#pragma unroll
        for (int m = 0; m < MF; m++) {
            const int r0 = mrow0 + m * 16 + (lane >> 2);
#pragma unroll
            for (int h = 0; h < 2; h++) {
                const int r = r0 + h * 8;
#pragma unroll
                for (int nf = 0; nf < NF; nf++) {
                    const int col = ncol0 + nf * 8 + (lane & 3) * 2;
                    __half2 hh;
                    hh.x = __float2half_rn(acc[m][nf][2*h + 0] * alpha);
                    hh.y = __float2half_rn(acc[m][nf][2*h + 1] * alpha);
                    *(__half2*)(Ch + (size_t)r * ldc + col) = hh;
                }
            }
        }
    } else {   // OUT == 3: h = sigmoid(gate) * silu(up)
        __half* Ch = Cp + cbase + (size_t)bm * ldc + bn;
        const float* Gb = res + cbase + (size_t)bm * ldc + bn;
#pragma unroll
        for (int m = 0; m < MF; m++) {
            const int r0 = mrow0 + m * 16 + (lane >> 2);
#pragma unroll
            for (int h = 0; h < 2; h++) {
                const int r = r0 + h * 8;
                const float* grow = Gb + (size_t)r * ldc;
#pragma unroll
                for (int nf = 0; nf < NF; nf++) {
                    const int col = ncol0 + nf * 8 + (lane & 3) * 2;
                    __half2 hh;
#pragma unroll
                    for (int q = 0; q < 2; q++) {
                        const float u = acc[m][nf][2*h + q];
                        const float g = grow[col + q];
                        const float sg = 1.f / (1.f + __expf(-g));
                        const float su = u / (1.f + __expf(-u));
                        ((__half*)&hh)[q] = __float2half_rn(sg * su);
                    }
                    *(__half2*)(Ch + (size_t)r * ldc + col) = hh;
                }
            }
        }
    }
}

// =====================================================================
// fp32 -> fp16 convert kernel
// =====================================================================
__global__ void __launch_bounds__(256)
half_kernel(const float* __restrict__ s, __half* __restrict__ hi, size_t n2)
{
    const float2* s2 = (const float2*)s;
    __half2* h2 = (__half2*)hi;
    for (size_t i = (size_t)blockIdx.x * 256 + threadIdx.x; i < n2; i += (size_t)gridDim.x * 256) {
        const float2 v = s2[i];
        __half2 h;
        h.x = __float2half_rn(v.x); h.y = __float2half_rn(v.y);
        h2[i] = h;
    }
}

// =====================================================================
// Family basis pool -> scores, basis, resid fp32 + resid fp16 plane
// =====================================================================
__global__ void __launch_bounds__(256)
family_kernel(const float* __restrict__ x, const float* __restrict__ fgw,
              const float* __restrict__ proto, float* __restrict__ fs_out)
{
    __shared__ float xs[D_MODEL];
    __shared__ float sc[NFAM];
    const int row = blockIdx.x;
    const int tid = threadIdx.x;
    const float* xr = x + (size_t)row * D_MODEL;
    for (int d = tid; d < D_MODEL; d += 256) xs[d] = xr[d];
    __syncthreads();

    const int warp = tid >> 5, lane = tid & 31;
    for (int f = warp; f < NFAM; f += 8) {
        const float* w = fgw + (size_t)f * D_MODEL;
        float s = 0.f;
        for (int d = lane; d < D_MODEL; d += 32) s += xs[d] * w[d];
#pragma unroll
        for (int o = 16; o; o >>= 1) s += __shfl_xor_sync(0xffffffffu, s, o);
        if (lane == 0) sc[f] = s;
    }
    __syncthreads();

    if (tid < 32) {
        float m = fmaxf(sc[tid], sc[tid + 32]);
#pragma unroll
        for (int o = 16; o; o >>= 1) m = fmaxf(m, __shfl_xor_sync(0xffffffffu, m, o));
        const float e0 = __expf(sc[tid] - m);
        const float e1 = __expf(sc[tid + 32] - m);
        float s = e0 + e1;
#pragma unroll
        for (int o = 16; o; o >>= 1) s += __shfl_xor_sync(0xffffffffu, s, o);
        const float inv = 1.f / s;
        sc[tid]      = e0 * inv;
        sc[tid + 32] = e1 * inv;
    }
    __syncthreads();

    if (tid < NFAM) fs_out[(size_t)row * NFAM + tid] = sc[tid];

    for (int d = tid; d < D_MODEL; d += 256) {
        float b = 0.f;
#pragma unroll 8
        for (int f = 0; f < NFAM; f++) b += sc[f] * proto[f * D_MODEL + d];
        const size_t idx = (size_t)row * D_MODEL + d;
        g_basis[idx] = b;
        const float r = xs[d] - b;
        g_resid[idx] = r;
        b_resid_h[idx] = __float2half_rn(r);
    }
}

// =====================================================================
// Top-16 candidates from approx fp16 coeffs, exact fp32 re-rank to top-8.
// =====================================================================
__global__ void __launch_bounds__(256)
topk_kernel(const float* __restrict__ dict_w, const float* __restrict__ enc_w,
            const float* __restrict__ bias)
{
    __shared__ float sval[256 * NCAND];
    __shared__ int   sidx[256 * NCAND];
    __shared__ float rv[256];
    __shared__ int   ri[256];
    __shared__ int   rp[256];
    __shared__ int   candi[NCAND];
    __shared__ float exv[NCAND];
    __shared__ float selv[TOPK];
    __shared__ int   seli[TOPK];

    const int row = blockIdx.x;
    const int tid = threadIdx.x;
    const __half* cr = b_coeffs + (size_t)row * DICT;

    float lv[NCAND]; int li[NCAND];
#pragma unroll
    for (int r = 0; r < NCAND; r++) { lv[r] = -FLT_MAX; li[r] = 0x7fffffff; }
    for (int j = tid; j < DICT; j += 256) {
        const float v = __half2float(cr[j]);
        if (v > lv[NCAND-1]) {
            int p = NCAND - 1;
            while (p > 0 && lv[p-1] < v) { lv[p] = lv[p-1]; li[p] = li[p-1]; p--; }
            lv[p] = v; li[p] = j;
        }
    }
#pragma unroll
    for (int r = 0; r < NCAND; r++) { sval[tid*NCAND + r] = lv[r]; sidx[tid*NCAND + r] = li[r]; }
    __syncthreads();

    for (int sel = 0; sel < NCAND; sel++) {
        float bv = -FLT_MAX; int bi = 0x7fffffff; int bp = 0;
#pragma unroll
        for (int r = 0; r < NCAND; r++) {
            const int p = tid*NCAND + r;
            const float v = sval[p]; const int ix = sidx[p];
            if (v > bv || (v == bv && ix < bi)) { bv = v; bi = ix; bp = p; }
        }
        rv[tid] = bv; ri[tid] = bi; rp[tid] = bp;
        __syncthreads();
        for (int s = 128; s > 0; s >>= 1) {
            if (tid < s) {
                if (rv[tid+s] > rv[tid] || (rv[tid+s] == rv[tid] && ri[tid+s] < ri[tid])) {
                    rv[tid] = rv[tid+s]; ri[tid] = ri[tid+s]; rp[tid] = rp[tid+s];
                }
            }
            __syncthreads();
        }
        if (tid == 0) {
            candi[sel] = ri[0];
            sval[rp[0]] = -FLT_MAX; sidx[rp[0]] = 0x7fffffff;
        }
        __syncthreads();
    }

    {
        const int warp = tid >> 5, lane = tid & 31;
        const float* rr = g_resid + (size_t)row * D_MODEL;
        for (int j = warp; j < NCAND; j += 8) {
            const float* er = enc_w + (size_t)candi[j] * D_MODEL;
            float s = 0.f;
            for (int d = lane; d < D_MODEL; d += 32) s += rr[d] * er[d];
#pragma unroll
            for (int o = 16; o; o >>= 1) s += __shfl_xor_sync(0xffffffffu, s, o);
            if (lane == 0) exv[j] = s;
        }
    }
    __syncthreads();

    if (tid == 0) {
        unsigned used = 0;
        float ssum = 0.f;
        for (int sel = 0; sel < TOPK; sel++) {
            float bv = -FLT_MAX; int bi = 0x7fffffff; int bp = -1;
            for (int j = 0; j < NCAND; j++) {
                if (used & (1u << j)) continue;
                const float v = exv[j]; const int ix = candi[j];
                if (v > bv || (v == bv && ix < bi)) { bv = v; bi = ix; bp = j; }
            }
            used |= (1u << bp);
            selv[sel] = bv; seli[sel] = bi;
            ssum += fabsf(bv);
        }
        g_spars[row] = ssum;
    }
    __syncthreads();

    for (int d = tid; d < D_MODEL; d += 256) {
        float o = g_basis[(size_t)row * D_MODEL + d] + bias[d];
#pragma unroll
        for (int j = 0; j < TOPK; j++) o += selv[j] * dict_w[(size_t)seli[j] * D_MODEL + d];
        g_xrec[(size_t)row * D_MODEL + d] = o;
    }
}

// =====================================================================
// RMSNorm -> fp16 plane
// =====================================================================
__global__ void __launch_bounds__(256)
rmsnorm_kernel(const float* __restrict__ in, const float* __restrict__ w,
               __half* __restrict__ hi, float* __restrict__ rmsbuf)
{
    __shared__ float red[256];
    const int row = blockIdx.x, tid = threadIdx.x;
    const float* xr = in + (size_t)row * D_MODEL;
    float s = 0.f;
    for (int d = tid; d < D_MODEL; d += 256) { const float v = xr[d]; s += v * v; }
    red[tid] = s;
    __syncthreads();
    for (int st = 128; st > 0; st >>= 1) { if (tid < st) red[tid] += red[tid + st]; __syncthreads(); }
    const float rms = sqrtf(red[0] / (float)D_MODEL + EPS_F);
    const float inv = 1.f / rms;
    for (int d = tid; d < D_MODEL; d += 256)
        hi[(size_t)row * D_MODEL + d] = __float2half_rn(w[d] * xr[d] * inv);
    if (tid == 0) rmsbuf[row] = rms;
}

// =====================================================================
// k_mod -> fp16 plane  [bh][t][64]
// =====================================================================
__global__ void __launch_bounds__(256)
kmod_kernel(const float* __restrict__ kbuf, const float* __restrict__ rel)
{
    __shared__ float ks[64][65];
    __shared__ float ts[64][65];
    const int bh = blockIdx.y, b = bh >> 4, h = bh & 15;
    const int t0 = blockIdx.x * 64;
    const int tid = threadIdx.x;
    for (int i = tid; i < 4096; i += 256) {
        const int r = i >> 6, c = i & 63;
        ks[r][c] = kbuf[(size_t)(b*TT + t0 + r) * D_MODEL + h*DH + c];
        ts[r][c] = rel[(size_t)h*DH*DH + r*DH + c];
    }
    __syncthreads();
    const int tx = tid & 15, ty = tid >> 4;
    float acc[4][4] = {};
#pragma unroll
    for (int d = 0; d < 64; d++) {
        float ra[4], rb[4];
#pragma unroll
        for (int i = 0; i < 4; i++) ra[i] = ks[ty*4 + i][d];
#pragma unroll
        for (int j = 0; j < 4; j++) rb[j] = ts[d][tx*4 + j];
#pragma unroll
        for (int i = 0; i < 4; i++)
#pragma unroll
            for (int j = 0; j < 4; j++) acc[i][j] += ra[i] * rb[j];
    }
#pragma unroll
    for (int i = 0; i < 4; i++)
#pragma unroll
        for (int j = 0; j < 4; j++)
            b_kmod[((size_t)bh*TT + t0 + ty*4 + i) * DH + tx*4 + j] = __float2half_rn(acc[i][j]);
}

// =====================================================================
// V transpose -> fp16 plane  [bh][64][t]
// =====================================================================
__global__ void __launch_bounds__(256)
vtrans_kernel(const float* __restrict__ v)
{
    __shared__ float t[64][65];
    const int z = blockIdx.y, b = z >> 4, h = z & 15;
    const int t0 = blockIdx.x * 64;
    for (int i = threadIdx.x; i < 4096; i += 256) {
        const int r = i >> 6, c = i & 63;
        t[r][c] = v[(size_t)(b*TT + t0 + r) * D_MODEL + h*DH + c];
    }
    __syncthreads();
    for (int i = threadIdx.x; i < 4096; i += 256) {
        const int e = i >> 6, r = i & 63;
        b_vt[(size_t)z * DH * TT + (size_t)e * TT + t0 + r] = __float2half_rn(t[r][e]);
    }
}

// =====================================================================
// Row softmax over 2048, fp32 in place + fp16 plane copy
// =====================================================================
__global__ void __launch_bounds__(256)
softmax_kernel(float* __restrict__ P, __half* __restrict__ ph)
{
    __shared__ float red[256];
    const size_t row = blockIdx.x;
    float* p = P + row * (size_t)TT;
    __half* oh = ph + row * (size_t)TT;
    const int tid = threadIdx.x;
    float v[8];
#pragma unroll
    for (int i = 0; i < 8; i++) v[i] = p[tid + i*256];
    float m = v[0];
#pragma unroll
    for (int i = 1; i < 8; i++) m = fmaxf(m, v[i]);
    red[tid] = m;
    __syncthreads();
    for (int st = 128; st > 0; st >>= 1) { if (tid < st) red[tid] = fmaxf(red[tid], red[tid+st]); __syncthreads(); }
    m = red[0];
    __syncthreads();
    float s = 0.f;
#pragma unroll
    for (int i = 0; i < 8; i++) { v[i] = __expf(v[i] - m); s += v[i]; }
    red[tid] = s;
    __syncthreads();
    for (int st = 128; st > 0; st >>= 1) { if (tid < st) red[tid] += red[tid+st]; __syncthreads(); }
    const float inv = 1.f / red[0];
#pragma unroll
    for (int i = 0; i < 8; i++) {
        const float vv = v[i] * inv;
        p[tid + i*256] = vv;
        oh[tid + i*256] = __float2half_rn(vv);
    }
}

// =====================================================================
// Final scalars
// =====================================================================
__global__ void __launch_bounds__(256)
finalize_kernel(float* __restrict__ out)
{
    __shared__ float s1[256], s2[256], s3[256];
    const int tid = threadIdx.x;
    float a = 0.f, b = 0.f, c = 0.f;
    for (int i = tid; i < BT; i += 256) { a += g_spars[i]; b += g_rms1[i]; c += g_rms2[i]; }
    s1[tid] = a; s2[tid] = b; s3[tid] = c;
    __syncthreads();
    for (int st = 128; st > 0; st >>= 1) {
        if (tid < st) { s1[tid] += s1[tid+st]; s2[tid] += s2[tid+st]; s3[tid] += s3[tid+st]; }
        __syncthreads();
    }
    if (tid == 0) {
        out[SC_OFF + 0] = s1[0] / ((float)BB * (float)TT * (float)DICT);
        out[SC_OFF + 1] = s2[0] / (float)BT;
        out[SC_OFF + 2] = s3[0] / (float)BT;
    }
}

// =====================================================================
// host launcher
// =====================================================================
extern "C" void kernel_launch(void* const* d_in, const int* in_sizes, int n_in,
                              void* d_out, int out_size)
{
    (void)in_sizes; (void)n_in; (void)out_size;
    const float* x     = (const float*)d_in[0];
    const float* proto = (const float*)d_in[2];
    const float* fgw   = (const float*)d_in[3];
    const float* dictw = (const float*)d_in[4];
    const float* encw  = (const float*)d_in[5];
    const float* wq    = (const float*)d_in[6];
    const float* wk    = (const float*)d_in[7];
    const float* wv    = (const float*)d_in[8];
    const float* wo    = (const float*)d_in[9];
    const float* rel   = (const float*)d_in[10];
    const float* gatew = (const float*)d_in[11];
    const float* upw   = (const float*)d_in[12];
    const float* downw = (const float*)d_in[13];
    const float* n1w   = (const float*)d_in[14];
    const float* n2w   = (const float*)d_in[15];
    const float* bias  = (const float*)d_in[16];
    float* out = (float*)d_out;

    const int SM_128 = 3 * (16384 + 16384);   // 98304
    const int SM_64  = 3 * (16384 +  8192);   // 73728
    cudaFuncSetAttribute(mma_gemm<128,0>, cudaFuncAttributeMaxDynamicSharedMemorySize, SM_128);
    cudaFuncSetAttribute(mma_gemm<128,2>, cudaFuncAttributeMaxDynamicSharedMemorySize, SM_128);
    cudaFuncSetAttribute(mma_gemm<128,3>, cudaFuncAttributeMaxDynamicSharedMemorySize, SM_128);
    cudaFuncSetAttribute(mma_gemm<64,2>,  cudaFuncAttributeMaxDynamicSharedMemorySize, SM_64);

    float *p_xrec, *p_k, *p_v, *p_x2, *p_gate, *p_rms1, *p_rms2;
    cudaGetSymbolAddress((void**)&p_xrec,   g_xrec);
    cudaGetSymbolAddress((void**)&p_k,      g_k);
    cudaGetSymbolAddress((void**)&p_v,      g_v);
    cudaGetSymbolAddress((void**)&p_x2,     g_x2);
    cudaGetSymbolAddress((void**)&p_gate,   g_gate);
    cudaGetSymbolAddress((void**)&p_rms1,   g_rms1);
    cudaGetSymbolAddress((void**)&p_rms2,   g_rms2);

    __half *pb_coeffs, *pb_resid, *pb_enc, *pb_normed, *pb_normed2, *pb_q, *pb_kmod,
           *pb_vt, *pb_ctx, *pb_h, *pb_attn,
           *pb_wq, *pb_wk, *pb_wv, *pb_wo, *pb_gw, *pb_uw, *pb_dw;
    cudaGetSymbolAddress((void**)&pb_coeffs,  b_coeffs);
    cudaGetSymbolAddress((void**)&pb_resid,   b_resid_h);
    cudaGetSymbolAddress((void**)&pb_enc,     b_enc_h);
    cudaGetSymbolAddress((void**)&pb_normed,  b_normed);
    cudaGetSymbolAddress((void**)&pb_normed2, b_normed2);
    cudaGetSymbolAddress((void**)&pb_q,       b_q);
    cudaGetSymbolAddress((void**)&pb_kmod,    b_kmod);
    cudaGetSymbolAddress((void**)&pb_vt,      b_vt);
    cudaGetSymbolAddress((void**)&pb_ctx,     b_ctx);
    cudaGetSymbolAddress((void**)&pb_h,       b_h);
    cudaGetSymbolAddress((void**)&pb_attn,    b_attn);
    cudaGetSymbolAddress((void**)&pb_wq,      b_wq);
    cudaGetSymbolAddress((void**)&pb_wk,      b_wk);
    cudaGetSymbolAddress((void**)&pb_wv,      b_wv);
    cudaGetSymbolAddress((void**)&pb_wo,      b_wo);
    cudaGetSymbolAddress((void**)&pb_gw,      b_gw);
    cudaGetSymbolAddress((void**)&pb_uw,      b_uw);
    cudaGetSymbolAddress((void**)&pb_dw,      b_dw);

    // launches 1-5 (skipped by ncu -s 5), #6 = coeffs GEMM (captured)
    half_kernel<<<1024, 256>>>(encw, pb_enc, PE/2);      // 1
    half_kernel<<<256, 256>>>(wq, pb_wq, PW/2);          // 2
    half_kernel<<<256, 256>>>(wk, pb_wk, PW/2);          // 3
    half_kernel<<<256, 256>>>(wv, pb_wv, PW/2);          // 4
    family_kernel<<<BT, 256>>>(x, fgw, proto, out + FS_OFF);   // 5

    // 6) approx coeffs (fp16 out; exact re-rank in topk)
    mma_gemm<128,2><<<dim3(DICT/128, BT/128, 1), 256, SM_128>>>(
        pb_resid, D_MODEL, 0, 0, pb_enc, D_MODEL, 0,
        nullptr, DICT, 0, 0, pb_coeffs, nullptr, D_MODEL, 1.0f);

    // remaining weight converts
    half_kernel<<<256, 256>>>(wo,    pb_wo, PW/2);
    half_kernel<<<512, 256>>>(gatew, pb_gw, PF/2);
    half_kernel<<<512, 256>>>(upw,   pb_uw, PF/2);
    half_kernel<<<512, 256>>>(downw, pb_dw, PF/2);

    // top-16 + exact fp32 re-rank -> x_rec, sparsity
    topk_kernel<<<BT, 256>>>(dictw, encw, bias);

    // norm1 -> fp16 plane
    rmsnorm_kernel<<<BT, 256>>>(p_xrec, n1w, pb_normed, p_rms1);

    // q (fp16 out), k, v (fp32 out)
    mma_gemm<128,2><<<dim3(D_MODEL/128, BT/128, 1), 256, SM_128>>>(
        pb_normed, D_MODEL, 0, 0, pb_wq, D_MODEL, 0,
        nullptr, D_MODEL, 0, 0, pb_q, nullptr, D_MODEL, 1.0f);
    mma_gemm<128,0><<<dim3(D_MODEL/128, BT/128, 1), 256, SM_128>>>(
        pb_normed, D_MODEL, 0, 0, pb_wk, D_MODEL, 0,
        p_k, D_MODEL, 0, 0, nullptr, nullptr, D_MODEL, 1.0f);
    mma_gemm<128,0><<<dim3(D_MODEL/128, BT/128, 1), 256, SM_128>>>(
        pb_normed, D_MODEL, 0, 0, pb_wv, D_MODEL, 0,
        p_v, D_MODEL, 0, 0, nullptr, nullptr, D_MODEL, 1.0f);

    // k_mod + V transpose (fp16 planes)
    kmod_kernel<<<dim3(TT/64, BB*N_HEADS), 256>>>(p_k, rel);
    vtrans_kernel<<<dim3(TT/64, BB*N_HEADS), 256>>>(p_v);

    // logits -> d_out fp32, softmax -> fp32 + fp16 plane
    mma_gemm<128,0><<<dim3(TT/128, TT/128, BB*N_HEADS), 256, SM_128>>>(
        pb_q, D_MODEL, 0, 1, pb_kmod, DH, (size_t)TT*DH,
        out + ATT_OFF, TT, (size_t)TT*TT, 0, nullptr, nullptr, DH, 0.125f);
    softmax_kernel<<<BB*N_HEADS*TT, 256>>>(out + ATT_OFF, pb_attn);

    // ctx = attn @ v (fp16 out, head-sliced)
    mma_gemm<64,2><<<dim3(1, TT/128, BB*N_HEADS), 256, SM_64>>>(
        pb_attn, TT, (size_t)TT*TT, 0, pb_vt, TT, (size_t)DH*TT,
        nullptr, D_MODEL, 0, 1, pb_ctx, nullptr, TT, 1.0f);

    // x2 = x + ctx @ wo^T
    mma_gemm<128,0><<<dim3(D_MODEL/128, BT/128, 1), 256, SM_128>>>(
        pb_ctx, D_MODEL, 0, 0, pb_wo, D_MODEL, 0,
        p_x2, D_MODEL, 0, 0, nullptr, x, D_MODEL, 1.0f);

    // norm2 -> fp16 plane
    rmsnorm_kernel<<<BT, 256>>>(p_x2, n2w, pb_normed2, p_rms2);

    // FFN: gate (fp32), up (+fused activation -> b_h fp16)
    mma_gemm<128,0><<<dim3(D_FF/128, BT/128, 1), 256, SM_128>>>(
        pb_normed2, D_MODEL, 0, 0, pb_gw, D_MODEL, 0,
        p_gate, D_FF, 0, 0, nullptr, nullptr, D_MODEL, 1.0f);
    mma_gemm<128,3><<<dim3(D_FF/128, BT/128, 1), 256, SM_128>>>(
        pb_normed2, D_MODEL, 0, 0, pb_uw, D_MODEL, 0,
        nullptr, D_FF, 0, 0, pb_h, p_gate, D_MODEL, 1.0f);

    // final x = x2 + h @ down^T -> d_out
    mma_gemm<128,0><<<dim3(D_MODEL/128, BT/128, 1), 256, SM_128>>>(
        pb_h, D_FF, 0, 0, pb_dw, D_FF, 0,
        out + X_OFF, D_MODEL, 0, 0, nullptr, p_x2, D_FF, 1.0f);

    // scalars
    finalize_kernel<<<1, 256>>>(out);
}

// round 14
// speedup vs baseline: 2.1300x; 1.0023x over previous
#include <cuda_runtime.h>
#include <cuda_fp16.h>
#include <math.h>
#include <float.h>
#include <stdint.h>

// ---------------- problem dims (fixed by setup_inputs) ----------------
#define D_MODEL 1024
#define N_HEADS 16
#define DH      64
#define D_FF    4096
#define NFAM    64
#define DICT    16384
#define BB      2
#define TT      2048
#define BT      (BB*TT)
#define TOPK    8
#define NCAND   16
#define EPS_F   1e-6f

#define X_N     ((size_t)BT * D_MODEL)
#define ATT_N   ((size_t)BB * N_HEADS * TT * TT)
#define FS_N    ((size_t)BT * NFAM)
#define X_OFF   ((size_t)0)
#define ATT_OFF (X_N)
#define FS_OFF  (X_N + ATT_N)
#define SC_OFF  (X_N + ATT_N + FS_N)

#define PD   ((size_t)BT * D_MODEL)
#define PW   ((size_t)D_MODEL * D_MODEL)
#define PF   ((size_t)D_FF * D_MODEL)
#define PH   ((size_t)BT * D_FF)
#define PE   ((size_t)DICT * D_MODEL)

// ---------------- fp32 scratch ----------------
__device__ float g_resid  [BT * D_MODEL];
__device__ float g_basis  [BT * D_MODEL];
__device__ float g_xrec   [BT * D_MODEL];
__device__ float g_x2     [BT * D_MODEL];
__device__ float g_up     [(size_t)BT * D_FF];
__device__ float g_rms1   [BT];
__device__ float g_rms2   [BT];
__device__ float g_spars  [BT];

// ---------------- fp16 planes ----------------
__device__ __align__(16) __half b_coeffs [(size_t)BT * DICT];   // 128 MB
__device__ __align__(16) __half b_resid_h[PD];
__device__ __align__(16) __half b_enc_h  [PE];
__device__ __align__(16) __half b_normed [PD];
__device__ __align__(16) __half b_normed2[PD];
__device__ __align__(16) __half b_qkv    [3 * PD];   // q/k/v fp16 planes
__device__ __align__(16) __half b_kmod   [PD];       // [bh][t][64]
__device__ __align__(16) __half b_vt     [PD];       // [bh][64][t]
__device__ __align__(16) __half b_ctx    [PD];
__device__ __align__(16) __half b_h      [PH];
__device__ __align__(16) __half b_wqkv   [3 * PW];   // packed wq/wk/wv
__device__ __align__(16) __half b_wo     [PW];
__device__ __align__(16) __half b_gw     [PF];
__device__ __align__(16) __half b_uw     [PF];
__device__ __align__(16) __half b_dw     [PF];
__device__ __align__(16) __half b_attn   [ATT_N];

// ===================== helpers (baseline PTX, sm_80+) =========
__device__ __forceinline__ uint32_t smem_u32(const void* p) {
    uint32_t a;
    asm("{ .reg .u64 t; cvta.to.shared.u64 t, %1; cvt.u32.u64 %0, t; }" : "=r"(a) : "l"(p));
    return a;
}
__device__ __forceinline__ void ldsm_x4(uint32_t& r0, uint32_t& r1, uint32_t& r2,
                                        uint32_t& r3, uint32_t addr) {
    asm volatile("ldmatrix.sync.aligned.m8n8.x4.shared.b16 {%0,%1,%2,%3}, [%4];"
                 : "=r"(r0), "=r"(r1), "=r"(r2), "=r"(r3) : "r"(addr));
}
__device__ __forceinline__ void mma_f16(float* d, const uint32_t* a, uint32_t b0, uint32_t b1) {
    asm volatile("mma.sync.aligned.m16n8k16.row.col.f32.f16.f16.f32 "
                 "{%0,%1,%2,%3},{%4,%5,%6,%7},{%8,%9},{%0,%1,%2,%3};"
                 : "+f"(d[0]), "+f"(d[1]), "+f"(d[2]), "+f"(d[3])
                 : "r"(a[0]), "r"(a[1]), "r"(a[2]), "r"(a[3]), "r"(b0), "r"(b1));
}
__device__ __forceinline__ void cpa16(uint32_t dst, const void* src) {
    asm volatile("cp.async.cg.shared.global [%0], [%1], 16;" :: "r"(dst), "l"(src) : "memory");
}
__device__ __forceinline__ void cpa_commit() { asm volatile("cp.async.commit_group;" ::: "memory"); }
__device__ __forceinline__ void cpa_wait1()  { asm volatile("cp.async.wait_group 1;" ::: "memory"); }
__device__ __forceinline__ void cpa_wait0()  { asm volatile("cp.async.wait_group 0;" ::: "memory"); }

// =====================================================================
// fp16 mma GEMM: C[M,N] = alpha*(A @ B^T) (+res), row-major, single pass.
// Tile 128 x BN (BN in {64,128}), BK=64, 3-stage cp.async pipeline,
// 128-byte smem rows with (c16 ^= row&7) swizzle.
// OUT=0: fp32 C (+res, *alpha).
// OUT=2: fp16 store to Cp (*alpha).
// OUT=3: fp16 store of sigmoid(acc)*silu(res) to Cp   (gate GEMM + activation).
// aHead/cHead: base = (z>>4)*TT*ld + (z&15)*DH (per-head slice of [token][1024]).
// =====================================================================
template<int BN, int OUT>
__global__ void __launch_bounds__(256, 2)
mma_gemm(const __half* __restrict__ A, int lda, size_t aZ, int aHead,
         const __half* __restrict__ B, int ldb, size_t bZ,
         float* __restrict__ C, int ldc, size_t cZ, int cHead,
         __half* __restrict__ Cp,
         const float* __restrict__ res, int K, float alpha)
{
    constexpr int APL = 128 * 128;             // bytes, A tile (128 rows x 128B)
    constexpr int BPL = BN * 128;
    constexpr int STG = APL + BPL;
    constexpr int UNITS = 1024 + BN * 8;       // 16B units per chunk
    constexpr int MF = (BN == 128) ? 4 : 2;
    constexpr int NF = 4;

    extern __shared__ char sm[];
    const int tid = threadIdx.x, wid = tid >> 5, lane = tid & 31;
    const int bm = blockIdx.y * 128, bn = blockIdx.x * BN;
    const int z = blockIdx.z;
    const uint32_t smb = smem_u32(sm);

    const size_t abase = aHead ? ((size_t)(z >> 4) * TT * lda + (size_t)(z & 15) * DH)
                               : (size_t)z * aZ;
    const __half* Ab = A + abase + (size_t)bm * lda;
    const __half* Bb = B + (size_t)z * bZ + (size_t)bn * ldb;

    const int wr = (BN == 128) ? (wid >> 2) : (wid >> 1);
    const int wc = (BN == 128) ? (wid & 3)  : (wid & 1);
    const int mrow0 = wr * (MF * 16);
    const int ncol0 = wc * 32;

    float acc[MF][NF][4];
#pragma unroll
    for (int m = 0; m < MF; m++)
#pragma unroll
        for (int n = 0; n < NF; n++)
#pragma unroll
            for (int q = 0; q < 4; q++) acc[m][n][q] = 0.f;

    const int NC = K >> 6;

    auto issue = [&](int c, int stage) {
        const int k0 = c << 6;
        const uint32_t sb = smb + stage * STG;
#pragma unroll
        for (int u = 0; u < UNITS / 256; u++) {
            const int idx = u * 256 + tid;
            if (idx < 1024) {
                const int r = idx >> 3, c8 = idx & 7;
                const uint32_t off = (uint32_t)(r * 128 + ((c8 ^ (r & 7)) << 4));
                cpa16(sb + off, Ab + (size_t)r * lda + k0 + c8 * 8);
            } else {
                const int j = idx - 1024;
                const int r = j >> 3, c8 = j & 7;
                const uint32_t off = (uint32_t)(r * 128 + ((c8 ^ (r & 7)) << 4));
                cpa16(sb + APL + off, Bb + (size_t)r * ldb + k0 + c8 * 8);
            }
        }
        cpa_commit();
    };

    issue(0, 0);
    if (NC > 1) issue(1, 1);

    for (int c = 0; c < NC; ++c) {
        if (c < NC - 1) cpa_wait1(); else cpa_wait0();
        __syncthreads();
        if (c + 2 < NC) issue(c + 2, (c + 2) % 3);

        const uint32_t aB = smb + (c % 3) * STG;
        const uint32_t bB = aB + APL;
#pragma unroll
        for (int ks = 0; ks < 4; ks++) {
            uint32_t af[MF][4];
#pragma unroll
            for (int m = 0; m < MF; m++) {
                const int row = mrow0 + m * 16 + (lane & 15);
                const int c16 = ks * 2 + (lane >> 4);
                ldsm_x4(af[m][0], af[m][1], af[m][2], af[m][3],
                        aB + row * 128 + ((c16 ^ (row & 7)) << 4));
            }
            uint32_t bf[2][4];
#pragma unroll
            for (int g = 0; g < 2; g++) {
                const int row = ncol0 + g * 16 + (lane & 15);
                const int c16 = ks * 2 + (lane >> 4);
                ldsm_x4(bf[g][0], bf[g][1], bf[g][2], bf[g][3],
                        bB + row * 128 + ((c16 ^ (row & 7)) << 4));
            }
#pragma unroll
            for (int m = 0; m < MF; m++)
#pragma unroll
                for (int nf = 0; nf < NF; nf++)
                    mma_f16(acc[m][nf], af[m], bf[nf >> 1][nf & 1], bf[nf >> 1][(nf & 1) + 2]);
        }
    }

    // ---- epilogue ----
    const size_t cbase = cHead ? ((size_t)(z >> 4) * TT * ldc + (size_t)(z & 15) * DH)
                               : (size_t)z * cZ;
    if (OUT == 0) {
        float* Cb = C + cbase + (size_t)bm * ldc + bn;
        const float* Rb = res ? res + cbase + (size_t)bm * ldc + bn : (const float*)0;
#pragma unroll
        for (int m = 0; m < MF; m++) {
            const int r0 = mrow0 + m * 16 + (lane >> 2);
#pragma unroll
            for (int h = 0; h < 2; h++) {
                const int r = r0 + h * 8;
                float* crow = Cb + (size_t)r * ldc;
                const float* rrow = Rb ? Rb + (size_t)r * ldc : (const float*)0;
#pragma unroll
                for (int nf = 0; nf < NF; nf++) {
                    const int col = ncol0 + nf * 8 + (lane & 3) * 2;
                    float2 v;
                    v.x = acc[m][nf][2*h + 0] * alpha;
                    v.y = acc[m][nf][2*h + 1] * alpha;
                    if (rrow) { v.x += rrow[col]; v.y += rrow[col + 1]; }
                    *(float2*)(crow + col) = v;
                }
            }
        }
    } else if (OUT == 2) {
        __half* Ch = Cp + cbase + (size_t)bm * ldc + bn;
#pragma unroll
        for (int m = 0; m < MF; m++) {
            const int r0 = mrow0 + m * 16 + (lane >> 2);
#pragma unroll
            for (int h = 0; h < 2; h++) {
                const int r = r0 + h * 8;
#pragma unroll
                for (int nf = 0; nf < NF; nf++) {
                    const int col = ncol0 + nf * 8 + (lane & 3) * 2;
                    __half2 hh;
                    hh.x = __float2half_rn(acc[m][nf][2*h + 0] * alpha);
                    hh.y = __float2half_rn(acc[m][nf][2*h + 1] * alpha);
                    *(__half2*)(Ch + (size_t)r * ldc + col) = hh;
                }
            }
        }
    } else {   // OUT == 3: h = sigmoid(acc) * silu(res)   (acc=gate, res=up)
        __half* Ch = Cp + cbase + (size_t)bm * ldc + bn;
        const float* Ub = res + cbase + (size_t)bm * ldc + bn;
#pragma unroll
        for (int m = 0; m < MF; m++) {
            const int r0 = mrow0 + m * 16 + (lane >> 2);
#pragma unroll
            for (int h = 0; h < 2; h++) {
                const int r = r0 + h * 8;
                const float* urow = Ub + (size_t)r * ldc;
#pragma unroll
                for (int nf = 0; nf < NF; nf++) {
                    const int col = ncol0 + nf * 8 + (lane & 3) * 2;
                    __half2 hh;
#pragma unroll
                    for (int q = 0; q < 2; q++) {
                        const float g = acc[m][nf][2*h + q];
                        const float u = urow[col + q];
                        const float sg = 1.f / (1.f + __expf(-g));
                        const float su = u / (1.f + __expf(-u));
                        ((__half*)&hh)[q] = __float2half_rn(sg * su);
                    }
                    *(__half2*)(Ch + (size_t)r * ldc + col) = hh;
                }
            }
        }
    }
}

// =====================================================================
// fp32 -> fp16 convert kernel
// =====================================================================
__global__ void __launch_bounds__(256)
half_kernel(const float* __restrict__ s, __half* __restrict__ hi, size_t n2)
{
    const float2* s2 = (const float2*)s;
    __half2* h2 = (__half2*)hi;
    for (size_t i = (size_t)blockIdx.x * 256 + threadIdx.x; i < n2; i += (size_t)gridDim.x * 256) {
        const float2 v = s2[i];
        __half2 h;
        h.x = __float2half_rn(v.x); h.y = __float2half_rn(v.y);
        h2[i] = h;
    }
}

// =====================================================================
// Family basis pool -> scores, basis, resid fp32 + resid fp16 plane
// =====================================================================
__global__ void __launch_bounds__(256)
family_kernel(const float* __restrict__ x, const float* __restrict__ fgw,
              const float* __restrict__ proto, float* __restrict__ fs_out)
{
    __shared__ float xs[D_MODEL];
    __shared__ float sc[NFAM];
    const int row = blockIdx.x;
    const int tid = threadIdx.x;
    const float* xr = x + (size_t)row * D_MODEL;
    for (int d = tid; d < D_MODEL; d += 256) xs[d] = xr[d];
    __syncthreads();

    const int warp = tid >> 5, lane = tid & 31;
    for (int f = warp; f < NFAM; f += 8) {
        const float* w = fgw + (size_t)f * D_MODEL;
        float s = 0.f;
        for (int d = lane; d < D_MODEL; d += 32) s += xs[d] * w[d];
#pragma unroll
        for (int o = 16; o; o >>= 1) s += __shfl_xor_sync(0xffffffffu, s, o);
        if (lane == 0) sc[f] = s;
    }
    __syncthreads();

    if (tid < 32) {
        float m = fmaxf(sc[tid], sc[tid + 32]);
#pragma unroll
        for (int o = 16; o; o >>= 1) m = fmaxf(m, __shfl_xor_sync(0xffffffffu, m, o));
        const float e0 = __expf(sc[tid] - m);
        const float e1 = __expf(sc[tid + 32] - m);
        float s = e0 + e1;
#pragma unroll
        for (int o = 16; o; o >>= 1) s += __shfl_xor_sync(0xffffffffu, s, o);
        const float inv = 1.f / s;
        sc[tid]      = e0 * inv;
        sc[tid + 32] = e1 * inv;
    }
    __syncthreads();

    if (tid < NFAM) fs_out[(size_t)row * NFAM + tid] = sc[tid];

    for (int d = tid; d < D_MODEL; d += 256) {
        float b = 0.f;
#pragma unroll 8
        for (int f = 0; f < NFAM; f++) b += sc[f] * proto[f * D_MODEL + d];
        const size_t idx = (size_t)row * D_MODEL + d;
        g_basis[idx] = b;
        const float r = xs[d] - b;
        g_resid[idx] = r;
        b_resid_h[idx] = __float2half_rn(r);
    }
}

// =====================================================================
// Top-16 candidates from approx fp16 coeffs, exact fp32 re-rank to top-8.
// =====================================================================
__global__ void __launch_bounds__(256)
topk_kernel(const float* __restrict__ dict_w, const float* __restrict__ enc_w,
            const float* __restrict__ bias)
{
    __shared__ float sval[256 * NCAND];
    __shared__ int   sidx[256 * NCAND];
    __shared__ float rv[256];
    __shared__ int   ri[256];
    __shared__ int   rp[256];
    __shared__ int   candi[NCAND];
    __shared__ float exv[NCAND];
    __shared__ float selv[TOPK];
    __shared__ int   seli[TOPK];

    const int row = blockIdx.x;
    const int tid = threadIdx.x;
    const __half* cr = b_coeffs + (size_t)row * DICT;

    float lv[NCAND]; int li[NCAND];
#pragma unroll
    for (int r = 0; r < NCAND; r++) { lv[r] = -FLT_MAX; li[r] = 0x7fffffff; }
    for (int j = tid; j < DICT; j += 256) {
        const float v = __half2float(cr[j]);
        if (v > lv[NCAND-1]) {
            int p = NCAND - 1;
            while (p > 0 && lv[p-1] < v) { lv[p] = lv[p-1]; li[p] = li[p-1]; p--; }
            lv[p] = v; li[p] = j;
        }
    }
#pragma unroll
    for (int r = 0; r < NCAND; r++) { sval[tid*NCAND + r] = lv[r]; sidx[tid*NCAND + r] = li[r]; }
    __syncthreads();

    for (int sel = 0; sel < NCAND; sel++) {
        float bv = -FLT_MAX; int bi = 0x7fffffff; int bp = 0;
#pragma unroll
        for (int r = 0; r < NCAND; r++) {
            const int p = tid*NCAND + r;
            const float v = sval[p]; const int ix = sidx[p];
            if (v > bv || (v == bv && ix < bi)) { bv = v; bi = ix; bp = p; }
        }
        rv[tid] = bv; ri[tid] = bi; rp[tid] = bp;
        __syncthreads();
        for (int s = 128; s > 0; s >>= 1) {
            if (tid < s) {
                if (rv[tid+s] > rv[tid] || (rv[tid+s] == rv[tid] && ri[tid+s] < ri[tid])) {
                    rv[tid] = rv[tid+s]; ri[tid] = ri[tid+s]; rp[tid] = rp[tid+s];
                }
            }
            __syncthreads();
        }
        if (tid == 0) {
            candi[sel] = ri[0];
            sval[rp[0]] = -FLT_MAX; sidx[rp[0]] = 0x7fffffff;
        }
        __syncthreads();
    }

    {
        const int warp = tid >> 5, lane = tid & 31;
        const float* rr = g_resid + (size_t)row * D_MODEL;
        for (int j = warp; j < NCAND; j += 8) {
            const float* er = enc_w + (size_t)candi[j] * D_MODEL;
            float s = 0.f;
            for (int d = lane; d < D_MODEL; d += 32) s += rr[d] * er[d];
#pragma unroll
            for (int o = 16; o; o >>= 1) s += __shfl_xor_sync(0xffffffffu, s, o);
            if (lane == 0) exv[j] = s;
        }
    }
    __syncthreads();

    if (tid == 0) {
        unsigned used = 0;
        float ssum = 0.f;
        for (int sel = 0; sel < TOPK; sel++) {
            float bv = -FLT_MAX; int bi = 0x7fffffff; int bp = -1;
            for (int j = 0; j < NCAND; j++) {
                if (used & (1u << j)) continue;
                const float v = exv[j]; const int ix = candi[j];
                if (v > bv || (v == bv && ix < bi)) { bv = v; bi = ix; bp = j; }
            }
            used |= (1u << bp);
            selv[sel] = bv; seli[sel] = bi;
            ssum += fabsf(bv);
        }
        g_spars[row] = ssum;
    }
    __syncthreads();

    for (int d = tid; d < D_MODEL; d += 256) {
        float o = g_basis[(size_t)row * D_MODEL + d] + bias[d];
#pragma unroll
        for (int j = 0; j < TOPK; j++) o += selv[j] * dict_w[(size_t)seli[j] * D_MODEL + d];
        g_xrec[(size_t)row * D_MODEL + d] = o;
    }
}

// =====================================================================
// RMSNorm -> fp16 plane
// =====================================================================
__global__ void __launch_bounds__(256)
rmsnorm_kernel(const float* __restrict__ in, const float* __restrict__ w,
               __half* __restrict__ hi, float* __restrict__ rmsbuf)
{
    __shared__ float red[256];
    const int row = blockIdx.x, tid = threadIdx.x;
    const float* xr = in + (size_t)row * D_MODEL;
    float s = 0.f;
    for (int d = tid; d < D_MODEL; d += 256) { const float v = xr[d]; s += v * v; }
    red[tid] = s;
    __syncthreads();
    for (int st = 128; st > 0; st >>= 1) { if (tid < st) red[tid] += red[tid + st]; __syncthreads(); }
    const float rms = sqrtf(red[0] / (float)D_MODEL + EPS_F);
    const float inv = 1.f / rms;
    for (int d = tid; d < D_MODEL; d += 256)
        hi[(size_t)row * D_MODEL + d] = __float2half_rn(w[d] * xr[d] * inv);
    if (tid == 0) rmsbuf[row] = rms;
}

// =====================================================================
// k_mod -> fp16 plane  [bh][t][64]   (reads fp16 k plane)
// =====================================================================
__global__ void __launch_bounds__(256)
kmod_kernel(const __half* __restrict__ kbuf, const float* __restrict__ rel)
{
    __shared__ float ks[64][65];
    __shared__ float ts[64][65];
    const int bh = blockIdx.y, b = bh >> 4, h = bh & 15;
    const int t0 = blockIdx.x * 64;
    const int tid = threadIdx.x;
    for (int i = tid; i < 4096; i += 256) {
        const int r = i >> 6, c = i & 63;
        ks[r][c] = __half2float(kbuf[(size_t)(b*TT + t0 + r) * D_MODEL + h*DH + c]);
        ts[r][c] = rel[(size_t)h*DH*DH + r*DH + c];
    }
    __syncthreads();
    const int tx = tid & 15, ty = tid >> 4;
    float acc[4][4] = {};
#pragma unroll
    for (int d = 0; d < 64; d++) {
        float ra[4], rb[4];
#pragma unroll
        for (int i = 0; i < 4; i++) ra[i] = ks[ty*4 + i][d];
#pragma unroll
        for (int j = 0; j < 4; j++) rb[j] = ts[d][tx*4 + j];
#pragma unroll
        for (int i = 0; i < 4; i++)
#pragma unroll
            for (int j = 0; j < 4; j++) acc[i][j] += ra[i] * rb[j];
    }
#pragma unroll
    for (int i = 0; i < 4; i++)
#pragma unroll
        for (int j = 0; j < 4; j++)
            b_kmod[((size_t)bh*TT + t0 + ty*4 + i) * DH + tx*4 + j] = __float2half_rn(acc[i][j]);
}

// =====================================================================
// V transpose -> fp16 plane  [bh][64][t]   (reads fp16 v plane)
// =====================================================================
__global__ void __launch_bounds__(256)
vtrans_kernel(const __half* __restrict__ v)
{
    __shared__ __half t[64][72];
    const int z = blockIdx.y, b = z >> 4, h = z & 15;
    const int t0 = blockIdx.x * 64;
    for (int i = threadIdx.x; i < 4096; i += 256) {
        const int r = i >> 6, c = i & 63;
        t[r][c] = v[(size_t)(b*TT + t0 + r) * D_MODEL + h*DH + c];
    }
    __syncthreads();
    for (int i = threadIdx.x; i < 4096; i += 256) {
        const int e = i >> 6, r = i & 63;
        b_vt[(size_t)z * DH * TT + (size_t)e * TT + t0 + r] = t[r][e];
    }
}

// =====================================================================
// Row softmax over 2048, fp32 in place + fp16 plane copy
// =====================================================================
__global__ void __launch_bounds__(256)
softmax_kernel(float* __restrict__ P, __half* __restrict__ ph)
{
    __shared__ float red[256];
    const size_t row = blockIdx.x;
    float* p = P + row * (size_t)TT;
    __half* oh = ph + row * (size_t)TT;
    const int tid = threadIdx.x;
    float v[8];
#pragma unroll
    for (int i = 0; i < 8; i++) v[i] = p[tid + i*256];
    float m = v[0];
#pragma unroll
    for (int i = 1; i < 8; i++) m = fmaxf(m, v[i]);
    red[tid] = m;
    __syncthreads();
    for (int st = 128; st > 0; st >>= 1) { if (tid < st) red[tid] = fmaxf(red[tid], red[tid+st]); __syncthreads(); }
    m = red[0];
    __syncthreads();
    float s = 0.f;
#pragma unroll
    for (int i = 0; i < 8; i++) { v[i] = __expf(v[i] - m); s += v[i]; }
    red[tid] = s;
    __syncthreads();
    for (int st = 128; st > 0; st >>= 1) { if (tid < st) red[tid] += red[tid+st]; __syncthreads(); }
    const float inv = 1.f / red[0];
#pragma unroll
    for (int i = 0; i < 8; i++) {
        const float vv = v[i] * inv;
        p[tid + i*256] = vv;
        oh[tid + i*256] = __float2half_rn(vv);
    }
}

// =====================================================================
// Final scalars
// =====================================================================
__global__ void __launch_bounds__(256)
finalize_kernel(float* __restrict__ out)
{
    __shared__ float s1[256], s2[256], s3[256];
    const int tid = threadIdx.x;
    float a = 0.f, b = 0.f, c = 0.f;
    for (int i = tid; i < BT; i += 256) { a += g_spars[i]; b += g_rms1[i]; c += g_rms2[i]; }
    s1[tid] = a; s2[tid] = b; s3[tid] = c;
    __syncthreads();
    for (int st = 128; st > 0; st >>= 1) {
        if (tid < st) { s1[tid] += s1[tid+st]; s2[tid] += s2[tid+st]; s3[tid] += s3[tid+st]; }
        __syncthreads();
    }
    if (tid == 0) {
        out[SC_OFF + 0] = s1[0] / ((float)BB * (float)TT * (float)DICT);
        out[SC_OFF + 1] = s2[0] / (float)BT;
        out[SC_OFF + 2] = s3[0] / (float)BT;
    }
}

// =====================================================================
// host launcher
// =====================================================================
extern "C" void kernel_launch(void* const* d_in, const int* in_sizes, int n_in,
                              void* d_out, int out_size)
{
    (void)in_sizes; (void)n_in; (void)out_size;
    const float* x     = (const float*)d_in[0];
    const float* proto = (const float*)d_in[2];
    const float* fgw   = (const float*)d_in[3];
    const float* dictw = (const float*)d_in[4];
    const float* encw  = (const float*)d_in[5];
    const float* wq    = (const float*)d_in[6];
    const float* wk    = (const float*)d_in[7];
    const float* wv    = (const float*)d_in[8];
    const float* wo    = (const float*)d_in[9];
    const float* rel   = (const float*)d_in[10];
    const float* gatew = (const float*)d_in[11];
    const float* upw   = (const float*)d_in[12];
    const float* downw = (const float*)d_in[13];
    const float* n1w   = (const float*)d_in[14];
    const float* n2w   = (const float*)d_in[15];
    const float* bias  = (const float*)d_in[16];
    float* out = (float*)d_out;

    const int SM_128 = 3 * (16384 + 16384);   // 98304
    const int SM_64  = 3 * (16384 +  8192);   // 73728
    cudaFuncSetAttribute(mma_gemm<128,0>, cudaFuncAttributeMaxDynamicSharedMemorySize, SM_128);
    cudaFuncSetAttribute(mma_gemm<128,2>, cudaFuncAttributeMaxDynamicSharedMemorySize, SM_128);
    cudaFuncSetAttribute(mma_gemm<128,3>, cudaFuncAttributeMaxDynamicSharedMemorySize, SM_128);
    cudaFuncSetAttribute(mma_gemm<64,2>,  cudaFuncAttributeMaxDynamicSharedMemorySize, SM_64);

    float *p_xrec, *p_x2, *p_up, *p_rms1, *p_rms2;
    cudaGetSymbolAddress((void**)&p_xrec, g_xrec);
    cudaGetSymbolAddress((void**)&p_x2,   g_x2);
    cudaGetSymbolAddress((void**)&p_up,   g_up);
    cudaGetSymbolAddress((void**)&p_rms1, g_rms1);
    cudaGetSymbolAddress((void**)&p_rms2, g_rms2);

    __half *pb_coeffs, *pb_resid, *pb_enc, *pb_normed, *pb_normed2, *pb_qkv, *pb_kmod,
           *pb_vt, *pb_ctx, *pb_h, *pb_attn, *pb_wqkv, *pb_wo, *pb_gw, *pb_uw, *pb_dw;
    cudaGetSymbolAddress((void**)&pb_coeffs,  b_coeffs);
    cudaGetSymbolAddress((void**)&pb_resid,   b_resid_h);
    cudaGetSymbolAddress((void**)&pb_enc,     b_enc_h);
    cudaGetSymbolAddress((void**)&pb_normed,  b_normed);
    cudaGetSymbolAddress((void**)&pb_normed2, b_normed2);
    cudaGetSymbolAddress((void**)&pb_qkv,     b_qkv);
    cudaGetSymbolAddress((void**)&pb_kmod,    b_kmod);
    cudaGetSymbolAddress((void**)&pb_vt,      b_vt);
    cudaGetSymbolAddress((void**)&pb_ctx,     b_ctx);
    cudaGetSymbolAddress((void**)&pb_h,       b_h);
    cudaGetSymbolAddress((void**)&pb_attn,    b_attn);
    cudaGetSymbolAddress((void**)&pb_wqkv,    b_wqkv);
    cudaGetSymbolAddress((void**)&pb_wo,      b_wo);
    cudaGetSymbolAddress((void**)&pb_gw,      b_gw);
    cudaGetSymbolAddress((void**)&pb_uw,      b_uw);
    cudaGetSymbolAddress((void**)&pb_dw,      b_dw);

    // weight converts
    half_kernel<<<1024, 256>>>(encw, pb_enc, PE/2);
    half_kernel<<<256, 256>>>(wq, pb_wqkv,          PW/2);
    half_kernel<<<256, 256>>>(wk, pb_wqkv + PW,     PW/2);
    half_kernel<<<256, 256>>>(wv, pb_wqkv + 2*PW,   PW/2);
    family_kernel<<<BT, 256>>>(x, fgw, proto, out + FS_OFF);

    // approx coeffs (fp16 out; exact re-rank in topk)
    mma_gemm<128,2><<<dim3(DICT/128, BT/128, 1), 256, SM_128>>>(
        pb_resid, D_MODEL, 0, 0, pb_enc, D_MODEL, 0,
        nullptr, DICT, 0, 0, pb_coeffs, nullptr, D_MODEL, 1.0f);

    // remaining weight converts (overlap with coeffs GEMM tail)
    half_kernel<<<256, 256>>>(wo,    pb_wo, PW/2);
    half_kernel<<<512, 256>>>(gatew, pb_gw, PF/2);
    half_kernel<<<512, 256>>>(upw,   pb_uw, PF/2);
    half_kernel<<<512, 256>>>(downw, pb_dw, PF/2);

    // top-16 + exact fp32 re-rank -> x_rec, sparsity
    topk_kernel<<<BT, 256>>>(dictw, encw, bias);

    // norm1 -> fp16 plane
    rmsnorm_kernel<<<BT, 256>>>(p_xrec, n1w, pb_normed, p_rms1);

    // q,k,v in ONE batched launch (fp16 planes out)
    mma_gemm<128,2><<<dim3(D_MODEL/128, BT/128, 3), 256, SM_128>>>(
        pb_normed, D_MODEL, 0, 0, pb_wqkv, D_MODEL, PW,
        nullptr, D_MODEL, PD, 0, pb_qkv, nullptr, D_MODEL, 1.0f);

    // k_mod + V transpose (fp16 in/out)
    kmod_kernel<<<dim3(TT/64, BB*N_HEADS), 256>>>(pb_qkv + PD, rel);
    vtrans_kernel<<<dim3(TT/64, BB*N_HEADS), 256>>>(pb_qkv + 2*PD);

    // logits -> d_out fp32, softmax -> fp32 + fp16 plane
    mma_gemm<128,0><<<dim3(TT/128, TT/128, BB*N_HEADS), 256, SM_128>>>(
        pb_qkv, D_MODEL, 0, 1, pb_kmod, DH, (size_t)TT*DH,
        out + ATT_OFF, TT, (size_t)TT*TT, 0, nullptr, nullptr, DH, 0.125f);
    softmax_kernel<<<BB*N_HEADS*TT, 256>>>(out + ATT_OFF, pb_attn);

    // ctx = attn @ v (fp16 out, head-sliced)
    mma_gemm<64,2><<<dim3(1, TT/128, BB*N_HEADS), 256, SM_64>>>(
        pb_attn, TT, (size_t)TT*TT, 0, pb_vt, TT, (size_t)DH*TT,
        nullptr, D_MODEL, 0, 1, pb_ctx, nullptr, TT, 1.0f);

    // x2 = x + ctx @ wo^T
    mma_gemm<128,0><<<dim3(D_MODEL/128, BT/128, 1), 256, SM_128>>>(
        pb_ctx, D_MODEL, 0, 0, pb_wo, D_MODEL, 0,
        p_x2, D_MODEL, 0, 0, nullptr, x, D_MODEL, 1.0f);

    // norm2 -> fp16 plane
    rmsnorm_kernel<<<BT, 256>>>(p_x2, n2w, pb_normed2, p_rms2);

    // FFN: up (fp32), gate (+fused activation -> b_h fp16)
    mma_gemm<128,0><<<dim3(D_FF/128, BT/128, 1), 256, SM_128>>>(
        pb_normed2, D_MODEL, 0, 0, pb_uw, D_MODEL, 0,
        p_up, D_FF, 0, 0, nullptr, nullptr, D_MODEL, 1.0f);
    mma_gemm<128,3><<<dim3(D_FF/128, BT/128, 1), 256, SM_128>>>(
        pb_normed2, D_MODEL, 0, 0, pb_gw, D_MODEL, 0,
        nullptr, D_FF, 0, 0, pb_h, p_up, D_MODEL, 1.0f);

    // final x = x2 + h @ down^T -> d_out
    mma_gemm<128,0><<<dim3(D_MODEL/128, BT/128, 1), 256, SM_128>>>(
        pb_h, D_FF, 0, 0, pb_dw, D_FF, 0,
        out + X_OFF, D_MODEL, 0, 0, nullptr, p_x2, D_FF, 1.0f);

    // scalars
    finalize_kernel<<<1, 256>>>(out);
}